// round 1
// baseline (speedup 1.0000x reference)
#include <cuda_runtime.h>
#include <cuda_bf16.h>
#include <math.h>

// Problem constants
#define BATCH 4
#define SEQ   2048
#define HID   1024
#define NHEAD 16
#define DK    64
#define DFF   4096
#define MTOT  (BATCH * SEQ)          // 8192 rows

// ---------------------------------------------------------------------------
// Scratch (static __device__ allocations — allowed by harness rules)
// ---------------------------------------------------------------------------
__device__ float g_q  [MTOT * HID];
__device__ float g_k  [MTOT * HID];
__device__ float g_v  [MTOT * HID];
__device__ float g_ctx[MTOT * HID];
__device__ float g_ao [MTOT * HID];   // attention output (Wo proj)
__device__ float g_x1 [MTOT * HID];   // post-LN1
__device__ float g_h  [MTOT * DFF];   // FFN hidden
__device__ float g_ff [MTOT * HID];   // FFN2 out

// ---------------------------------------------------------------------------
// GELU (exact tanh formulation from reference)
// ---------------------------------------------------------------------------
__device__ __forceinline__ float gelu_fn(float x) {
    const float c = 0.7978845608028654f;  // sqrt(2/pi)
    float x3 = x * x * x;
    return 0.5f * x * (1.0f + tanhf(c * (x + 0.044715f * x3)));
}

// ---------------------------------------------------------------------------
// SIMT fp32 GEMM:  C[M,N] = A[M,K] @ B[K,N] + bias[N]  (optional GELU)
// 128x128 block tile, BK=8, 256 threads, 8x8 microtile (split 4+4 @ +64)
// M,N,K all multiples of 128 here — no bounds checks.
// ---------------------------------------------------------------------------
template<int GELU_EPI>
__global__ void __launch_bounds__(256) gemm_kernel(
    const float* __restrict__ A, const float* __restrict__ B,
    const float* __restrict__ bias, float* __restrict__ C,
    int M, int N, int K)
{
    __shared__ float As[8][128];
    __shared__ float Bs[8][128];

    const int tid = threadIdx.x;
    const int bm  = blockIdx.y * 128;
    const int bn  = blockIdx.x * 128;
    const int tx  = tid & 15;
    const int ty  = tid >> 4;

    // A staging: thread -> (row, 4-col chunk)
    const int arow = tid >> 1;
    const int acol = (tid & 1) << 2;
    // B staging: thread -> (row, 4-col chunk)
    const int brow = tid >> 5;
    const int bcol = (tid & 31) << 2;

    const float* Ap = A + (size_t)(bm + arow) * K + acol;
    const float* Bp = B + (size_t)brow * N + (bn + bcol);

    float acc[8][8];
#pragma unroll
    for (int i = 0; i < 8; i++)
#pragma unroll
        for (int j = 0; j < 8; j++) acc[i][j] = 0.0f;

    for (int k0 = 0; k0 < K; k0 += 8) {
        float4 av = *(const float4*)(Ap + k0);
        float4 bv = *(const float4*)(Bp + (size_t)k0 * N);
        As[acol + 0][arow] = av.x;
        As[acol + 1][arow] = av.y;
        As[acol + 2][arow] = av.z;
        As[acol + 3][arow] = av.w;
        *(float4*)&Bs[brow][bcol] = bv;
        __syncthreads();

#pragma unroll
        for (int kk = 0; kk < 8; kk++) {
            float a[8], b[8];
            *(float4*)&a[0] = *(const float4*)&As[kk][ty * 4];
            *(float4*)&a[4] = *(const float4*)&As[kk][64 + ty * 4];
            *(float4*)&b[0] = *(const float4*)&Bs[kk][tx * 4];
            *(float4*)&b[4] = *(const float4*)&Bs[kk][64 + tx * 4];
#pragma unroll
            for (int i = 0; i < 8; i++)
#pragma unroll
                for (int j = 0; j < 8; j++)
                    acc[i][j] = fmaf(a[i], b[j], acc[i][j]);
        }
        __syncthreads();
    }

    // Epilogue: bias (+GELU), vectorized stores
#pragma unroll
    for (int ih = 0; ih < 2; ih++) {
#pragma unroll
        for (int ii = 0; ii < 4; ii++) {
            int r = bm + ih * 64 + ty * 4 + ii;
#pragma unroll
            for (int jh = 0; jh < 2; jh++) {
                int c0 = bn + jh * 64 + tx * 4;
                float4 v;
                v.x = acc[ih * 4 + ii][jh * 4 + 0] + bias[c0 + 0];
                v.y = acc[ih * 4 + ii][jh * 4 + 1] + bias[c0 + 1];
                v.z = acc[ih * 4 + ii][jh * 4 + 2] + bias[c0 + 2];
                v.w = acc[ih * 4 + ii][jh * 4 + 3] + bias[c0 + 3];
                if (GELU_EPI) {
                    v.x = gelu_fn(v.x); v.y = gelu_fn(v.y);
                    v.z = gelu_fn(v.z); v.w = gelu_fn(v.w);
                }
                *(float4*)&C[(size_t)r * N + c0] = v;
            }
        }
    }
}

// ---------------------------------------------------------------------------
// Flash-style attention, fp32.
// One CTA = 64 query rows of one (batch, head). 256 threads (16x16 grid),
// each thread owns a 4x4 O microtile. Online softmax, scale = 1/8.
// smem arrays padded to 65 floats/row (conflict-free staging writes).
// ---------------------------------------------------------------------------
#define APAD 65
#define ATT_SMEM (4 * 64 * APAD * 4)

__global__ void __launch_bounds__(256) attn_kernel(
    const float* __restrict__ Qg, const float* __restrict__ Kg,
    const float* __restrict__ Vg, float* __restrict__ Og)
{
    extern __shared__ float sm[];
    float* Qts = sm;                 // [d][row]
    float* Kts = sm + 64 * APAD;     // [d][key]
    float* Vs  = sm + 2 * 64 * APAD; // [key][d]
    float* Pts = sm + 3 * 64 * APAD; // [key][row]

    const int qt   = blockIdx.x;     // 0..31
    const int head = blockIdx.y;     // 0..15
    const int b    = blockIdx.z;     // 0..3
    const int tid  = threadIdx.x;
    const int tx   = tid & 15;
    const int ty   = tid >> 4;

    const size_t base = ((size_t)b * SEQ) * HID + (size_t)head * DK;
    const int q0 = qt * 64;

    // stage Q transposed: Qts[d][r]
    for (int i = tid; i < 64 * 64; i += 256) {
        int r = i >> 6, d = i & 63;
        Qts[d * APAD + r] = Qg[base + (size_t)(q0 + r) * HID + d];
    }

    float m[4], l[4], acc[4][4];
#pragma unroll
    for (int i = 0; i < 4; i++) {
        m[i] = -1e30f; l[i] = 0.0f;
#pragma unroll
        for (int j = 0; j < 4; j++) acc[i][j] = 0.0f;
    }
    __syncthreads();

    for (int t = 0; t < SEQ / 64; t++) {
        const int k0 = t * 64;
        for (int i = tid; i < 64 * 64; i += 256) {
            int r = i >> 6, d = i & 63;
            Kts[d * APAD + r] = Kg[base + (size_t)(k0 + r) * HID + d];
            Vs [r * APAD + d] = Vg[base + (size_t)(k0 + r) * HID + d];
        }
        __syncthreads();

        // S = Q K^T * 0.125
        float s[4][4];
#pragma unroll
        for (int i = 0; i < 4; i++)
#pragma unroll
            for (int j = 0; j < 4; j++) s[i][j] = 0.0f;

        for (int d = 0; d < 64; d++) {
            float a[4], bb[4];
#pragma unroll
            for (int i = 0; i < 4; i++) a[i]  = Qts[d * APAD + ty * 4 + i];
#pragma unroll
            for (int j = 0; j < 4; j++) bb[j] = Kts[d * APAD + tx * 4 + j];
#pragma unroll
            for (int i = 0; i < 4; i++)
#pragma unroll
                for (int j = 0; j < 4; j++)
                    s[i][j] = fmaf(a[i], bb[j], s[i][j]);
        }

#pragma unroll
        for (int i = 0; i < 4; i++) {
#pragma unroll
            for (int j = 0; j < 4; j++) s[i][j] *= 0.125f;

            // row max across the 16 tx lanes (same 16-lane half-warp group)
            float tmax = fmaxf(fmaxf(s[i][0], s[i][1]), fmaxf(s[i][2], s[i][3]));
#pragma unroll
            for (int off = 1; off < 16; off <<= 1)
                tmax = fmaxf(tmax, __shfl_xor_sync(0xffffffffu, tmax, off));

            float mn   = fmaxf(m[i], tmax);
            float corr = __expf(m[i] - mn);
            float rs = 0.0f;
#pragma unroll
            for (int j = 0; j < 4; j++) {
                float p = __expf(s[i][j] - mn);
                s[i][j] = p;
                rs += p;
            }
#pragma unroll
            for (int off = 1; off < 16; off <<= 1)
                rs += __shfl_xor_sync(0xffffffffu, rs, off);

            l[i] = l[i] * corr + rs;
            m[i] = mn;
#pragma unroll
            for (int j = 0; j < 4; j++) acc[i][j] *= corr;
        }

        // stage P transposed: Pts[key][row]
#pragma unroll
        for (int i = 0; i < 4; i++)
#pragma unroll
            for (int j = 0; j < 4; j++)
                Pts[(tx * 4 + j) * APAD + ty * 4 + i] = s[i][j];
        __syncthreads();

        // O += P @ V
        for (int kk = 0; kk < 64; kk++) {
            float a[4], vv[4];
#pragma unroll
            for (int i = 0; i < 4; i++) a[i]  = Pts[kk * APAD + ty * 4 + i];
#pragma unroll
            for (int j = 0; j < 4; j++) vv[j] = Vs [kk * APAD + tx * 4 + j];
#pragma unroll
            for (int i = 0; i < 4; i++)
#pragma unroll
                for (int j = 0; j < 4; j++)
                    acc[i][j] = fmaf(a[i], vv[j], acc[i][j]);
        }
        __syncthreads();
    }

    // normalize + write ctx as [B,S,H] (head-contiguous 64 cols)
#pragma unroll
    for (int i = 0; i < 4; i++) {
        float inv = 1.0f / l[i];
        int r = q0 + ty * 4 + i;
#pragma unroll
        for (int j = 0; j < 4; j++)
            Og[base + (size_t)r * HID + tx * 4 + j] = acc[i][j] * inv;
    }
}

// ---------------------------------------------------------------------------
// Residual add + LayerNorm: out = LN(X + Y) * g + be      (H = 1024 per row)
// One block (256 thr) per row; 4 elems/thread held in registers.
// ---------------------------------------------------------------------------
__global__ void __launch_bounds__(256) add_ln_kernel(
    const float* __restrict__ X, const float* __restrict__ Y,
    const float* __restrict__ g, const float* __restrict__ be,
    float* __restrict__ out)
{
    const int row = blockIdx.x;
    const int tid = threadIdx.x;
    const size_t base = (size_t)row * HID;

    float v[4];
    float s = 0.0f, s2 = 0.0f;
#pragma unroll
    for (int k = 0; k < 4; k++) {
        int c = tid + k * 256;
        float t = X[base + c] + Y[base + c];
        v[k] = t;
        s += t;
        s2 += t * t;
    }
#pragma unroll
    for (int off = 16; off > 0; off >>= 1) {
        s  += __shfl_xor_sync(0xffffffffu, s,  off);
        s2 += __shfl_xor_sync(0xffffffffu, s2, off);
    }
    __shared__ float red[16];
    const int warp = tid >> 5, lane = tid & 31;
    if (lane == 0) { red[warp] = s; red[warp + 8] = s2; }
    __syncthreads();
    if (tid < 32) {
        float a = (lane < 8) ? red[lane]     : 0.0f;
        float c2 = (lane < 8) ? red[lane + 8] : 0.0f;
#pragma unroll
        for (int off = 4; off > 0; off >>= 1) {
            a  += __shfl_xor_sync(0xffffffffu, a,  off);
            c2 += __shfl_xor_sync(0xffffffffu, c2, off);
        }
        if (lane == 0) { red[0] = a; red[1] = c2; }
    }
    __syncthreads();
    const float mu  = red[0] * (1.0f / HID);
    const float var = red[1] * (1.0f / HID) - mu * mu;
    const float inv = rsqrtf(var + 1e-5f);
#pragma unroll
    for (int k = 0; k < 4; k++) {
        int c = tid + k * 256;
        out[base + c] = (v[k] - mu) * inv * g[c] + be[c];
    }
}

// ---------------------------------------------------------------------------
// kernel_launch
// ---------------------------------------------------------------------------
extern "C" void kernel_launch(void* const* d_in, const int* in_sizes, int n_in,
                              void* d_out, int out_size)
{
    const float* x  = (const float*)d_in[0];
    const float* Wq = (const float*)d_in[1];
    const float* bq = (const float*)d_in[2];
    const float* Wk = (const float*)d_in[3];
    const float* bk = (const float*)d_in[4];
    const float* Wv = (const float*)d_in[5];
    const float* bv = (const float*)d_in[6];
    const float* Wo = (const float*)d_in[7];
    const float* bo = (const float*)d_in[8];
    const float* W1 = (const float*)d_in[9];
    const float* b1 = (const float*)d_in[10];
    const float* W2 = (const float*)d_in[11];
    const float* b2 = (const float*)d_in[12];
    const float* g1 = (const float*)d_in[13];
    const float* be1= (const float*)d_in[14];
    const float* g2 = (const float*)d_in[15];
    const float* be2= (const float*)d_in[16];
    float* out = (float*)d_out;

    float *pq, *pk, *pv, *pctx, *pao, *px1, *ph, *pff;
    cudaGetSymbolAddress((void**)&pq,   g_q);
    cudaGetSymbolAddress((void**)&pk,   g_k);
    cudaGetSymbolAddress((void**)&pv,   g_v);
    cudaGetSymbolAddress((void**)&pctx, g_ctx);
    cudaGetSymbolAddress((void**)&pao,  g_ao);
    cudaGetSymbolAddress((void**)&px1,  g_x1);
    cudaGetSymbolAddress((void**)&ph,   g_h);
    cudaGetSymbolAddress((void**)&pff,  g_ff);

    cudaFuncSetAttribute(attn_kernel,
                         cudaFuncAttributeMaxDynamicSharedMemorySize, ATT_SMEM);

    const dim3 gProj(HID / 128, MTOT / 128);   // (8, 64)
    const dim3 gFF1 (DFF / 128, MTOT / 128);   // (32, 64)
    const dim3 blk(256);

    // QKV projections
    gemm_kernel<0><<<gProj, blk>>>(x, Wq, bq, pq, MTOT, HID, HID);
    gemm_kernel<0><<<gProj, blk>>>(x, Wk, bk, pk, MTOT, HID, HID);
    gemm_kernel<0><<<gProj, blk>>>(x, Wv, bv, pv, MTOT, HID, HID);

    // Attention
    attn_kernel<<<dim3(SEQ / 64, NHEAD, BATCH), blk, ATT_SMEM>>>(pq, pk, pv, pctx);

    // Output projection + residual/LN1
    gemm_kernel<0><<<gProj, blk>>>(pctx, Wo, bo, pao, MTOT, HID, HID);
    add_ln_kernel<<<MTOT, blk>>>(x, pao, g1, be1, px1);

    // FFN
    gemm_kernel<1><<<gFF1, blk>>>(px1, W1, b1, ph, MTOT, DFF, HID);
    gemm_kernel<0><<<gProj, blk>>>(ph, W2, b2, pff, MTOT, HID, DFF);

    // Residual/LN2 -> output
    add_ln_kernel<<<MTOT, blk>>>(px1, pff, g2, be2, out);
}

// round 3
// speedup vs baseline: 1.7240x; 1.7240x over previous
#include <cuda_runtime.h>
#include <cuda_bf16.h>
#include <math.h>
#include <cstdint>

// Problem constants
#define BATCH 4
#define SEQ   2048
#define HID   1024
#define NHEAD 16
#define DK    64
#define DFF   4096
#define MTOT  (BATCH * SEQ)          // 8192 rows

// ---------------------------------------------------------------------------
// Scratch (static __device__ allocations)
// ---------------------------------------------------------------------------
__device__ float g_q  [MTOT * HID];
__device__ float g_k  [MTOT * HID];
__device__ float g_v  [MTOT * HID];
__device__ float g_ctx[MTOT * HID];
__device__ float g_ao [MTOT * HID];
__device__ float g_x1 [MTOT * HID];
__device__ float g_h  [MTOT * DFF];
__device__ float g_ff [MTOT * HID];
// transposed (and tf32-rounded) weights: Wt[n][k]
__device__ float g_wqt[HID * HID];
__device__ float g_wkt[HID * HID];
__device__ float g_wvt[HID * HID];
__device__ float g_wot[HID * HID];
__device__ float g_w1t[HID * DFF];
__device__ float g_w2t[DFF * HID];

// ---------------------------------------------------------------------------
// helpers
// ---------------------------------------------------------------------------
__device__ __forceinline__ float to_tf32(float x) {
    float r;
    asm("cvt.rna.tf32.f32 %0, %1;" : "=f"(r) : "f"(x));
    return r;
}
__device__ __forceinline__ uint32_t smem_u32(const void* p) {
    uint32_t a;
    asm("{ .reg .u64 t; cvta.to.shared.u64 t, %1; cvt.u32.u64 %0, t; }" : "=r"(a) : "l"(p));
    return a;
}
__device__ __forceinline__ void cp_async16(uint32_t saddr, const void* gaddr) {
    asm volatile("cp.async.cg.shared.global [%0], [%1], 16;" :: "r"(saddr), "l"(gaddr) : "memory");
}
#define CP_COMMIT() asm volatile("cp.async.commit_group;" ::: "memory")
#define CP_WAIT(n)  asm volatile("cp.async.wait_group %0;" :: "n"(n) : "memory")

__device__ __forceinline__ void mma_tf32(
    float& d0, float& d1, float& d2, float& d3,
    uint32_t a0, uint32_t a1, uint32_t a2, uint32_t a3,
    uint32_t b0, uint32_t b1)
{
    asm volatile(
        "mma.sync.aligned.m16n8k8.row.col.f32.tf32.tf32.f32 "
        "{%0,%1,%2,%3}, {%4,%5,%6,%7}, {%8,%9}, {%0,%1,%2,%3};"
        : "+f"(d0), "+f"(d1), "+f"(d2), "+f"(d3)
        : "r"(a0), "r"(a1), "r"(a2), "r"(a3), "r"(b0), "r"(b1));
}

// ---------------------------------------------------------------------------
// GELU (exact tanh formulation)
// ---------------------------------------------------------------------------
__device__ __forceinline__ float gelu_fn(float x) {
    const float c = 0.7978845608028654f;
    float x3 = x * x * x;
    return 0.5f * x * (1.0f + tanhf(c * (x + 0.044715f * x3)));
}

// ---------------------------------------------------------------------------
// Weight transpose with tf32 rounding:  Wt[n][k] = tf32(W[k][n])
// ---------------------------------------------------------------------------
__global__ void __launch_bounds__(256) transpose_tf32_kernel(
    const float* __restrict__ W, float* __restrict__ Wt, int K, int N)
{
    __shared__ float t[32][33];
    const int bx = blockIdx.x * 32;   // n
    const int by = blockIdx.y * 32;   // k
    const int tx = threadIdx.x & 31;
    const int ty = threadIdx.x >> 5;  // 0..7
#pragma unroll
    for (int q = 0; q < 4; q++)
        t[ty + q * 8][tx] = W[(size_t)(by + ty + q * 8) * N + bx + tx];
    __syncthreads();
#pragma unroll
    for (int q = 0; q < 4; q++)
        Wt[(size_t)(bx + ty + q * 8) * K + by + tx] = to_tf32(t[tx][ty + q * 8]);
}

// ---------------------------------------------------------------------------
// tf32 mma.sync GEMM:  C[M,N] = A[M,K] @ W[K,N] + bias   (W given as Wt[n][k])
// CTA tile 128x128, BK=32, 3-stage pipeline, 256 threads = 8 warps (2m x 4n),
// warp tile 64x32 = 4x4 m16n8k8 mma tiles.
// A: LDG -> cvt.rna.tf32 -> STS.   B: cp.async (weights pre-rounded).
// ---------------------------------------------------------------------------
#define SPAD   36
#define STAGES 3
#define STAGE_FLOATS (2 * 128 * SPAD)               // A then B
#define GEMM_SMEM (STAGES * STAGE_FLOATS * 4)       // 110592 bytes

template<int GELU_EPI>
__global__ void __launch_bounds__(256) mma_gemm(
    const float* __restrict__ A, const float* __restrict__ Bt,
    const float* __restrict__ bias, float* __restrict__ C,
    int M, int N, int K)
{
    extern __shared__ float sh[];
    const int tid = threadIdx.x;
    const int wid = tid >> 5;
    const int lane = tid & 31;
    const int g = lane >> 2;          // group (row within mma)
    const int t = lane & 3;           // thread-in-group (k/col)
    const int bm = blockIdx.y * 128;
    const int bn = blockIdx.x * 128;
    const int moff = (wid >> 2) * 64; // warp m offset
    const int noff = (wid & 3) * 32;  // warp n offset

    // tile-fill mapping: 4 chunks of 16B per thread, chunk c -> row c>>3, col4 c&7
    const int iters = K / 32;

    float acc[4][4][4];
#pragma unroll
    for (int a = 0; a < 4; a++)
#pragma unroll
        for (int b = 0; b < 4; b++)
#pragma unroll
            for (int c = 0; c < 4; c++) acc[a][b][c] = 0.0f;

    float4 aregs[4];

    // --- prologue ---
    {
        // stage 0: A (LDG+cvt+STS) and B (cp.async)
        float* As0 = sh;
        float* Bs0 = sh + 128 * SPAD;
#pragma unroll
        for (int q = 0; q < 4; q++) {
            int c = q * 256 + tid;
            int row = c >> 3, c4 = c & 7;
            float4 v = *(const float4*)&A[(size_t)(bm + row) * K + c4 * 4];
            v.x = to_tf32(v.x); v.y = to_tf32(v.y); v.z = to_tf32(v.z); v.w = to_tf32(v.w);
            *(float4*)&As0[row * SPAD + c4 * 4] = v;
            cp_async16(smem_u32(&Bs0[row * SPAD + c4 * 4]),
                       &Bt[(size_t)(bn + row) * K + c4 * 4]);
        }
        CP_COMMIT();
        if (iters > 1) {
            float* Bs1 = sh + STAGE_FLOATS + 128 * SPAD;
#pragma unroll
            for (int q = 0; q < 4; q++) {
                int c = q * 256 + tid;
                int row = c >> 3, c4 = c & 7;
                aregs[q] = *(const float4*)&A[(size_t)(bm + row) * K + 32 + c4 * 4];
                cp_async16(smem_u32(&Bs1[row * SPAD + c4 * 4]),
                           &Bt[(size_t)(bn + row) * K + 32 + c4 * 4]);
            }
            CP_COMMIT();
        }
    }

    for (int i = 0; i < iters; i++) {
        if (i + 1 < iters) { CP_WAIT(1); } else { CP_WAIT(0); }
        __syncthreads();

        // issue B for stage i+2
        if (i + 2 < iters) {
            float* Bs = sh + ((i + 2) % STAGES) * STAGE_FLOATS + 128 * SPAD;
            const int k0 = (i + 2) * 32;
#pragma unroll
            for (int q = 0; q < 4; q++) {
                int c = q * 256 + tid;
                int row = c >> 3, c4 = c & 7;
                cp_async16(smem_u32(&Bs[row * SPAD + c4 * 4]),
                           &Bt[(size_t)(bn + row) * K + k0 + c4 * 4]);
            }
            CP_COMMIT();
        }
        // STS A for stage i+1 (from regs), then LDG A for stage i+2
        if (i + 1 < iters) {
            float* As = sh + ((i + 1) % STAGES) * STAGE_FLOATS;
#pragma unroll
            for (int q = 0; q < 4; q++) {
                int c = q * 256 + tid;
                int row = c >> 3, c4 = c & 7;
                float4 v = aregs[q];
                v.x = to_tf32(v.x); v.y = to_tf32(v.y); v.z = to_tf32(v.z); v.w = to_tf32(v.w);
                *(float4*)&As[row * SPAD + c4 * 4] = v;
            }
        }
        if (i + 2 < iters) {
            const int k0 = (i + 2) * 32;
#pragma unroll
            for (int q = 0; q < 4; q++) {
                int c = q * 256 + tid;
                int row = c >> 3, c4 = c & 7;
                aregs[q] = *(const float4*)&A[(size_t)(bm + row) * K + k0 + c4 * 4];
            }
        }

        // compute stage i
        const float* As = sh + (i % STAGES) * STAGE_FLOATS;
        const float* Bs = As + 128 * SPAD;
#pragma unroll
        for (int k8 = 0; k8 < 4; k8++) {
            uint32_t af[4][4], bf[4][2];
            const int kc = k8 * 8 + t;
#pragma unroll
            for (int mt = 0; mt < 4; mt++) {
                const int r0 = moff + mt * 16 + g;
                af[mt][0] = __float_as_uint(As[r0 * SPAD + kc]);
                af[mt][1] = __float_as_uint(As[(r0 + 8) * SPAD + kc]);
                af[mt][2] = __float_as_uint(As[r0 * SPAD + kc + 4]);
                af[mt][3] = __float_as_uint(As[(r0 + 8) * SPAD + kc + 4]);
            }
#pragma unroll
            for (int nt = 0; nt < 4; nt++) {
                const int n0 = noff + nt * 8 + g;
                bf[nt][0] = __float_as_uint(Bs[n0 * SPAD + kc]);
                bf[nt][1] = __float_as_uint(Bs[n0 * SPAD + kc + 4]);
            }
#pragma unroll
            for (int mt = 0; mt < 4; mt++)
#pragma unroll
                for (int nt = 0; nt < 4; nt++)
                    mma_tf32(acc[mt][nt][0], acc[mt][nt][1], acc[mt][nt][2], acc[mt][nt][3],
                             af[mt][0], af[mt][1], af[mt][2], af[mt][3],
                             bf[nt][0], bf[nt][1]);
        }
    }

    // --- epilogue: bias (+GELU), float2 stores ---
#pragma unroll
    for (int nt = 0; nt < 4; nt++) {
        const int col = bn + noff + nt * 8 + 2 * t;
        const float2 bv = *(const float2*)&bias[col];
#pragma unroll
        for (int mt = 0; mt < 4; mt++) {
            const int r0 = bm + moff + mt * 16 + g;
            float2 v0, v1;
            v0.x = acc[mt][nt][0] + bv.x;
            v0.y = acc[mt][nt][1] + bv.y;
            v1.x = acc[mt][nt][2] + bv.x;
            v1.y = acc[mt][nt][3] + bv.y;
            if (GELU_EPI) {
                v0.x = gelu_fn(v0.x); v0.y = gelu_fn(v0.y);
                v1.x = gelu_fn(v1.x); v1.y = gelu_fn(v1.y);
            }
            *(float2*)&C[(size_t)r0 * N + col] = v0;
            *(float2*)&C[(size_t)(r0 + 8) * N + col] = v1;
        }
    }
}

// ---------------------------------------------------------------------------
// Flash-style attention, fp32, vectorized LDS (APAD=68 keeps 16B alignment).
// One CTA = 64 query rows of one (batch, head). 256 threads, 4x4 microtile.
// ---------------------------------------------------------------------------
#define APAD 68
#define ATT_SMEM (4 * 64 * APAD * 4)

__global__ void __launch_bounds__(256) attn_kernel(
    const float* __restrict__ Qg, const float* __restrict__ Kg,
    const float* __restrict__ Vg, float* __restrict__ Og)
{
    extern __shared__ float sm[];
    float* Qts = sm;                 // [d][row]
    float* Kts = sm + 64 * APAD;     // [d][key]
    float* Vs  = sm + 2 * 64 * APAD; // [key][d]
    float* Pts = sm + 3 * 64 * APAD; // [key][row]

    const int qt   = blockIdx.x;
    const int head = blockIdx.y;
    const int b    = blockIdx.z;
    const int tid  = threadIdx.x;
    const int tx   = tid & 15;
    const int ty   = tid >> 4;

    const size_t base = ((size_t)b * SEQ) * HID + (size_t)head * DK;
    const int q0 = qt * 64;

    for (int i = tid; i < 64 * 16; i += 256) {
        int r = i >> 4, d4 = i & 15;
        float4 v = *(const float4*)&Qg[base + (size_t)(q0 + r) * HID + d4 * 4];
        Qts[(d4 * 4 + 0) * APAD + r] = v.x;
        Qts[(d4 * 4 + 1) * APAD + r] = v.y;
        Qts[(d4 * 4 + 2) * APAD + r] = v.z;
        Qts[(d4 * 4 + 3) * APAD + r] = v.w;
    }

    float m[4], l[4], acc[4][4];
#pragma unroll
    for (int i = 0; i < 4; i++) {
        m[i] = -1e30f; l[i] = 0.0f;
#pragma unroll
        for (int j = 0; j < 4; j++) acc[i][j] = 0.0f;
    }
    __syncthreads();

    for (int tk = 0; tk < SEQ / 64; tk++) {
        const int k0 = tk * 64;
        for (int i = tid; i < 64 * 16; i += 256) {
            int r = i >> 4, d4 = i & 15;
            float4 kv = *(const float4*)&Kg[base + (size_t)(k0 + r) * HID + d4 * 4];
            Kts[(d4 * 4 + 0) * APAD + r] = kv.x;
            Kts[(d4 * 4 + 1) * APAD + r] = kv.y;
            Kts[(d4 * 4 + 2) * APAD + r] = kv.z;
            Kts[(d4 * 4 + 3) * APAD + r] = kv.w;
            float4 vv = *(const float4*)&Vg[base + (size_t)(k0 + r) * HID + d4 * 4];
            *(float4*)&Vs[r * APAD + d4 * 4] = vv;
        }
        __syncthreads();

        float s[4][4];
#pragma unroll
        for (int i = 0; i < 4; i++)
#pragma unroll
            for (int j = 0; j < 4; j++) s[i][j] = 0.0f;

        for (int d = 0; d < 64; d++) {
            float4 a4 = *(const float4*)&Qts[d * APAD + ty * 4];
            float4 b4 = *(const float4*)&Kts[d * APAD + tx * 4];
            float a[4] = {a4.x, a4.y, a4.z, a4.w};
            float bb[4] = {b4.x, b4.y, b4.z, b4.w};
#pragma unroll
            for (int i = 0; i < 4; i++)
#pragma unroll
                for (int j = 0; j < 4; j++)
                    s[i][j] = fmaf(a[i], bb[j], s[i][j]);
        }

#pragma unroll
        for (int i = 0; i < 4; i++) {
#pragma unroll
            for (int j = 0; j < 4; j++) s[i][j] *= 0.125f;

            float tmax = fmaxf(fmaxf(s[i][0], s[i][1]), fmaxf(s[i][2], s[i][3]));
#pragma unroll
            for (int off = 1; off < 16; off <<= 1)
                tmax = fmaxf(tmax, __shfl_xor_sync(0xffffffffu, tmax, off));

            float mn   = fmaxf(m[i], tmax);
            float corr = __expf(m[i] - mn);
            float rs = 0.0f;
#pragma unroll
            for (int j = 0; j < 4; j++) {
                float p = __expf(s[i][j] - mn);
                s[i][j] = p;
                rs += p;
            }
#pragma unroll
            for (int off = 1; off < 16; off <<= 1)
                rs += __shfl_xor_sync(0xffffffffu, rs, off);

            l[i] = l[i] * corr + rs;
            m[i] = mn;
#pragma unroll
            for (int j = 0; j < 4; j++) acc[i][j] *= corr;
        }

#pragma unroll
        for (int i = 0; i < 4; i++)
#pragma unroll
            for (int j = 0; j < 4; j++)
                Pts[(tx * 4 + j) * APAD + ty * 4 + i] = s[i][j];
        __syncthreads();

        for (int kk = 0; kk < 64; kk++) {
            float4 a4 = *(const float4*)&Pts[kk * APAD + ty * 4];
            float4 v4 = *(const float4*)&Vs[kk * APAD + tx * 4];
            float a[4] = {a4.x, a4.y, a4.z, a4.w};
            float vv[4] = {v4.x, v4.y, v4.z, v4.w};
#pragma unroll
            for (int i = 0; i < 4; i++)
#pragma unroll
                for (int j = 0; j < 4; j++)
                    acc[i][j] = fmaf(a[i], vv[j], acc[i][j]);
        }
        __syncthreads();
    }

#pragma unroll
    for (int i = 0; i < 4; i++) {
        float inv = 1.0f / l[i];
        int r = q0 + ty * 4 + i;
#pragma unroll
        for (int j = 0; j < 4; j++)
            Og[base + (size_t)r * HID + tx * 4 + j] = acc[i][j] * inv;
    }
}

// ---------------------------------------------------------------------------
// Residual add + LayerNorm
// ---------------------------------------------------------------------------
__global__ void __launch_bounds__(256) add_ln_kernel(
    const float* __restrict__ X, const float* __restrict__ Y,
    const float* __restrict__ g, const float* __restrict__ be,
    float* __restrict__ out)
{
    const int row = blockIdx.x;
    const int tid = threadIdx.x;
    const size_t base = (size_t)row * HID;

    float v[4];
    float s = 0.0f, s2 = 0.0f;
#pragma unroll
    for (int k = 0; k < 4; k++) {
        int c = tid + k * 256;
        float t = X[base + c] + Y[base + c];
        v[k] = t;
        s += t;
        s2 += t * t;
    }
#pragma unroll
    for (int off = 16; off > 0; off >>= 1) {
        s  += __shfl_xor_sync(0xffffffffu, s,  off);
        s2 += __shfl_xor_sync(0xffffffffu, s2, off);
    }
    __shared__ float red[16];
    const int warp = tid >> 5, lane = tid & 31;
    if (lane == 0) { red[warp] = s; red[warp + 8] = s2; }
    __syncthreads();
    if (tid < 32) {
        float a = (lane < 8) ? red[lane]     : 0.0f;
        float c2 = (lane < 8) ? red[lane + 8] : 0.0f;
#pragma unroll
        for (int off = 4; off > 0; off >>= 1) {
            a  += __shfl_xor_sync(0xffffffffu, a,  off);
            c2 += __shfl_xor_sync(0xffffffffu, c2, off);
        }
        if (lane == 0) { red[0] = a; red[1] = c2; }
    }
    __syncthreads();
    const float mu  = red[0] * (1.0f / HID);
    const float var = red[1] * (1.0f / HID) - mu * mu;
    const float inv = rsqrtf(var + 1e-5f);
#pragma unroll
    for (int k = 0; k < 4; k++) {
        int c = tid + k * 256;
        out[base + c] = (v[k] - mu) * inv * g[c] + be[c];
    }
}

// ---------------------------------------------------------------------------
// kernel_launch
// ---------------------------------------------------------------------------
extern "C" void kernel_launch(void* const* d_in, const int* in_sizes, int n_in,
                              void* d_out, int out_size)
{
    const float* x  = (const float*)d_in[0];
    const float* Wq = (const float*)d_in[1];
    const float* bq = (const float*)d_in[2];
    const float* Wk = (const float*)d_in[3];
    const float* bk = (const float*)d_in[4];
    const float* Wv = (const float*)d_in[5];
    const float* bv = (const float*)d_in[6];
    const float* Wo = (const float*)d_in[7];
    const float* bo = (const float*)d_in[8];
    const float* W1 = (const float*)d_in[9];
    const float* b1 = (const float*)d_in[10];
    const float* W2 = (const float*)d_in[11];
    const float* b2 = (const float*)d_in[12];
    const float* g1 = (const float*)d_in[13];
    const float* be1= (const float*)d_in[14];
    const float* g2 = (const float*)d_in[15];
    const float* be2= (const float*)d_in[16];
    float* out = (float*)d_out;

    float *pq, *pk, *pv, *pctx, *pao, *px1, *ph, *pff;
    float *wqt, *wkt, *wvt, *wot, *w1t, *w2t;
    cudaGetSymbolAddress((void**)&pq,   g_q);
    cudaGetSymbolAddress((void**)&pk,   g_k);
    cudaGetSymbolAddress((void**)&pv,   g_v);
    cudaGetSymbolAddress((void**)&pctx, g_ctx);
    cudaGetSymbolAddress((void**)&pao,  g_ao);
    cudaGetSymbolAddress((void**)&px1,  g_x1);
    cudaGetSymbolAddress((void**)&ph,   g_h);
    cudaGetSymbolAddress((void**)&pff,  g_ff);
    cudaGetSymbolAddress((void**)&wqt,  g_wqt);
    cudaGetSymbolAddress((void**)&wkt,  g_wkt);
    cudaGetSymbolAddress((void**)&wvt,  g_wvt);
    cudaGetSymbolAddress((void**)&wot,  g_wot);
    cudaGetSymbolAddress((void**)&w1t,  g_w1t);
    cudaGetSymbolAddress((void**)&w2t,  g_w2t);

    cudaFuncSetAttribute(attn_kernel,
                         cudaFuncAttributeMaxDynamicSharedMemorySize, ATT_SMEM);
    cudaFuncSetAttribute(mma_gemm<0>,
                         cudaFuncAttributeMaxDynamicSharedMemorySize, GEMM_SMEM);
    cudaFuncSetAttribute(mma_gemm<1>,
                         cudaFuncAttributeMaxDynamicSharedMemorySize, GEMM_SMEM);

    const dim3 blk256(256);

    // weight transposes (tf32-rounded)
    transpose_tf32_kernel<<<dim3(HID/32, HID/32), blk256>>>(Wq, wqt, HID, HID);
    transpose_tf32_kernel<<<dim3(HID/32, HID/32), blk256>>>(Wk, wkt, HID, HID);
    transpose_tf32_kernel<<<dim3(HID/32, HID/32), blk256>>>(Wv, wvt, HID, HID);
    transpose_tf32_kernel<<<dim3(HID/32, HID/32), blk256>>>(Wo, wot, HID, HID);
    transpose_tf32_kernel<<<dim3(DFF/32, HID/32), blk256>>>(W1, w1t, HID, DFF);
    transpose_tf32_kernel<<<dim3(HID/32, DFF/32), blk256>>>(W2, w2t, DFF, HID);

    const dim3 gProj(HID / 128, MTOT / 128);   // (8, 64)
    const dim3 gFF1 (DFF / 128, MTOT / 128);   // (32, 64)

    // QKV projections
    mma_gemm<0><<<gProj, blk256, GEMM_SMEM>>>(x, wqt, bq, pq, MTOT, HID, HID);
    mma_gemm<0><<<gProj, blk256, GEMM_SMEM>>>(x, wkt, bk, pk, MTOT, HID, HID);
    mma_gemm<0><<<gProj, blk256, GEMM_SMEM>>>(x, wvt, bv, pv, MTOT, HID, HID);

    // Attention
    attn_kernel<<<dim3(SEQ / 64, NHEAD, BATCH), blk256, ATT_SMEM>>>(pq, pk, pv, pctx);

    // Output projection + residual/LN1
    mma_gemm<0><<<gProj, blk256, GEMM_SMEM>>>(pctx, wot, bo, pao, MTOT, HID, HID);
    add_ln_kernel<<<MTOT, blk256>>>(x, pao, g1, be1, px1);

    // FFN
    mma_gemm<1><<<gFF1, blk256, GEMM_SMEM>>>(px1, w1t, b1, ph, MTOT, DFF, HID);
    mma_gemm<0><<<gProj, blk256, GEMM_SMEM>>>(ph, w2t, b2, pff, MTOT, HID, DFF);

    // Residual/LN2 -> output
    add_ln_kernel<<<MTOT, blk256>>>(px1, pff, g2, be2, out);
}

// round 4
// speedup vs baseline: 2.7486x; 1.5943x over previous
#include <cuda_runtime.h>
#include <cuda_bf16.h>
#include <math.h>
#include <cstdint>

// Problem constants
#define BATCH 4
#define SEQ   2048
#define HID   1024
#define NHEAD 16
#define DK    64
#define DFF   4096
#define MTOT  (BATCH * SEQ)          // 8192 rows

// ---------------------------------------------------------------------------
// Scratch
// ---------------------------------------------------------------------------
__device__ float g_q  [MTOT * HID];
__device__ float g_k  [MTOT * HID];
__device__ float g_v  [MTOT * HID];
__device__ float g_ctx[MTOT * HID];
__device__ float g_ao [MTOT * HID];
__device__ float g_x1 [MTOT * HID];
__device__ float g_h  [MTOT * DFF];
__device__ float g_ff [MTOT * HID];
__device__ float g_wqt[HID * HID];
__device__ float g_wkt[HID * HID];
__device__ float g_wvt[HID * HID];
__device__ float g_wot[HID * HID];
__device__ float g_w1t[HID * DFF];
__device__ float g_w2t[DFF * HID];

// ---------------------------------------------------------------------------
// helpers
// ---------------------------------------------------------------------------
__device__ __forceinline__ float to_tf32(float x) {
    float r;
    asm("cvt.rna.tf32.f32 %0, %1;" : "=f"(r) : "f"(x));
    return r;
}
__device__ __forceinline__ uint32_t smem_u32(const void* p) {
    uint32_t a;
    asm("{ .reg .u64 t; cvta.to.shared.u64 t, %1; cvt.u32.u64 %0, t; }" : "=r"(a) : "l"(p));
    return a;
}
__device__ __forceinline__ void cp_async16(uint32_t saddr, const void* gaddr) {
    asm volatile("cp.async.cg.shared.global [%0], [%1], 16;" :: "r"(saddr), "l"(gaddr) : "memory");
}
#define CP_COMMIT() asm volatile("cp.async.commit_group;" ::: "memory")
#define CP_WAIT(n)  asm volatile("cp.async.wait_group %0;" :: "n"(n) : "memory")

__device__ __forceinline__ void mma_tf32(
    float& d0, float& d1, float& d2, float& d3,
    uint32_t a0, uint32_t a1, uint32_t a2, uint32_t a3,
    uint32_t b0, uint32_t b1)
{
    asm volatile(
        "mma.sync.aligned.m16n8k8.row.col.f32.tf32.tf32.f32 "
        "{%0,%1,%2,%3}, {%4,%5,%6,%7}, {%8,%9}, {%0,%1,%2,%3};"
        : "+f"(d0), "+f"(d1), "+f"(d2), "+f"(d3)
        : "r"(a0), "r"(a1), "r"(a2), "r"(a3), "r"(b0), "r"(b1));
}

__device__ __forceinline__ float gelu_fn(float x) {
    const float c = 0.7978845608028654f;
    float x3 = x * x * x;
    return 0.5f * x * (1.0f + tanhf(c * (x + 0.044715f * x3)));
}

// ---------------------------------------------------------------------------
// Weight transpose with tf32 rounding:  Wt[n][k] = tf32(W[k][n])
// ---------------------------------------------------------------------------
__global__ void __launch_bounds__(256) transpose_tf32_kernel(
    const float* __restrict__ W, float* __restrict__ Wt, int K, int N)
{
    __shared__ float t[32][33];
    const int bx = blockIdx.x * 32;
    const int by = blockIdx.y * 32;
    const int tx = threadIdx.x & 31;
    const int ty = threadIdx.x >> 5;
#pragma unroll
    for (int q = 0; q < 4; q++)
        t[ty + q * 8][tx] = W[(size_t)(by + ty + q * 8) * N + bx + tx];
    __syncthreads();
#pragma unroll
    for (int q = 0; q < 4; q++)
        Wt[(size_t)(bx + ty + q * 8) * K + by + tx] = to_tf32(t[tx][ty + q * 8]);
}

// ---------------------------------------------------------------------------
// tf32 mma.sync GEMM:  C[M,N] = A[M,K] @ W[K,N] + bias   (W given as Wt[n][k])
// EPI: 0 = none, 1 = GELU, 2 = round result to tf32 (for attention operands)
// ---------------------------------------------------------------------------
#define SPAD   36
#define STAGES 3
#define STAGE_FLOATS (2 * 128 * SPAD)
#define GEMM_SMEM (STAGES * STAGE_FLOATS * 4)

template<int EPI>
__global__ void __launch_bounds__(256) mma_gemm(
    const float* __restrict__ A, const float* __restrict__ Bt,
    const float* __restrict__ bias, float* __restrict__ C,
    int M, int N, int K)
{
    extern __shared__ float sh[];
    const int tid = threadIdx.x;
    const int wid = tid >> 5;
    const int lane = tid & 31;
    const int g = lane >> 2;
    const int t = lane & 3;
    const int bm = blockIdx.y * 128;
    const int bn = blockIdx.x * 128;
    const int moff = (wid >> 2) * 64;
    const int noff = (wid & 3) * 32;

    const int iters = K / 32;

    float acc[4][4][4];
#pragma unroll
    for (int a = 0; a < 4; a++)
#pragma unroll
        for (int b = 0; b < 4; b++)
#pragma unroll
            for (int c = 0; c < 4; c++) acc[a][b][c] = 0.0f;

    float4 aregs[4];

    {
        float* As0 = sh;
        float* Bs0 = sh + 128 * SPAD;
#pragma unroll
        for (int q = 0; q < 4; q++) {
            int c = q * 256 + tid;
            int row = c >> 3, c4 = c & 7;
            float4 v = *(const float4*)&A[(size_t)(bm + row) * K + c4 * 4];
            v.x = to_tf32(v.x); v.y = to_tf32(v.y); v.z = to_tf32(v.z); v.w = to_tf32(v.w);
            *(float4*)&As0[row * SPAD + c4 * 4] = v;
            cp_async16(smem_u32(&Bs0[row * SPAD + c4 * 4]),
                       &Bt[(size_t)(bn + row) * K + c4 * 4]);
        }
        CP_COMMIT();
        if (iters > 1) {
            float* Bs1 = sh + STAGE_FLOATS + 128 * SPAD;
#pragma unroll
            for (int q = 0; q < 4; q++) {
                int c = q * 256 + tid;
                int row = c >> 3, c4 = c & 7;
                aregs[q] = *(const float4*)&A[(size_t)(bm + row) * K + 32 + c4 * 4];
                cp_async16(smem_u32(&Bs1[row * SPAD + c4 * 4]),
                           &Bt[(size_t)(bn + row) * K + 32 + c4 * 4]);
            }
            CP_COMMIT();
        }
    }

    for (int i = 0; i < iters; i++) {
        if (i + 1 < iters) { CP_WAIT(1); } else { CP_WAIT(0); }
        __syncthreads();

        if (i + 2 < iters) {
            float* Bs = sh + ((i + 2) % STAGES) * STAGE_FLOATS + 128 * SPAD;
            const int k0 = (i + 2) * 32;
#pragma unroll
            for (int q = 0; q < 4; q++) {
                int c = q * 256 + tid;
                int row = c >> 3, c4 = c & 7;
                cp_async16(smem_u32(&Bs[row * SPAD + c4 * 4]),
                           &Bt[(size_t)(bn + row) * K + k0 + c4 * 4]);
            }
            CP_COMMIT();
        }
        if (i + 1 < iters) {
            float* As = sh + ((i + 1) % STAGES) * STAGE_FLOATS;
#pragma unroll
            for (int q = 0; q < 4; q++) {
                int c = q * 256 + tid;
                int row = c >> 3, c4 = c & 7;
                float4 v = aregs[q];
                v.x = to_tf32(v.x); v.y = to_tf32(v.y); v.z = to_tf32(v.z); v.w = to_tf32(v.w);
                *(float4*)&As[row * SPAD + c4 * 4] = v;
            }
        }
        if (i + 2 < iters) {
            const int k0 = (i + 2) * 32;
#pragma unroll
            for (int q = 0; q < 4; q++) {
                int c = q * 256 + tid;
                int row = c >> 3, c4 = c & 7;
                aregs[q] = *(const float4*)&A[(size_t)(bm + row) * K + k0 + c4 * 4];
            }
        }

        const float* As = sh + (i % STAGES) * STAGE_FLOATS;
        const float* Bs = As + 128 * SPAD;
#pragma unroll
        for (int k8 = 0; k8 < 4; k8++) {
            uint32_t af[4][4], bf[4][2];
            const int kc = k8 * 8 + t;
#pragma unroll
            for (int mt = 0; mt < 4; mt++) {
                const int r0 = moff + mt * 16 + g;
                af[mt][0] = __float_as_uint(As[r0 * SPAD + kc]);
                af[mt][1] = __float_as_uint(As[(r0 + 8) * SPAD + kc]);
                af[mt][2] = __float_as_uint(As[r0 * SPAD + kc + 4]);
                af[mt][3] = __float_as_uint(As[(r0 + 8) * SPAD + kc + 4]);
            }
#pragma unroll
            for (int nt = 0; nt < 4; nt++) {
                const int n0 = noff + nt * 8 + g;
                bf[nt][0] = __float_as_uint(Bs[n0 * SPAD + kc]);
                bf[nt][1] = __float_as_uint(Bs[n0 * SPAD + kc + 4]);
            }
#pragma unroll
            for (int mt = 0; mt < 4; mt++)
#pragma unroll
                for (int nt = 0; nt < 4; nt++)
                    mma_tf32(acc[mt][nt][0], acc[mt][nt][1], acc[mt][nt][2], acc[mt][nt][3],
                             af[mt][0], af[mt][1], af[mt][2], af[mt][3],
                             bf[nt][0], bf[nt][1]);
        }
    }

#pragma unroll
    for (int nt = 0; nt < 4; nt++) {
        const int col = bn + noff + nt * 8 + 2 * t;
        const float2 bv = *(const float2*)&bias[col];
#pragma unroll
        for (int mt = 0; mt < 4; mt++) {
            const int r0 = bm + moff + mt * 16 + g;
            float2 v0, v1;
            v0.x = acc[mt][nt][0] + bv.x;
            v0.y = acc[mt][nt][1] + bv.y;
            v1.x = acc[mt][nt][2] + bv.x;
            v1.y = acc[mt][nt][3] + bv.y;
            if (EPI == 1) {
                v0.x = gelu_fn(v0.x); v0.y = gelu_fn(v0.y);
                v1.x = gelu_fn(v1.x); v1.y = gelu_fn(v1.y);
            }
            if (EPI == 2) {
                v0.x = to_tf32(v0.x); v0.y = to_tf32(v0.y);
                v1.x = to_tf32(v1.x); v1.y = to_tf32(v1.y);
            }
            *(float2*)&C[(size_t)r0 * N + col] = v0;
            *(float2*)&C[(size_t)(r0 + 8) * N + col] = v1;
        }
    }
}

// ---------------------------------------------------------------------------
// Flash attention on tensor cores (tf32 mma.sync).
// CTA: 128 queries x (head, batch). 8 warps, 16 query rows each.
// Key blocks of 64, d = 64. K/V double-buffered via cp.async.
// Q lives in A-fragments (regs) for the whole kernel; its smem region is
// recycled as the P (probability) tile between the two GEMMs.
// ---------------------------------------------------------------------------
#define BQ   128
#define BKV  64
#define KPAD 68
#define NKB  (SEQ / BKV)
#define ATT2_SMEM ((4 * BKV * KPAD + BQ * KPAD) * 4)   // 104448 B

__global__ void __launch_bounds__(256) attn_mma_kernel(
    const float* __restrict__ Qg, const float* __restrict__ Kg,
    const float* __restrict__ Vg, float* __restrict__ Og)
{
    extern __shared__ float sh[];
    float* Ks = sh;                       // [2][BKV][KPAD]
    float* Vs = sh + 2 * BKV * KPAD;      // [2][BKV][KPAD]
    float* Ps = sh + 4 * BKV * KPAD;      // [BQ][KPAD]  (Q staging, then P)

    const int tid  = threadIdx.x;
    const int wid  = tid >> 5;
    const int lane = tid & 31;
    const int g    = lane >> 2;
    const int t    = lane & 3;
    const int qt   = blockIdx.x;
    const int head = blockIdx.y;
    const int b    = blockIdx.z;

    const size_t base = ((size_t)b * SEQ) * HID + (size_t)head * DK;
    const int q0   = qt * BQ;
    const int moff = wid * 16;

    // prologue: Q (into Ps) + K0/V0, one cp.async group
#pragma unroll
    for (int q = 0; q < 8; q++) {
        int c = q * 256 + tid;
        int r = c >> 4, d4 = c & 15;
        cp_async16(smem_u32(&Ps[r * KPAD + d4 * 4]),
                   &Qg[base + (size_t)(q0 + r) * HID + d4 * 4]);
    }
#pragma unroll
    for (int q = 0; q < 4; q++) {
        int c = q * 256 + tid;
        int r = c >> 4, d4 = c & 15;
        cp_async16(smem_u32(&Ks[r * KPAD + d4 * 4]),
                   &Kg[base + (size_t)r * HID + d4 * 4]);
        cp_async16(smem_u32(&Vs[r * KPAD + d4 * 4]),
                   &Vg[base + (size_t)r * HID + d4 * 4]);
    }
    CP_COMMIT();

    uint32_t qf[8][4];
    float oacc[8][4];
#pragma unroll
    for (int nt = 0; nt < 8; nt++)
#pragma unroll
        for (int c = 0; c < 4; c++) oacc[nt][c] = 0.0f;
    float m0 = -1e30f, m1 = -1e30f, l0 = 0.0f, l1 = 0.0f;

    for (int i = 0; i < NKB; i++) {
        if (i + 1 < NKB) {
            const int kn = (i + 1) * BKV;
            float* Kb = Ks + ((i + 1) & 1) * BKV * KPAD;
            float* Vb = Vs + ((i + 1) & 1) * BKV * KPAD;
#pragma unroll
            for (int q = 0; q < 4; q++) {
                int c = q * 256 + tid;
                int r = c >> 4, d4 = c & 15;
                cp_async16(smem_u32(&Kb[r * KPAD + d4 * 4]),
                           &Kg[base + (size_t)(kn + r) * HID + d4 * 4]);
                cp_async16(smem_u32(&Vb[r * KPAD + d4 * 4]),
                           &Vg[base + (size_t)(kn + r) * HID + d4 * 4]);
            }
            CP_COMMIT();
            CP_WAIT(1);
        } else {
            CP_WAIT(0);
        }
        __syncthreads();

        if (i == 0) {
            // Q fragments (warp-private rows of Ps; read once, region reused for P)
#pragma unroll
            for (int ks = 0; ks < 8; ks++) {
                const int kc = ks * 8 + t;
                qf[ks][0] = __float_as_uint(Ps[(moff + g) * KPAD + kc]);
                qf[ks][1] = __float_as_uint(Ps[(moff + 8 + g) * KPAD + kc]);
                qf[ks][2] = __float_as_uint(Ps[(moff + g) * KPAD + kc + 4]);
                qf[ks][3] = __float_as_uint(Ps[(moff + 8 + g) * KPAD + kc + 4]);
            }
        }

        const float* Kb = Ks + (i & 1) * BKV * KPAD;
        const float* Vb = Vs + (i & 1) * BKV * KPAD;

        // ---- S = Q K^T ----
        float sacc[8][4];
#pragma unroll
        for (int nt = 0; nt < 8; nt++)
#pragma unroll
            for (int c = 0; c < 4; c++) sacc[nt][c] = 0.0f;

#pragma unroll
        for (int ks = 0; ks < 8; ks++) {
            const int kc = ks * 8 + t;
            uint32_t b0[8], b1[8];
#pragma unroll
            for (int nt = 0; nt < 8; nt++) {
                b0[nt] = __float_as_uint(Kb[(nt * 8 + g) * KPAD + kc]);
                b1[nt] = __float_as_uint(Kb[(nt * 8 + g) * KPAD + kc + 4]);
            }
#pragma unroll
            for (int nt = 0; nt < 8; nt++)
                mma_tf32(sacc[nt][0], sacc[nt][1], sacc[nt][2], sacc[nt][3],
                         qf[ks][0], qf[ks][1], qf[ks][2], qf[ks][3],
                         b0[nt], b1[nt]);
        }

        // ---- online softmax on fragments ----
        float rx0 = -1e30f, rx1 = -1e30f;
#pragma unroll
        for (int nt = 0; nt < 8; nt++) {
            sacc[nt][0] *= 0.125f; sacc[nt][1] *= 0.125f;
            sacc[nt][2] *= 0.125f; sacc[nt][3] *= 0.125f;
            rx0 = fmaxf(rx0, fmaxf(sacc[nt][0], sacc[nt][1]));
            rx1 = fmaxf(rx1, fmaxf(sacc[nt][2], sacc[nt][3]));
        }
        rx0 = fmaxf(rx0, __shfl_xor_sync(0xffffffffu, rx0, 1));
        rx0 = fmaxf(rx0, __shfl_xor_sync(0xffffffffu, rx0, 2));
        rx1 = fmaxf(rx1, __shfl_xor_sync(0xffffffffu, rx1, 1));
        rx1 = fmaxf(rx1, __shfl_xor_sync(0xffffffffu, rx1, 2));

        const float nm0 = fmaxf(m0, rx0);
        const float nm1 = fmaxf(m1, rx1);
        const float corr0 = __expf(m0 - nm0);
        const float corr1 = __expf(m1 - nm1);

        float rs0 = 0.0f, rs1 = 0.0f;
#pragma unroll
        for (int nt = 0; nt < 8; nt++) {
            sacc[nt][0] = __expf(sacc[nt][0] - nm0);
            sacc[nt][1] = __expf(sacc[nt][1] - nm0);
            sacc[nt][2] = __expf(sacc[nt][2] - nm1);
            sacc[nt][3] = __expf(sacc[nt][3] - nm1);
            rs0 += sacc[nt][0] + sacc[nt][1];
            rs1 += sacc[nt][2] + sacc[nt][3];
        }
        rs0 += __shfl_xor_sync(0xffffffffu, rs0, 1);
        rs0 += __shfl_xor_sync(0xffffffffu, rs0, 2);
        rs1 += __shfl_xor_sync(0xffffffffu, rs1, 1);
        rs1 += __shfl_xor_sync(0xffffffffu, rs1, 2);

        l0 = l0 * corr0 + rs0;  m0 = nm0;
        l1 = l1 * corr1 + rs1;  m1 = nm1;

#pragma unroll
        for (int nt = 0; nt < 8; nt++) {
            oacc[nt][0] *= corr0; oacc[nt][1] *= corr0;
            oacc[nt][2] *= corr1; oacc[nt][3] *= corr1;
        }

        // ---- P -> smem (tf32-rounded), warp-private rows ----
#pragma unroll
        for (int nt = 0; nt < 8; nt++) {
            float2 p0, p1;
            p0.x = to_tf32(sacc[nt][0]); p0.y = to_tf32(sacc[nt][1]);
            p1.x = to_tf32(sacc[nt][2]); p1.y = to_tf32(sacc[nt][3]);
            *(float2*)&Ps[(moff + g) * KPAD + nt * 8 + 2 * t] = p0;
            *(float2*)&Ps[(moff + 8 + g) * KPAD + nt * 8 + 2 * t] = p1;
        }
        __syncwarp();

        // ---- O += P @ V ----
#pragma unroll
        for (int ks = 0; ks < 8; ks++) {
            const int kc = ks * 8 + t;
            const uint32_t a0 = __float_as_uint(Ps[(moff + g) * KPAD + kc]);
            const uint32_t a1 = __float_as_uint(Ps[(moff + 8 + g) * KPAD + kc]);
            const uint32_t a2 = __float_as_uint(Ps[(moff + g) * KPAD + kc + 4]);
            const uint32_t a3 = __float_as_uint(Ps[(moff + 8 + g) * KPAD + kc + 4]);
#pragma unroll
            for (int nt = 0; nt < 8; nt++) {
                const uint32_t b0 = __float_as_uint(Vb[(ks * 8 + t) * KPAD + nt * 8 + g]);
                const uint32_t b1 = __float_as_uint(Vb[(ks * 8 + t + 4) * KPAD + nt * 8 + g]);
                mma_tf32(oacc[nt][0], oacc[nt][1], oacc[nt][2], oacc[nt][3],
                         a0, a1, a2, a3, b0, b1);
            }
        }
        __syncthreads();
    }

    // epilogue: normalize, write ctx
    const float inv0 = 1.0f / l0;
    const float inv1 = 1.0f / l1;
    const int r0 = q0 + moff + g;
    const int r1 = r0 + 8;
#pragma unroll
    for (int nt = 0; nt < 8; nt++) {
        const int col = nt * 8 + 2 * t;
        float2 v0, v1;
        v0.x = oacc[nt][0] * inv0; v0.y = oacc[nt][1] * inv0;
        v1.x = oacc[nt][2] * inv1; v1.y = oacc[nt][3] * inv1;
        *(float2*)&Og[base + (size_t)r0 * HID + col] = v0;
        *(float2*)&Og[base + (size_t)r1 * HID + col] = v1;
    }
}

// ---------------------------------------------------------------------------
// Residual add + LayerNorm
// ---------------------------------------------------------------------------
__global__ void __launch_bounds__(256) add_ln_kernel(
    const float* __restrict__ X, const float* __restrict__ Y,
    const float* __restrict__ g, const float* __restrict__ be,
    float* __restrict__ out)
{
    const int row = blockIdx.x;
    const int tid = threadIdx.x;
    const size_t base = (size_t)row * HID;

    float v[4];
    float s = 0.0f, s2 = 0.0f;
#pragma unroll
    for (int k = 0; k < 4; k++) {
        int c = tid + k * 256;
        float t = X[base + c] + Y[base + c];
        v[k] = t;
        s += t;
        s2 += t * t;
    }
#pragma unroll
    for (int off = 16; off > 0; off >>= 1) {
        s  += __shfl_xor_sync(0xffffffffu, s,  off);
        s2 += __shfl_xor_sync(0xffffffffu, s2, off);
    }
    __shared__ float red[16];
    const int warp = tid >> 5, lane = tid & 31;
    if (lane == 0) { red[warp] = s; red[warp + 8] = s2; }
    __syncthreads();
    if (tid < 32) {
        float a = (lane < 8) ? red[lane]     : 0.0f;
        float c2 = (lane < 8) ? red[lane + 8] : 0.0f;
#pragma unroll
        for (int off = 4; off > 0; off >>= 1) {
            a  += __shfl_xor_sync(0xffffffffu, a,  off);
            c2 += __shfl_xor_sync(0xffffffffu, c2, off);
        }
        if (lane == 0) { red[0] = a; red[1] = c2; }
    }
    __syncthreads();
    const float mu  = red[0] * (1.0f / HID);
    const float var = red[1] * (1.0f / HID) - mu * mu;
    const float inv = rsqrtf(var + 1e-5f);
#pragma unroll
    for (int k = 0; k < 4; k++) {
        int c = tid + k * 256;
        out[base + c] = (v[k] - mu) * inv * g[c] + be[c];
    }
}

// ---------------------------------------------------------------------------
// kernel_launch
// ---------------------------------------------------------------------------
extern "C" void kernel_launch(void* const* d_in, const int* in_sizes, int n_in,
                              void* d_out, int out_size)
{
    const float* x  = (const float*)d_in[0];
    const float* Wq = (const float*)d_in[1];
    const float* bq = (const float*)d_in[2];
    const float* Wk = (const float*)d_in[3];
    const float* bk = (const float*)d_in[4];
    const float* Wv = (const float*)d_in[5];
    const float* bv = (const float*)d_in[6];
    const float* Wo = (const float*)d_in[7];
    const float* bo = (const float*)d_in[8];
    const float* W1 = (const float*)d_in[9];
    const float* b1 = (const float*)d_in[10];
    const float* W2 = (const float*)d_in[11];
    const float* b2 = (const float*)d_in[12];
    const float* g1 = (const float*)d_in[13];
    const float* be1= (const float*)d_in[14];
    const float* g2 = (const float*)d_in[15];
    const float* be2= (const float*)d_in[16];
    float* out = (float*)d_out;

    float *pq, *pk, *pv, *pctx, *pao, *px1, *ph, *pff;
    float *wqt, *wkt, *wvt, *wot, *w1t, *w2t;
    cudaGetSymbolAddress((void**)&pq,   g_q);
    cudaGetSymbolAddress((void**)&pk,   g_k);
    cudaGetSymbolAddress((void**)&pv,   g_v);
    cudaGetSymbolAddress((void**)&pctx, g_ctx);
    cudaGetSymbolAddress((void**)&pao,  g_ao);
    cudaGetSymbolAddress((void**)&px1,  g_x1);
    cudaGetSymbolAddress((void**)&ph,   g_h);
    cudaGetSymbolAddress((void**)&pff,  g_ff);
    cudaGetSymbolAddress((void**)&wqt,  g_wqt);
    cudaGetSymbolAddress((void**)&wkt,  g_wkt);
    cudaGetSymbolAddress((void**)&wvt,  g_wvt);
    cudaGetSymbolAddress((void**)&wot,  g_wot);
    cudaGetSymbolAddress((void**)&w1t,  g_w1t);
    cudaGetSymbolAddress((void**)&w2t,  g_w2t);

    cudaFuncSetAttribute(attn_mma_kernel,
                         cudaFuncAttributeMaxDynamicSharedMemorySize, ATT2_SMEM);
    cudaFuncSetAttribute(mma_gemm<0>,
                         cudaFuncAttributeMaxDynamicSharedMemorySize, GEMM_SMEM);
    cudaFuncSetAttribute(mma_gemm<1>,
                         cudaFuncAttributeMaxDynamicSharedMemorySize, GEMM_SMEM);
    cudaFuncSetAttribute(mma_gemm<2>,
                         cudaFuncAttributeMaxDynamicSharedMemorySize, GEMM_SMEM);

    const dim3 blk256(256);

    // weight transposes (tf32-rounded)
    transpose_tf32_kernel<<<dim3(HID/32, HID/32), blk256>>>(Wq, wqt, HID, HID);
    transpose_tf32_kernel<<<dim3(HID/32, HID/32), blk256>>>(Wk, wkt, HID, HID);
    transpose_tf32_kernel<<<dim3(HID/32, HID/32), blk256>>>(Wv, wvt, HID, HID);
    transpose_tf32_kernel<<<dim3(HID/32, HID/32), blk256>>>(Wo, wot, HID, HID);
    transpose_tf32_kernel<<<dim3(DFF/32, HID/32), blk256>>>(W1, w1t, HID, DFF);
    transpose_tf32_kernel<<<dim3(HID/32, DFF/32), blk256>>>(W2, w2t, DFF, HID);

    const dim3 gProj(HID / 128, MTOT / 128);   // (8, 64)
    const dim3 gFF1 (DFF / 128, MTOT / 128);   // (32, 64)

    // QKV projections (EPI=2: emit tf32-rounded operands for attention)
    mma_gemm<2><<<gProj, blk256, GEMM_SMEM>>>(x, wqt, bq, pq, MTOT, HID, HID);
    mma_gemm<2><<<gProj, blk256, GEMM_SMEM>>>(x, wkt, bk, pk, MTOT, HID, HID);
    mma_gemm<2><<<gProj, blk256, GEMM_SMEM>>>(x, wvt, bv, pv, MTOT, HID, HID);

    // Attention (tensor cores)
    attn_mma_kernel<<<dim3(SEQ / BQ, NHEAD, BATCH), blk256, ATT2_SMEM>>>(pq, pk, pv, pctx);

    // Output projection + residual/LN1
    mma_gemm<0><<<gProj, blk256, GEMM_SMEM>>>(pctx, wot, bo, pao, MTOT, HID, HID);
    add_ln_kernel<<<MTOT, blk256>>>(x, pao, g1, be1, px1);

    // FFN
    mma_gemm<1><<<gFF1, blk256, GEMM_SMEM>>>(px1, w1t, b1, ph, MTOT, DFF, HID);
    mma_gemm<0><<<gProj, blk256, GEMM_SMEM>>>(ph, w2t, b2, pff, MTOT, HID, DFF);

    // Residual/LN2 -> output
    add_ln_kernel<<<MTOT, blk256>>>(px1, pff, g2, be2, out);
}

// round 6
// speedup vs baseline: 5.6209x; 2.0450x over previous
#include <cuda_runtime.h>
#include <cuda_fp16.h>
#include <math.h>
#include <cstdint>

// Problem constants
#define BATCH 4
#define SEQ   2048
#define HID   1024
#define NHEAD 16
#define DK    64
#define DFF   4096
#define MTOT  (BATCH * SEQ)          // 8192 rows

// ---------------------------------------------------------------------------
// Scratch
// ---------------------------------------------------------------------------
__device__ __half g_xh [MTOT * HID];   // half copy of input x
__device__ __half g_qh [MTOT * HID];
__device__ __half g_kh [MTOT * HID];
__device__ __half g_vh [MTOT * HID];
__device__ __half g_ctxh[MTOT * HID];
__device__ float  g_ao [MTOT * HID];
__device__ float  g_x1 [MTOT * HID];
__device__ __half g_x1h[MTOT * HID];
__device__ __half g_hh [MTOT * DFF];
__device__ float  g_ff [MTOT * HID];
// transposed fp16 weights: Wt[n][k]
__device__ __half g_wqt[HID * HID];
__device__ __half g_wkt[HID * HID];
__device__ __half g_wvt[HID * HID];
__device__ __half g_wot[HID * HID];
__device__ __half g_w1t[HID * DFF];
__device__ __half g_w2t[DFF * HID];

// ---------------------------------------------------------------------------
// helpers
// ---------------------------------------------------------------------------
__device__ __forceinline__ uint32_t smem_u32(const void* p) {
    uint32_t a;
    asm("{ .reg .u64 t; cvta.to.shared.u64 t, %1; cvt.u32.u64 %0, t; }" : "=r"(a) : "l"(p));
    return a;
}
__device__ __forceinline__ void cp_async16(uint32_t saddr, const void* gaddr) {
    asm volatile("cp.async.cg.shared.global [%0], [%1], 16;" :: "r"(saddr), "l"(gaddr) : "memory");
}
#define CP_COMMIT() asm volatile("cp.async.commit_group;" ::: "memory")
#define CP_WAIT(n)  asm volatile("cp.async.wait_group %0;" :: "n"(n) : "memory")

__device__ __forceinline__ void mma_f16(
    float& d0, float& d1, float& d2, float& d3,
    uint32_t a0, uint32_t a1, uint32_t a2, uint32_t a3,
    uint32_t b0, uint32_t b1)
{
    asm volatile(
        "mma.sync.aligned.m16n8k16.row.col.f32.f16.f16.f32 "
        "{%0,%1,%2,%3}, {%4,%5,%6,%7}, {%8,%9}, {%0,%1,%2,%3};"
        : "+f"(d0), "+f"(d1), "+f"(d2), "+f"(d3)
        : "r"(a0), "r"(a1), "r"(a2), "r"(a3), "r"(b0), "r"(b1));
}
__device__ __forceinline__ void ldmatrix_x4_trans(
    uint32_t& r0, uint32_t& r1, uint32_t& r2, uint32_t& r3, uint32_t addr)
{
    asm volatile("ldmatrix.sync.aligned.m8n8.x4.trans.shared.b16 {%0,%1,%2,%3}, [%4];"
                 : "=r"(r0), "=r"(r1), "=r"(r2), "=r"(r3) : "r"(addr));
}

__device__ __forceinline__ float gelu_fn(float x) {
    const float c = 0.7978845608028654f;
    float x3 = x * x * x;
    return 0.5f * x * (1.0f + tanhf(c * (x + 0.044715f * x3)));
}

// ---------------------------------------------------------------------------
// Weight transpose to fp16:  Wt[n][k] = half(W[k][n])
// ---------------------------------------------------------------------------
__global__ void __launch_bounds__(256) transpose_h_kernel(
    const float* __restrict__ W, __half* __restrict__ Wt, int K, int N)
{
    __shared__ float t[32][33];
    const int bx = blockIdx.x * 32;
    const int by = blockIdx.y * 32;
    const int tx = threadIdx.x & 31;
    const int ty = threadIdx.x >> 5;
#pragma unroll
    for (int q = 0; q < 4; q++)
        t[ty + q * 8][tx] = W[(size_t)(by + ty + q * 8) * N + bx + tx];
    __syncthreads();
#pragma unroll
    for (int q = 0; q < 4; q++)
        Wt[(size_t)(bx + ty + q * 8) * K + by + tx] = __float2half_rn(t[tx][ty + q * 8]);
}

// x (fp32) -> xh (fp16)
__global__ void __launch_bounds__(256) convert_h_kernel(
    const float* __restrict__ X, __half* __restrict__ Xh)
{
    const int i = (blockIdx.x * 256 + threadIdx.x) * 8;
    float4 a = *(const float4*)&X[i];
    float4 b = *(const float4*)&X[i + 4];
    __half2 h[4];
    h[0] = __floats2half2_rn(a.x, a.y);
    h[1] = __floats2half2_rn(a.z, a.w);
    h[2] = __floats2half2_rn(b.x, b.y);
    h[3] = __floats2half2_rn(b.z, b.w);
    *(uint4*)&Xh[i] = *(uint4*)h;
}

// ---------------------------------------------------------------------------
// fp16 mma.sync GEMM:  C[M,N] = A[M,K] @ W[K,N] + bias   (W given as Wt[n][k])
// CTA tile 128x128, BK=64 halves, 3-stage cp.async pipeline, 8 warps (2m x 4n),
// warp tile 64x32 = 4x4 m16n8k16 mma tiles. Rows padded to 72 halves.
// EPI: 0 = fp32 out, 1 = half out, 2 = half out + GELU
// ---------------------------------------------------------------------------
#define HPAD 72
#define STAGE_H (2 * 128 * HPAD)                       // A then B (halves)
#define GEMM_SMEM (3 * STAGE_H * 2)                    // 110592 bytes

__device__ __forceinline__ void fill_stage(
    __half* As, __half* Bs, const __half* A, const __half* Bt,
    int bm, int bn, int k0, int K, int tid)
{
#pragma unroll
    for (int q = 0; q < 4; q++) {
        int idx = q * 256 + tid;
        int row = idx >> 3, c = idx & 7;
        cp_async16(smem_u32(&As[row * HPAD + c * 8]),
                   &A[(size_t)(bm + row) * K + k0 + c * 8]);
        cp_async16(smem_u32(&Bs[row * HPAD + c * 8]),
                   &Bt[(size_t)(bn + row) * K + k0 + c * 8]);
    }
}

template<int EPI>
__global__ void __launch_bounds__(256) mma_gemm_h(
    const __half* __restrict__ A, const __half* __restrict__ Bt,
    const float* __restrict__ bias, void* __restrict__ Cout,
    int M, int N, int K)
{
    extern __shared__ __half shh[];
    const int tid  = threadIdx.x;
    const int wid  = tid >> 5;
    const int lane = tid & 31;
    const int g    = lane >> 2;
    const int t    = lane & 3;
    const int bm   = blockIdx.y * 128;
    const int bn   = blockIdx.x * 128;
    const int moff = (wid >> 2) * 64;
    const int noff = (wid & 3) * 32;

    const int iters = K >> 6;

    float acc[4][4][4];
#pragma unroll
    for (int a = 0; a < 4; a++)
#pragma unroll
        for (int b = 0; b < 4; b++)
#pragma unroll
            for (int c = 0; c < 4; c++) acc[a][b][c] = 0.0f;

    fill_stage(shh, shh + 128 * HPAD, A, Bt, bm, bn, 0, K, tid);
    CP_COMMIT();
    fill_stage(shh + STAGE_H, shh + STAGE_H + 128 * HPAD, A, Bt, bm, bn, 64, K, tid);
    CP_COMMIT();

    for (int i = 0; i < iters; i++) {
        if (i + 1 < iters) { CP_WAIT(1); } else { CP_WAIT(0); }
        __syncthreads();

        if (i + 2 < iters) {
            __half* st = shh + ((i + 2) % 3) * STAGE_H;
            fill_stage(st, st + 128 * HPAD, A, Bt, bm, bn, (i + 2) * 64, K, tid);
            CP_COMMIT();
        }

        const __half* As = shh + (i % 3) * STAGE_H;
        const __half* Bs = As + 128 * HPAD;
#pragma unroll
        for (int ks = 0; ks < 4; ks++) {
            const int kc = ks * 16 + 2 * t;
            uint32_t af[4][4], bf[4][2];
#pragma unroll
            for (int mt = 0; mt < 4; mt++) {
                const int r0 = moff + mt * 16 + g;
                af[mt][0] = *(const uint32_t*)&As[r0 * HPAD + kc];
                af[mt][1] = *(const uint32_t*)&As[(r0 + 8) * HPAD + kc];
                af[mt][2] = *(const uint32_t*)&As[r0 * HPAD + kc + 8];
                af[mt][3] = *(const uint32_t*)&As[(r0 + 8) * HPAD + kc + 8];
            }
#pragma unroll
            for (int nt = 0; nt < 4; nt++) {
                const int n0 = noff + nt * 8 + g;
                bf[nt][0] = *(const uint32_t*)&Bs[n0 * HPAD + kc];
                bf[nt][1] = *(const uint32_t*)&Bs[n0 * HPAD + kc + 8];
            }
#pragma unroll
            for (int mt = 0; mt < 4; mt++)
#pragma unroll
                for (int nt = 0; nt < 4; nt++)
                    mma_f16(acc[mt][nt][0], acc[mt][nt][1], acc[mt][nt][2], acc[mt][nt][3],
                            af[mt][0], af[mt][1], af[mt][2], af[mt][3],
                            bf[nt][0], bf[nt][1]);
        }
    }

    // epilogue
#pragma unroll
    for (int nt = 0; nt < 4; nt++) {
        const int col = bn + noff + nt * 8 + 2 * t;
        const float2 bv = *(const float2*)&bias[col];
#pragma unroll
        for (int mt = 0; mt < 4; mt++) {
            const int r0 = bm + moff + mt * 16 + g;
            float c0 = acc[mt][nt][0] + bv.x;
            float c1 = acc[mt][nt][1] + bv.y;
            float c2 = acc[mt][nt][2] + bv.x;
            float c3 = acc[mt][nt][3] + bv.y;
            if (EPI == 2) {
                c0 = gelu_fn(c0); c1 = gelu_fn(c1);
                c2 = gelu_fn(c2); c3 = gelu_fn(c3);
            }
            if (EPI == 0) {
                float* C = (float*)Cout;
                *(float2*)&C[(size_t)r0 * N + col]       = make_float2(c0, c1);
                *(float2*)&C[(size_t)(r0 + 8) * N + col] = make_float2(c2, c3);
            } else {
                __half* C = (__half*)Cout;
                *(__half2*)&C[(size_t)r0 * N + col]       = __floats2half2_rn(c0, c1);
                *(__half2*)&C[(size_t)(r0 + 8) * N + col] = __floats2half2_rn(c2, c3);
            }
        }
    }
}

// ---------------------------------------------------------------------------
// Flash attention, fp16 mma (m16n8k16).
// CTA: 128 queries x (head, batch). 8 warps x 16 query rows. Key blocks of 64.
// Q lives in fragments; its smem tile is recycled as the P tile.
// V fragments via ldmatrix.x4.trans.
// ---------------------------------------------------------------------------
#define BQ   128
#define BKV  64
#define NKB  (SEQ / BKV)
#define ATT_SMEM ((4 * BKV * HPAD + BQ * HPAD) * 2)    // 55296 B

__global__ void __launch_bounds__(256) attn_mma_h_kernel(
    const __half* __restrict__ Qg, const __half* __restrict__ Kg,
    const __half* __restrict__ Vg, __half* __restrict__ Og)
{
    extern __shared__ __half sha[];
    __half* Ks = sha;                        // [2][BKV][HPAD]
    __half* Vs = sha + 2 * BKV * HPAD;       // [2][BKV][HPAD]
    __half* Ps = sha + 4 * BKV * HPAD;       // [BQ][HPAD] (Q staging, then P)

    const int tid  = threadIdx.x;
    const int wid  = tid >> 5;
    const int lane = tid & 31;
    const int g    = lane >> 2;
    const int t    = lane & 3;
    const int qt   = blockIdx.x;
    const int head = blockIdx.y;
    const int b    = blockIdx.z;

    const size_t base = ((size_t)b * SEQ) * HID + (size_t)head * DK;
    const int q0   = qt * BQ;
    const int moff = wid * 16;

    // prologue: Q (into Ps) + K0/V0, one group
#pragma unroll
    for (int q = 0; q < 4; q++) {
        int idx = q * 256 + tid;
        int r = idx >> 3, c = idx & 7;
        cp_async16(smem_u32(&Ps[r * HPAD + c * 8]),
                   &Qg[base + (size_t)(q0 + r) * HID + c * 8]);
    }
#pragma unroll
    for (int q = 0; q < 2; q++) {
        int idx = q * 256 + tid;
        int r = idx >> 3, c = idx & 7;
        cp_async16(smem_u32(&Ks[r * HPAD + c * 8]),
                   &Kg[base + (size_t)r * HID + c * 8]);
        cp_async16(smem_u32(&Vs[r * HPAD + c * 8]),
                   &Vg[base + (size_t)r * HID + c * 8]);
    }
    CP_COMMIT();

    // per-lane ldmatrix base offset (halves) within a V buffer
    const uint32_t vlane_off = (uint32_t)((lane & 15) * HPAD + (lane >> 4) * 8);

    uint32_t qf[4][4];
    float oacc[8][4];
#pragma unroll
    for (int nt = 0; nt < 8; nt++)
#pragma unroll
        for (int c = 0; c < 4; c++) oacc[nt][c] = 0.0f;
    float m0 = -1e30f, m1 = -1e30f, l0 = 0.0f, l1 = 0.0f;

    for (int i = 0; i < NKB; i++) {
        if (i + 1 < NKB) {
            const int kn = (i + 1) * BKV;
            __half* Kb = Ks + ((i + 1) & 1) * BKV * HPAD;
            __half* Vb = Vs + ((i + 1) & 1) * BKV * HPAD;
#pragma unroll
            for (int q = 0; q < 2; q++) {
                int idx = q * 256 + tid;
                int r = idx >> 3, c = idx & 7;
                cp_async16(smem_u32(&Kb[r * HPAD + c * 8]),
                           &Kg[base + (size_t)(kn + r) * HID + c * 8]);
                cp_async16(smem_u32(&Vb[r * HPAD + c * 8]),
                           &Vg[base + (size_t)(kn + r) * HID + c * 8]);
            }
            CP_COMMIT();
            CP_WAIT(1);
        } else {
            CP_WAIT(0);
        }
        __syncthreads();

        if (i == 0) {
            // Q fragments from warp-private rows of Ps
#pragma unroll
            for (int ks = 0; ks < 4; ks++) {
                const int kc = ks * 16 + 2 * t;
                qf[ks][0] = *(const uint32_t*)&Ps[(moff + g) * HPAD + kc];
                qf[ks][1] = *(const uint32_t*)&Ps[(moff + 8 + g) * HPAD + kc];
                qf[ks][2] = *(const uint32_t*)&Ps[(moff + g) * HPAD + kc + 8];
                qf[ks][3] = *(const uint32_t*)&Ps[(moff + 8 + g) * HPAD + kc + 8];
            }
        }

        const __half* Kb = Ks + (i & 1) * BKV * HPAD;
        const __half* Vb = Vs + (i & 1) * BKV * HPAD;

        // ---- S = Q K^T ----
        float sacc[8][4];
#pragma unroll
        for (int nt = 0; nt < 8; nt++)
#pragma unroll
            for (int c = 0; c < 4; c++) sacc[nt][c] = 0.0f;

#pragma unroll
        for (int ks = 0; ks < 4; ks++) {
            const int kc = ks * 16 + 2 * t;
            uint32_t b0[8], b1[8];
#pragma unroll
            for (int nt = 0; nt < 8; nt++) {
                const int key = nt * 8 + g;
                b0[nt] = *(const uint32_t*)&Kb[key * HPAD + kc];
                b1[nt] = *(const uint32_t*)&Kb[key * HPAD + kc + 8];
            }
#pragma unroll
            for (int nt = 0; nt < 8; nt++)
                mma_f16(sacc[nt][0], sacc[nt][1], sacc[nt][2], sacc[nt][3],
                        qf[ks][0], qf[ks][1], qf[ks][2], qf[ks][3],
                        b0[nt], b1[nt]);
        }

        // ---- online softmax ----
        float rx0 = -1e30f, rx1 = -1e30f;
#pragma unroll
        for (int nt = 0; nt < 8; nt++) {
            sacc[nt][0] *= 0.125f; sacc[nt][1] *= 0.125f;
            sacc[nt][2] *= 0.125f; sacc[nt][3] *= 0.125f;
            rx0 = fmaxf(rx0, fmaxf(sacc[nt][0], sacc[nt][1]));
            rx1 = fmaxf(rx1, fmaxf(sacc[nt][2], sacc[nt][3]));
        }
        rx0 = fmaxf(rx0, __shfl_xor_sync(0xffffffffu, rx0, 1));
        rx0 = fmaxf(rx0, __shfl_xor_sync(0xffffffffu, rx0, 2));
        rx1 = fmaxf(rx1, __shfl_xor_sync(0xffffffffu, rx1, 1));
        rx1 = fmaxf(rx1, __shfl_xor_sync(0xffffffffu, rx1, 2));

        const float nm0 = fmaxf(m0, rx0);
        const float nm1 = fmaxf(m1, rx1);
        const float corr0 = __expf(m0 - nm0);
        const float corr1 = __expf(m1 - nm1);

        float rs0 = 0.0f, rs1 = 0.0f;
#pragma unroll
        for (int nt = 0; nt < 8; nt++) {
            sacc[nt][0] = __expf(sacc[nt][0] - nm0);
            sacc[nt][1] = __expf(sacc[nt][1] - nm0);
            sacc[nt][2] = __expf(sacc[nt][2] - nm1);
            sacc[nt][3] = __expf(sacc[nt][3] - nm1);
            rs0 += sacc[nt][0] + sacc[nt][1];
            rs1 += sacc[nt][2] + sacc[nt][3];
        }
        rs0 += __shfl_xor_sync(0xffffffffu, rs0, 1);
        rs0 += __shfl_xor_sync(0xffffffffu, rs0, 2);
        rs1 += __shfl_xor_sync(0xffffffffu, rs1, 1);
        rs1 += __shfl_xor_sync(0xffffffffu, rs1, 2);

        l0 = l0 * corr0 + rs0;  m0 = nm0;
        l1 = l1 * corr1 + rs1;  m1 = nm1;

#pragma unroll
        for (int nt = 0; nt < 8; nt++) {
            oacc[nt][0] *= corr0; oacc[nt][1] *= corr0;
            oacc[nt][2] *= corr1; oacc[nt][3] *= corr1;
        }

        // ---- P -> smem (half2), warp-private rows ----
#pragma unroll
        for (int nt = 0; nt < 8; nt++) {
            *(__half2*)&Ps[(moff + g) * HPAD + nt * 8 + 2 * t] =
                __floats2half2_rn(sacc[nt][0], sacc[nt][1]);
            *(__half2*)&Ps[(moff + 8 + g) * HPAD + nt * 8 + 2 * t] =
                __floats2half2_rn(sacc[nt][2], sacc[nt][3]);
        }
        __syncwarp();

        // ---- O += P @ V ----  (V fragments via ldmatrix.x4.trans)
        const uint32_t vbase = smem_u32(Vb) + vlane_off * 2;
#pragma unroll
        for (int ks = 0; ks < 4; ks++) {
            const int kc = ks * 16 + 2 * t;
            const uint32_t a0 = *(const uint32_t*)&Ps[(moff + g) * HPAD + kc];
            const uint32_t a1 = *(const uint32_t*)&Ps[(moff + 8 + g) * HPAD + kc];
            const uint32_t a2 = *(const uint32_t*)&Ps[(moff + g) * HPAD + kc + 8];
            const uint32_t a3 = *(const uint32_t*)&Ps[(moff + 8 + g) * HPAD + kc + 8];
            const uint32_t vrow = vbase + (uint32_t)(ks * 16 * HPAD * 2);
#pragma unroll
            for (int n16 = 0; n16 < 4; n16++) {
                uint32_t r0, r1, r2, r3;
                ldmatrix_x4_trans(r0, r1, r2, r3, vrow + (uint32_t)(n16 * 32));
                mma_f16(oacc[n16 * 2][0], oacc[n16 * 2][1], oacc[n16 * 2][2], oacc[n16 * 2][3],
                        a0, a1, a2, a3, r0, r1);
                mma_f16(oacc[n16 * 2 + 1][0], oacc[n16 * 2 + 1][1],
                        oacc[n16 * 2 + 1][2], oacc[n16 * 2 + 1][3],
                        a0, a1, a2, a3, r2, r3);
            }
        }
        __syncthreads();
    }

    // epilogue: normalize, write ctx (half)
    const float inv0 = 1.0f / l0;
    const float inv1 = 1.0f / l1;
    const int r0 = q0 + moff + g;
    const int r1 = r0 + 8;
#pragma unroll
    for (int nt = 0; nt < 8; nt++) {
        const int col = nt * 8 + 2 * t;
        *(__half2*)&Og[base + (size_t)r0 * HID + col] =
            __floats2half2_rn(oacc[nt][0] * inv0, oacc[nt][1] * inv0);
        *(__half2*)&Og[base + (size_t)r1 * HID + col] =
            __floats2half2_rn(oacc[nt][2] * inv1, oacc[nt][3] * inv1);
    }
}

// ---------------------------------------------------------------------------
// Residual add + LayerNorm (optionally also emits a half copy)
// ---------------------------------------------------------------------------
template<int HALF_OUT>
__global__ void __launch_bounds__(256) add_ln_kernel(
    const float* __restrict__ X, const float* __restrict__ Y,
    const float* __restrict__ g, const float* __restrict__ be,
    float* __restrict__ out, __half* __restrict__ outh)
{
    const int row = blockIdx.x;
    const int tid = threadIdx.x;
    const size_t base = (size_t)row * HID;

    float v[4];
    float s = 0.0f, s2 = 0.0f;
#pragma unroll
    for (int k = 0; k < 4; k++) {
        int c = tid + k * 256;
        float tt = X[base + c] + Y[base + c];
        v[k] = tt;
        s += tt;
        s2 += tt * tt;
    }
#pragma unroll
    for (int off = 16; off > 0; off >>= 1) {
        s  += __shfl_xor_sync(0xffffffffu, s,  off);
        s2 += __shfl_xor_sync(0xffffffffu, s2, off);
    }
    __shared__ float red[16];
    const int warp = tid >> 5, lane = tid & 31;
    if (lane == 0) { red[warp] = s; red[warp + 8] = s2; }
    __syncthreads();
    if (tid < 32) {
        float a = (lane < 8) ? red[lane]     : 0.0f;
        float c2 = (lane < 8) ? red[lane + 8] : 0.0f;
#pragma unroll
        for (int off = 4; off > 0; off >>= 1) {
            a  += __shfl_xor_sync(0xffffffffu, a,  off);
            c2 += __shfl_xor_sync(0xffffffffu, c2, off);
        }
        if (lane == 0) { red[0] = a; red[1] = c2; }
    }
    __syncthreads();
    const float mu  = red[0] * (1.0f / HID);
    const float var = red[1] * (1.0f / HID) - mu * mu;
    const float inv = rsqrtf(var + 1e-5f);
#pragma unroll
    for (int k = 0; k < 4; k++) {
        int c = tid + k * 256;
        float r = (v[k] - mu) * inv * g[c] + be[c];
        out[base + c] = r;
        if (HALF_OUT) outh[base + c] = __float2half_rn(r);
    }
}

// ---------------------------------------------------------------------------
// kernel_launch
// ---------------------------------------------------------------------------
extern "C" void kernel_launch(void* const* d_in, const int* in_sizes, int n_in,
                              void* d_out, int out_size)
{
    const float* x  = (const float*)d_in[0];
    const float* Wq = (const float*)d_in[1];
    const float* bq = (const float*)d_in[2];
    const float* Wk = (const float*)d_in[3];
    const float* bk = (const float*)d_in[4];
    const float* Wv = (const float*)d_in[5];
    const float* bv = (const float*)d_in[6];
    const float* Wo = (const float*)d_in[7];
    const float* bo = (const float*)d_in[8];
    const float* W1 = (const float*)d_in[9];
    const float* b1 = (const float*)d_in[10];
    const float* W2 = (const float*)d_in[11];
    const float* b2 = (const float*)d_in[12];
    const float* g1 = (const float*)d_in[13];
    const float* be1= (const float*)d_in[14];
    const float* g2 = (const float*)d_in[15];
    const float* be2= (const float*)d_in[16];
    float* out = (float*)d_out;

    __half *xh, *qh, *kh, *vh, *ctxh, *x1h, *hh;
    float *ao, *x1, *ff;
    __half *wqt, *wkt, *wvt, *wot, *w1t, *w2t;
    cudaGetSymbolAddress((void**)&xh,   g_xh);
    cudaGetSymbolAddress((void**)&qh,   g_qh);
    cudaGetSymbolAddress((void**)&kh,   g_kh);
    cudaGetSymbolAddress((void**)&vh,   g_vh);
    cudaGetSymbolAddress((void**)&ctxh, g_ctxh);
    cudaGetSymbolAddress((void**)&ao,   g_ao);
    cudaGetSymbolAddress((void**)&x1,   g_x1);
    cudaGetSymbolAddress((void**)&x1h,  g_x1h);
    cudaGetSymbolAddress((void**)&hh,   g_hh);
    cudaGetSymbolAddress((void**)&ff,   g_ff);
    cudaGetSymbolAddress((void**)&wqt,  g_wqt);
    cudaGetSymbolAddress((void**)&wkt,  g_wkt);
    cudaGetSymbolAddress((void**)&wvt,  g_wvt);
    cudaGetSymbolAddress((void**)&wot,  g_wot);
    cudaGetSymbolAddress((void**)&w1t,  g_w1t);
    cudaGetSymbolAddress((void**)&w2t,  g_w2t);

    cudaFuncSetAttribute(attn_mma_h_kernel,
                         cudaFuncAttributeMaxDynamicSharedMemorySize, ATT_SMEM);
    cudaFuncSetAttribute(mma_gemm_h<0>,
                         cudaFuncAttributeMaxDynamicSharedMemorySize, GEMM_SMEM);
    cudaFuncSetAttribute(mma_gemm_h<1>,
                         cudaFuncAttributeMaxDynamicSharedMemorySize, GEMM_SMEM);
    cudaFuncSetAttribute(mma_gemm_h<2>,
                         cudaFuncAttributeMaxDynamicSharedMemorySize, GEMM_SMEM);

    const dim3 blk256(256);

    // weight prep + input conversion
    transpose_h_kernel<<<dim3(HID/32, HID/32), blk256>>>(Wq, wqt, HID, HID);
    transpose_h_kernel<<<dim3(HID/32, HID/32), blk256>>>(Wk, wkt, HID, HID);
    transpose_h_kernel<<<dim3(HID/32, HID/32), blk256>>>(Wv, wvt, HID, HID);
    transpose_h_kernel<<<dim3(HID/32, HID/32), blk256>>>(Wo, wot, HID, HID);
    transpose_h_kernel<<<dim3(DFF/32, HID/32), blk256>>>(W1, w1t, HID, DFF);
    transpose_h_kernel<<<dim3(HID/32, DFF/32), blk256>>>(W2, w2t, DFF, HID);
    convert_h_kernel<<<MTOT * HID / (256 * 8), blk256>>>(x, xh);

    const dim3 gProj(HID / 128, MTOT / 128);   // (8, 64)
    const dim3 gFF1 (DFF / 128, MTOT / 128);   // (32, 64)

    // QKV projections (half outputs)
    mma_gemm_h<1><<<gProj, blk256, GEMM_SMEM>>>(xh, wqt, bq, qh, MTOT, HID, HID);
    mma_gemm_h<1><<<gProj, blk256, GEMM_SMEM>>>(xh, wkt, bk, kh, MTOT, HID, HID);
    mma_gemm_h<1><<<gProj, blk256, GEMM_SMEM>>>(xh, wvt, bv, vh, MTOT, HID, HID);

    // Attention (fp16 tensor cores)
    attn_mma_h_kernel<<<dim3(SEQ / BQ, NHEAD, BATCH), blk256, ATT_SMEM>>>(qh, kh, vh, ctxh);

    // Output projection (fp32 out) + residual/LN1 (emit half copy for FF1)
    mma_gemm_h<0><<<gProj, blk256, GEMM_SMEM>>>(ctxh, wot, bo, ao, MTOT, HID, HID);
    add_ln_kernel<1><<<MTOT, blk256>>>(x, ao, g1, be1, x1, x1h);

    // FFN
    mma_gemm_h<2><<<gFF1, blk256, GEMM_SMEM>>>(x1h, w1t, b1, hh, MTOT, DFF, HID);
    mma_gemm_h<0><<<gProj, blk256, GEMM_SMEM>>>(hh, w2t, b2, ff, MTOT, HID, DFF);

    // Residual/LN2 -> output
    add_ln_kernel<0><<<MTOT, blk256>>>(x1, ff, g2, be2, out, nullptr);
}

// round 7
// speedup vs baseline: 6.5125x; 1.1586x over previous
#include <cuda_runtime.h>
#include <cuda_fp16.h>
#include <math.h>
#include <cstdint>

// Problem constants
#define BATCH 4
#define SEQ   2048
#define HID   1024
#define NHEAD 16
#define DK    64
#define DFF   4096
#define MTOT  (BATCH * SEQ)          // 8192 rows

// ---------------------------------------------------------------------------
// Scratch
// ---------------------------------------------------------------------------
__device__ __half g_xh [MTOT * HID];
__device__ __half g_qh [MTOT * HID];
__device__ __half g_kh [MTOT * HID];
__device__ __half g_vh [MTOT * HID];
__device__ __half g_ctxh[MTOT * HID];
__device__ float  g_ao [MTOT * HID];
__device__ float  g_x1 [MTOT * HID];
__device__ __half g_x1h[MTOT * HID];
__device__ __half g_hh [MTOT * DFF];
__device__ float  g_ff [MTOT * HID];
// transposed fp16 weights: Wt[n][k]
__device__ __half g_wqt[HID * HID];
__device__ __half g_wkt[HID * HID];
__device__ __half g_wvt[HID * HID];
__device__ __half g_wot[HID * HID];
__device__ __half g_w1t[HID * DFF];
__device__ __half g_w2t[DFF * HID];

// ---------------------------------------------------------------------------
// helpers
// ---------------------------------------------------------------------------
__device__ __forceinline__ uint32_t smem_u32(const void* p) {
    uint32_t a;
    asm("{ .reg .u64 t; cvta.to.shared.u64 t, %1; cvt.u32.u64 %0, t; }" : "=r"(a) : "l"(p));
    return a;
}
__device__ __forceinline__ void cp_async16(uint32_t saddr, const void* gaddr) {
    asm volatile("cp.async.cg.shared.global [%0], [%1], 16;" :: "r"(saddr), "l"(gaddr) : "memory");
}
#define CP_COMMIT() asm volatile("cp.async.commit_group;" ::: "memory")
#define CP_WAIT(n)  asm volatile("cp.async.wait_group %0;" :: "n"(n) : "memory")

__device__ __forceinline__ void mma_f16(
    float& d0, float& d1, float& d2, float& d3,
    uint32_t a0, uint32_t a1, uint32_t a2, uint32_t a3,
    uint32_t b0, uint32_t b1)
{
    asm volatile(
        "mma.sync.aligned.m16n8k16.row.col.f32.f16.f16.f32 "
        "{%0,%1,%2,%3}, {%4,%5,%6,%7}, {%8,%9}, {%0,%1,%2,%3};"
        : "+f"(d0), "+f"(d1), "+f"(d2), "+f"(d3)
        : "r"(a0), "r"(a1), "r"(a2), "r"(a3), "r"(b0), "r"(b1));
}
__device__ __forceinline__ void ldmatrix_x4(
    uint32_t& r0, uint32_t& r1, uint32_t& r2, uint32_t& r3, uint32_t addr)
{
    asm volatile("ldmatrix.sync.aligned.m8n8.x4.shared.b16 {%0,%1,%2,%3}, [%4];"
                 : "=r"(r0), "=r"(r1), "=r"(r2), "=r"(r3) : "r"(addr));
}
__device__ __forceinline__ void ldmatrix_x4_trans(
    uint32_t& r0, uint32_t& r1, uint32_t& r2, uint32_t& r3, uint32_t addr)
{
    asm volatile("ldmatrix.sync.aligned.m8n8.x4.trans.shared.b16 {%0,%1,%2,%3}, [%4];"
                 : "=r"(r0), "=r"(r1), "=r"(r2), "=r"(r3) : "r"(addr));
}

__device__ __forceinline__ float gelu_fn(float x) {
    const float c = 0.7978845608028654f;
    float x3 = x * x * x;
    return 0.5f * x * (1.0f + tanhf(c * (x + 0.044715f * x3)));
}

// ---------------------------------------------------------------------------
// Weight transpose to fp16:  Wt[n][k] = half(W[k][n])
// ---------------------------------------------------------------------------
__global__ void __launch_bounds__(256) transpose_h_kernel(
    const float* __restrict__ W, __half* __restrict__ Wt, int K, int N)
{
    __shared__ float t[32][33];
    const int bx = blockIdx.x * 32;
    const int by = blockIdx.y * 32;
    const int tx = threadIdx.x & 31;
    const int ty = threadIdx.x >> 5;
#pragma unroll
    for (int q = 0; q < 4; q++)
        t[ty + q * 8][tx] = W[(size_t)(by + ty + q * 8) * N + bx + tx];
    __syncthreads();
#pragma unroll
    for (int q = 0; q < 4; q++)
        Wt[(size_t)(bx + ty + q * 8) * K + by + tx] = __float2half_rn(t[tx][ty + q * 8]);
}

// x (fp32) -> xh (fp16)
__global__ void __launch_bounds__(256) convert_h_kernel(
    const float* __restrict__ X, __half* __restrict__ Xh)
{
    const int i = (blockIdx.x * 256 + threadIdx.x) * 8;
    float4 a = *(const float4*)&X[i];
    float4 b = *(const float4*)&X[i + 4];
    __half2 h[4];
    h[0] = __floats2half2_rn(a.x, a.y);
    h[1] = __floats2half2_rn(a.z, a.w);
    h[2] = __floats2half2_rn(b.x, b.y);
    h[3] = __floats2half2_rn(b.z, b.w);
    *(uint4*)&Xh[i] = *(uint4*)h;
}

// ---------------------------------------------------------------------------
// fp16 mma.sync GEMM:  C[M,N] = A[M,K] @ W[K,N] + bias   (W given as Wt[n][k])
// CTA tile 128x256, BK=64 halves, 3-stage cp.async pipeline, 8 warps (2m x 4n),
// warp tile 64x64 = 4x8 m16n8k16 mma tiles. Fragments via ldmatrix.x4.
// EPI: 0 = fp32 out, 1 = half out, 2 = half out + GELU
// ---------------------------------------------------------------------------
#define HPAD 72
#define BN 256
#define STAGE_H ((128 + BN) * HPAD)                    // halves per stage
#define GEMM_SMEM (3 * STAGE_H * 2)                    // 165888 bytes

__device__ __forceinline__ void fill_stage(
    __half* As, __half* Bs, const __half* A, const __half* Bt,
    int bm, int bn, int k0, int K, int tid)
{
#pragma unroll
    for (int q = 0; q < 4; q++) {
        int idx = q * 256 + tid;
        int row = idx >> 3, c = idx & 7;
        cp_async16(smem_u32(&As[row * HPAD + c * 8]),
                   &A[(size_t)(bm + row) * K + k0 + c * 8]);
    }
#pragma unroll
    for (int q = 0; q < 8; q++) {
        int idx = q * 256 + tid;
        int row = idx >> 3, c = idx & 7;
        cp_async16(smem_u32(&Bs[row * HPAD + c * 8]),
                   &Bt[(size_t)(bn + row) * K + k0 + c * 8]);
    }
}

template<int EPI>
__global__ void __launch_bounds__(256) mma_gemm_h(
    const __half* __restrict__ A, const __half* __restrict__ Bt,
    const float* __restrict__ bias, void* __restrict__ Cout,
    int M, int N, int K)
{
    extern __shared__ __half shh[];
    const int tid  = threadIdx.x;
    const int wid  = tid >> 5;
    const int lane = tid & 31;
    const int g    = lane >> 2;
    const int t    = lane & 3;
    const int bm   = blockIdx.y * 128;
    const int bn   = blockIdx.x * BN;
    const int moff = (wid >> 2) * 64;
    const int noff = (wid & 3) * 64;

    // ldmatrix lane mappings
    const int a_r = lane & 15;                              // A: row within 16
    const int a_c = (lane >> 4) * 8;                        // A: k-half select
    const int b_r = (lane & 7) + ((lane >> 4) << 3);        // B: row within 16
    const int b_c = ((lane >> 3) & 1) * 8;                  // B: k-half select

    const int iters = K >> 6;

    float acc[4][8][4];
#pragma unroll
    for (int a = 0; a < 4; a++)
#pragma unroll
        for (int b = 0; b < 8; b++)
#pragma unroll
            for (int c = 0; c < 4; c++) acc[a][b][c] = 0.0f;

    fill_stage(shh, shh + 128 * HPAD, A, Bt, bm, bn, 0, K, tid);
    CP_COMMIT();
    fill_stage(shh + STAGE_H, shh + STAGE_H + 128 * HPAD, A, Bt, bm, bn, 64, K, tid);
    CP_COMMIT();

    for (int i = 0; i < iters; i++) {
        if (i + 1 < iters) { CP_WAIT(1); } else { CP_WAIT(0); }
        __syncthreads();

        if (i + 2 < iters) {
            __half* st = shh + ((i + 2) % 3) * STAGE_H;
            fill_stage(st, st + 128 * HPAD, A, Bt, bm, bn, (i + 2) * 64, K, tid);
            CP_COMMIT();
        }

        const __half* As = shh + (i % 3) * STAGE_H;
        const __half* Bs = As + 128 * HPAD;
#pragma unroll
        for (int ks = 0; ks < 4; ks++) {
            uint32_t af[4][4], bf[8][2];
#pragma unroll
            for (int mt = 0; mt < 4; mt++) {
                uint32_t addr = smem_u32(
                    &As[(moff + mt * 16 + a_r) * HPAD + ks * 16 + a_c]);
                ldmatrix_x4(af[mt][0], af[mt][1], af[mt][2], af[mt][3], addr);
            }
#pragma unroll
            for (int np = 0; np < 4; np++) {
                uint32_t addr = smem_u32(
                    &Bs[(noff + np * 16 + b_r) * HPAD + ks * 16 + b_c]);
                ldmatrix_x4(bf[np * 2][0], bf[np * 2][1],
                            bf[np * 2 + 1][0], bf[np * 2 + 1][1], addr);
            }
#pragma unroll
            for (int mt = 0; mt < 4; mt++)
#pragma unroll
                for (int nt = 0; nt < 8; nt++)
                    mma_f16(acc[mt][nt][0], acc[mt][nt][1], acc[mt][nt][2], acc[mt][nt][3],
                            af[mt][0], af[mt][1], af[mt][2], af[mt][3],
                            bf[nt][0], bf[nt][1]);
        }
    }

    // epilogue
#pragma unroll
    for (int nt = 0; nt < 8; nt++) {
        const int col = bn + noff + nt * 8 + 2 * t;
        const float2 bv = *(const float2*)&bias[col];
#pragma unroll
        for (int mt = 0; mt < 4; mt++) {
            const int r0 = bm + moff + mt * 16 + g;
            float c0 = acc[mt][nt][0] + bv.x;
            float c1 = acc[mt][nt][1] + bv.y;
            float c2 = acc[mt][nt][2] + bv.x;
            float c3 = acc[mt][nt][3] + bv.y;
            if (EPI == 2) {
                c0 = gelu_fn(c0); c1 = gelu_fn(c1);
                c2 = gelu_fn(c2); c3 = gelu_fn(c3);
            }
            if (EPI == 0) {
                float* C = (float*)Cout;
                *(float2*)&C[(size_t)r0 * N + col]       = make_float2(c0, c1);
                *(float2*)&C[(size_t)(r0 + 8) * N + col] = make_float2(c2, c3);
            } else {
                __half* C = (__half*)Cout;
                *(__half2*)&C[(size_t)r0 * N + col]       = __floats2half2_rn(c0, c1);
                *(__half2*)&C[(size_t)(r0 + 8) * N + col] = __floats2half2_rn(c2, c3);
            }
        }
    }
}

// ---------------------------------------------------------------------------
// Flash attention, fp16 mma (m16n8k16).
// CTA: 128 queries x (head, batch). 8 warps x 16 query rows. Key blocks of 64.
// Q lives in fragments; its smem tile is recycled as the P tile.
// K fragments via ldmatrix.x4, V via ldmatrix.x4.trans.
// ---------------------------------------------------------------------------
#define BQ   128
#define BKV  64
#define NKB  (SEQ / BKV)
#define ATT_SMEM ((4 * BKV * HPAD + BQ * HPAD) * 2)    // 55296 B

__global__ void __launch_bounds__(256) attn_mma_h_kernel(
    const __half* __restrict__ Qg, const __half* __restrict__ Kg,
    const __half* __restrict__ Vg, __half* __restrict__ Og)
{
    extern __shared__ __half sha[];
    __half* Ks = sha;                        // [2][BKV][HPAD]
    __half* Vs = sha + 2 * BKV * HPAD;       // [2][BKV][HPAD]
    __half* Ps = sha + 4 * BKV * HPAD;       // [BQ][HPAD] (Q staging, then P)

    const int tid  = threadIdx.x;
    const int wid  = tid >> 5;
    const int lane = tid & 31;
    const int g    = lane >> 2;
    const int t    = lane & 3;
    const int qt   = blockIdx.x;
    const int head = blockIdx.y;
    const int b    = blockIdx.z;

    const size_t base = ((size_t)b * SEQ) * HID + (size_t)head * DK;
    const int q0   = qt * BQ;
    const int moff = wid * 16;

    const int b_r = (lane & 7) + ((lane >> 4) << 3);
    const int b_c = ((lane >> 3) & 1) * 8;

    // prologue: Q (into Ps) + K0/V0
#pragma unroll
    for (int q = 0; q < 4; q++) {
        int idx = q * 256 + tid;
        int r = idx >> 3, c = idx & 7;
        cp_async16(smem_u32(&Ps[r * HPAD + c * 8]),
                   &Qg[base + (size_t)(q0 + r) * HID + c * 8]);
    }
#pragma unroll
    for (int q = 0; q < 2; q++) {
        int idx = q * 256 + tid;
        int r = idx >> 3, c = idx & 7;
        cp_async16(smem_u32(&Ks[r * HPAD + c * 8]),
                   &Kg[base + (size_t)r * HID + c * 8]);
        cp_async16(smem_u32(&Vs[r * HPAD + c * 8]),
                   &Vg[base + (size_t)r * HID + c * 8]);
    }
    CP_COMMIT();

    const uint32_t vlane_off = (uint32_t)((lane & 15) * HPAD + (lane >> 4) * 8);

    uint32_t qf[4][4];
    float oacc[8][4];
#pragma unroll
    for (int nt = 0; nt < 8; nt++)
#pragma unroll
        for (int c = 0; c < 4; c++) oacc[nt][c] = 0.0f;
    float m0 = -1e30f, m1 = -1e30f, l0 = 0.0f, l1 = 0.0f;

    for (int i = 0; i < NKB; i++) {
        if (i + 1 < NKB) {
            const int kn = (i + 1) * BKV;
            __half* Kb = Ks + ((i + 1) & 1) * BKV * HPAD;
            __half* Vb = Vs + ((i + 1) & 1) * BKV * HPAD;
#pragma unroll
            for (int q = 0; q < 2; q++) {
                int idx = q * 256 + tid;
                int r = idx >> 3, c = idx & 7;
                cp_async16(smem_u32(&Kb[r * HPAD + c * 8]),
                           &Kg[base + (size_t)(kn + r) * HID + c * 8]);
                cp_async16(smem_u32(&Vb[r * HPAD + c * 8]),
                           &Vg[base + (size_t)(kn + r) * HID + c * 8]);
            }
            CP_COMMIT();
            CP_WAIT(1);
        } else {
            CP_WAIT(0);
        }
        __syncthreads();

        if (i == 0) {
#pragma unroll
            for (int ks = 0; ks < 4; ks++) {
                const int kc = ks * 16 + 2 * t;
                qf[ks][0] = *(const uint32_t*)&Ps[(moff + g) * HPAD + kc];
                qf[ks][1] = *(const uint32_t*)&Ps[(moff + 8 + g) * HPAD + kc];
                qf[ks][2] = *(const uint32_t*)&Ps[(moff + g) * HPAD + kc + 8];
                qf[ks][3] = *(const uint32_t*)&Ps[(moff + 8 + g) * HPAD + kc + 8];
            }
        }

        const __half* Kb = Ks + (i & 1) * BKV * HPAD;
        const __half* Vb = Vs + (i & 1) * BKV * HPAD;

        // ---- S = Q K^T ----  (K fragments via ldmatrix.x4)
        float sacc[8][4];
#pragma unroll
        for (int nt = 0; nt < 8; nt++)
#pragma unroll
            for (int c = 0; c < 4; c++) sacc[nt][c] = 0.0f;

#pragma unroll
        for (int ks = 0; ks < 4; ks++) {
            uint32_t bf[8][2];
#pragma unroll
            for (int np = 0; np < 4; np++) {
                uint32_t addr = smem_u32(
                    &Kb[(np * 16 + b_r) * HPAD + ks * 16 + b_c]);
                ldmatrix_x4(bf[np * 2][0], bf[np * 2][1],
                            bf[np * 2 + 1][0], bf[np * 2 + 1][1], addr);
            }
#pragma unroll
            for (int nt = 0; nt < 8; nt++)
                mma_f16(sacc[nt][0], sacc[nt][1], sacc[nt][2], sacc[nt][3],
                        qf[ks][0], qf[ks][1], qf[ks][2], qf[ks][3],
                        bf[nt][0], bf[nt][1]);
        }

        // ---- online softmax ----
        float rx0 = -1e30f, rx1 = -1e30f;
#pragma unroll
        for (int nt = 0; nt < 8; nt++) {
            sacc[nt][0] *= 0.125f; sacc[nt][1] *= 0.125f;
            sacc[nt][2] *= 0.125f; sacc[nt][3] *= 0.125f;
            rx0 = fmaxf(rx0, fmaxf(sacc[nt][0], sacc[nt][1]));
            rx1 = fmaxf(rx1, fmaxf(sacc[nt][2], sacc[nt][3]));
        }
        rx0 = fmaxf(rx0, __shfl_xor_sync(0xffffffffu, rx0, 1));
        rx0 = fmaxf(rx0, __shfl_xor_sync(0xffffffffu, rx0, 2));
        rx1 = fmaxf(rx1, __shfl_xor_sync(0xffffffffu, rx1, 1));
        rx1 = fmaxf(rx1, __shfl_xor_sync(0xffffffffu, rx1, 2));

        const float nm0 = fmaxf(m0, rx0);
        const float nm1 = fmaxf(m1, rx1);
        const float corr0 = __expf(m0 - nm0);
        const float corr1 = __expf(m1 - nm1);

        float rs0 = 0.0f, rs1 = 0.0f;
#pragma unroll
        for (int nt = 0; nt < 8; nt++) {
            sacc[nt][0] = __expf(sacc[nt][0] - nm0);
            sacc[nt][1] = __expf(sacc[nt][1] - nm0);
            sacc[nt][2] = __expf(sacc[nt][2] - nm1);
            sacc[nt][3] = __expf(sacc[nt][3] - nm1);
            rs0 += sacc[nt][0] + sacc[nt][1];
            rs1 += sacc[nt][2] + sacc[nt][3];
        }
        rs0 += __shfl_xor_sync(0xffffffffu, rs0, 1);
        rs0 += __shfl_xor_sync(0xffffffffu, rs0, 2);
        rs1 += __shfl_xor_sync(0xffffffffu, rs1, 1);
        rs1 += __shfl_xor_sync(0xffffffffu, rs1, 2);

        l0 = l0 * corr0 + rs0;  m0 = nm0;
        l1 = l1 * corr1 + rs1;  m1 = nm1;

#pragma unroll
        for (int nt = 0; nt < 8; nt++) {
            oacc[nt][0] *= corr0; oacc[nt][1] *= corr0;
            oacc[nt][2] *= corr1; oacc[nt][3] *= corr1;
        }

        // ---- P -> smem (half2), warp-private rows ----
#pragma unroll
        for (int nt = 0; nt < 8; nt++) {
            *(__half2*)&Ps[(moff + g) * HPAD + nt * 8 + 2 * t] =
                __floats2half2_rn(sacc[nt][0], sacc[nt][1]);
            *(__half2*)&Ps[(moff + 8 + g) * HPAD + nt * 8 + 2 * t] =
                __floats2half2_rn(sacc[nt][2], sacc[nt][3]);
        }
        __syncwarp();

        // ---- O += P @ V ----  (V fragments via ldmatrix.x4.trans)
        const uint32_t vbase = smem_u32(Vb) + vlane_off * 2;
#pragma unroll
        for (int ks = 0; ks < 4; ks++) {
            const int kc = ks * 16 + 2 * t;
            const uint32_t a0 = *(const uint32_t*)&Ps[(moff + g) * HPAD + kc];
            const uint32_t a1 = *(const uint32_t*)&Ps[(moff + 8 + g) * HPAD + kc];
            const uint32_t a2 = *(const uint32_t*)&Ps[(moff + g) * HPAD + kc + 8];
            const uint32_t a3 = *(const uint32_t*)&Ps[(moff + 8 + g) * HPAD + kc + 8];
            const uint32_t vrow = vbase + (uint32_t)(ks * 16 * HPAD * 2);
#pragma unroll
            for (int n16 = 0; n16 < 4; n16++) {
                uint32_t r0, r1, r2, r3;
                ldmatrix_x4_trans(r0, r1, r2, r3, vrow + (uint32_t)(n16 * 32));
                mma_f16(oacc[n16 * 2][0], oacc[n16 * 2][1], oacc[n16 * 2][2], oacc[n16 * 2][3],
                        a0, a1, a2, a3, r0, r1);
                mma_f16(oacc[n16 * 2 + 1][0], oacc[n16 * 2 + 1][1],
                        oacc[n16 * 2 + 1][2], oacc[n16 * 2 + 1][3],
                        a0, a1, a2, a3, r2, r3);
            }
        }
        __syncthreads();
    }

    // epilogue: normalize, write ctx (half)
    const float inv0 = 1.0f / l0;
    const float inv1 = 1.0f / l1;
    const int r0 = q0 + moff + g;
    const int r1 = r0 + 8;
#pragma unroll
    for (int nt = 0; nt < 8; nt++) {
        const int col = nt * 8 + 2 * t;
        *(__half2*)&Og[base + (size_t)r0 * HID + col] =
            __floats2half2_rn(oacc[nt][0] * inv0, oacc[nt][1] * inv0);
        *(__half2*)&Og[base + (size_t)r1 * HID + col] =
            __floats2half2_rn(oacc[nt][2] * inv1, oacc[nt][3] * inv1);
    }
}

// ---------------------------------------------------------------------------
// Residual add + LayerNorm (optionally also emits a half copy)
// ---------------------------------------------------------------------------
template<int HALF_OUT>
__global__ void __launch_bounds__(256) add_ln_kernel(
    const float* __restrict__ X, const float* __restrict__ Y,
    const float* __restrict__ g, const float* __restrict__ be,
    float* __restrict__ out, __half* __restrict__ outh)
{
    const int row = blockIdx.x;
    const int tid = threadIdx.x;
    const size_t base = (size_t)row * HID;

    float v[4];
    float s = 0.0f, s2 = 0.0f;
#pragma unroll
    for (int k = 0; k < 4; k++) {
        int c = tid + k * 256;
        float tt = X[base + c] + Y[base + c];
        v[k] = tt;
        s += tt;
        s2 += tt * tt;
    }
#pragma unroll
    for (int off = 16; off > 0; off >>= 1) {
        s  += __shfl_xor_sync(0xffffffffu, s,  off);
        s2 += __shfl_xor_sync(0xffffffffu, s2, off);
    }
    __shared__ float red[16];
    const int warp = tid >> 5, lane = tid & 31;
    if (lane == 0) { red[warp] = s; red[warp + 8] = s2; }
    __syncthreads();
    if (tid < 32) {
        float a = (lane < 8) ? red[lane]     : 0.0f;
        float c2 = (lane < 8) ? red[lane + 8] : 0.0f;
#pragma unroll
        for (int off = 4; off > 0; off >>= 1) {
            a  += __shfl_xor_sync(0xffffffffu, a,  off);
            c2 += __shfl_xor_sync(0xffffffffu, c2, off);
        }
        if (lane == 0) { red[0] = a; red[1] = c2; }
    }
    __syncthreads();
    const float mu  = red[0] * (1.0f / HID);
    const float var = red[1] * (1.0f / HID) - mu * mu;
    const float inv = rsqrtf(var + 1e-5f);
#pragma unroll
    for (int k = 0; k < 4; k++) {
        int c = tid + k * 256;
        float r = (v[k] - mu) * inv * g[c] + be[c];
        out[base + c] = r;
        if (HALF_OUT) outh[base + c] = __float2half_rn(r);
    }
}

// ---------------------------------------------------------------------------
// kernel_launch
// ---------------------------------------------------------------------------
extern "C" void kernel_launch(void* const* d_in, const int* in_sizes, int n_in,
                              void* d_out, int out_size)
{
    const float* x  = (const float*)d_in[0];
    const float* Wq = (const float*)d_in[1];
    const float* bq = (const float*)d_in[2];
    const float* Wk = (const float*)d_in[3];
    const float* bk = (const float*)d_in[4];
    const float* Wv = (const float*)d_in[5];
    const float* bv = (const float*)d_in[6];
    const float* Wo = (const float*)d_in[7];
    const float* bo = (const float*)d_in[8];
    const float* W1 = (const float*)d_in[9];
    const float* b1 = (const float*)d_in[10];
    const float* W2 = (const float*)d_in[11];
    const float* b2 = (const float*)d_in[12];
    const float* g1 = (const float*)d_in[13];
    const float* be1= (const float*)d_in[14];
    const float* g2 = (const float*)d_in[15];
    const float* be2= (const float*)d_in[16];
    float* out = (float*)d_out;

    __half *xh, *qh, *kh, *vh, *ctxh, *x1h, *hh;
    float *ao, *x1, *ff;
    __half *wqt, *wkt, *wvt, *wot, *w1t, *w2t;
    cudaGetSymbolAddress((void**)&xh,   g_xh);
    cudaGetSymbolAddress((void**)&qh,   g_qh);
    cudaGetSymbolAddress((void**)&kh,   g_kh);
    cudaGetSymbolAddress((void**)&vh,   g_vh);
    cudaGetSymbolAddress((void**)&ctxh, g_ctxh);
    cudaGetSymbolAddress((void**)&ao,   g_ao);
    cudaGetSymbolAddress((void**)&x1,   g_x1);
    cudaGetSymbolAddress((void**)&x1h,  g_x1h);
    cudaGetSymbolAddress((void**)&hh,   g_hh);
    cudaGetSymbolAddress((void**)&ff,   g_ff);
    cudaGetSymbolAddress((void**)&wqt,  g_wqt);
    cudaGetSymbolAddress((void**)&wkt,  g_wkt);
    cudaGetSymbolAddress((void**)&wvt,  g_wvt);
    cudaGetSymbolAddress((void**)&wot,  g_wot);
    cudaGetSymbolAddress((void**)&w1t,  g_w1t);
    cudaGetSymbolAddress((void**)&w2t,  g_w2t);

    cudaFuncSetAttribute(attn_mma_h_kernel,
                         cudaFuncAttributeMaxDynamicSharedMemorySize, ATT_SMEM);
    cudaFuncSetAttribute(mma_gemm_h<0>,
                         cudaFuncAttributeMaxDynamicSharedMemorySize, GEMM_SMEM);
    cudaFuncSetAttribute(mma_gemm_h<1>,
                         cudaFuncAttributeMaxDynamicSharedMemorySize, GEMM_SMEM);
    cudaFuncSetAttribute(mma_gemm_h<2>,
                         cudaFuncAttributeMaxDynamicSharedMemorySize, GEMM_SMEM);

    const dim3 blk256(256);

    // weight prep + input conversion
    transpose_h_kernel<<<dim3(HID/32, HID/32), blk256>>>(Wq, wqt, HID, HID);
    transpose_h_kernel<<<dim3(HID/32, HID/32), blk256>>>(Wk, wkt, HID, HID);
    transpose_h_kernel<<<dim3(HID/32, HID/32), blk256>>>(Wv, wvt, HID, HID);
    transpose_h_kernel<<<dim3(HID/32, HID/32), blk256>>>(Wo, wot, HID, HID);
    transpose_h_kernel<<<dim3(DFF/32, HID/32), blk256>>>(W1, w1t, HID, DFF);
    transpose_h_kernel<<<dim3(HID/32, DFF/32), blk256>>>(W2, w2t, DFF, HID);
    convert_h_kernel<<<MTOT * HID / (256 * 8), blk256>>>(x, xh);

    const dim3 gProj(HID / BN, MTOT / 128);   // (4, 64)
    const dim3 gFF1 (DFF / BN, MTOT / 128);   // (16, 64)

    // QKV projections (half outputs)
    mma_gemm_h<1><<<gProj, blk256, GEMM_SMEM>>>(xh, wqt, bq, qh, MTOT, HID, HID);
    mma_gemm_h<1><<<gProj, blk256, GEMM_SMEM>>>(xh, wkt, bk, kh, MTOT, HID, HID);
    mma_gemm_h<1><<<gProj, blk256, GEMM_SMEM>>>(xh, wvt, bv, vh, MTOT, HID, HID);

    // Attention (fp16 tensor cores)
    attn_mma_h_kernel<<<dim3(SEQ / BQ, NHEAD, BATCH), blk256, ATT_SMEM>>>(qh, kh, vh, ctxh);

    // Output projection (fp32 out) + residual/LN1 (emit half copy for FF1)
    mma_gemm_h<0><<<gProj, blk256, GEMM_SMEM>>>(ctxh, wot, bo, ao, MTOT, HID, HID);
    add_ln_kernel<1><<<MTOT, blk256>>>(x, ao, g1, be1, x1, x1h);

    // FFN
    mma_gemm_h<2><<<gFF1, blk256, GEMM_SMEM>>>(x1h, w1t, b1, hh, MTOT, DFF, HID);
    mma_gemm_h<0><<<gProj, blk256, GEMM_SMEM>>>(hh, w2t, b2, ff, MTOT, HID, DFF);

    // Residual/LN2 -> output
    add_ln_kernel<0><<<MTOT, blk256>>>(x1, ff, g2, be2, out, nullptr);
}

// round 8
// speedup vs baseline: 6.5210x; 1.0013x over previous
#include <cuda_runtime.h>
#include <cuda_fp16.h>
#include <math.h>
#include <cstdint>

// Problem constants
#define BATCH 4
#define SEQ   2048
#define HID   1024
#define NHEAD 16
#define DK    64
#define DFF   4096
#define MTOT  (BATCH * SEQ)          // 8192 rows
#define NQKV  (3 * HID)              // 3072

// ---------------------------------------------------------------------------
// Scratch
// ---------------------------------------------------------------------------
__device__ __half g_xh  [MTOT * HID];
__device__ __half g_qkvh[MTOT * NQKV];   // fused QKV output
__device__ __half g_ctxh[MTOT * HID];
__device__ float  g_ao  [MTOT * HID];
__device__ float  g_x1  [MTOT * HID];
__device__ __half g_x1h [MTOT * HID];
__device__ __half g_hh  [MTOT * DFF];
__device__ float  g_ff  [MTOT * HID];
// transposed fp16 weights
__device__ __half g_wqkvt[NQKV * HID];   // rows: [Wq^T | Wk^T | Wv^T]
__device__ __half g_wot [HID * HID];
__device__ __half g_w1t [HID * DFF];
__device__ __half g_w2t [DFF * HID];
__device__ float  g_bqkv[NQKV];

// ---------------------------------------------------------------------------
// helpers
// ---------------------------------------------------------------------------
__device__ __forceinline__ uint32_t smem_u32(const void* p) {
    uint32_t a;
    asm("{ .reg .u64 t; cvta.to.shared.u64 t, %1; cvt.u32.u64 %0, t; }" : "=r"(a) : "l"(p));
    return a;
}
__device__ __forceinline__ void cp_async16(uint32_t saddr, const void* gaddr) {
    asm volatile("cp.async.cg.shared.global [%0], [%1], 16;" :: "r"(saddr), "l"(gaddr) : "memory");
}
#define CP_COMMIT() asm volatile("cp.async.commit_group;" ::: "memory")
#define CP_WAIT(n)  asm volatile("cp.async.wait_group %0;" :: "n"(n) : "memory")

__device__ __forceinline__ void mma_f16(
    float& d0, float& d1, float& d2, float& d3,
    uint32_t a0, uint32_t a1, uint32_t a2, uint32_t a3,
    uint32_t b0, uint32_t b1)
{
    asm volatile(
        "mma.sync.aligned.m16n8k16.row.col.f32.f16.f16.f32 "
        "{%0,%1,%2,%3}, {%4,%5,%6,%7}, {%8,%9}, {%0,%1,%2,%3};"
        : "+f"(d0), "+f"(d1), "+f"(d2), "+f"(d3)
        : "r"(a0), "r"(a1), "r"(a2), "r"(a3), "r"(b0), "r"(b1));
}
__device__ __forceinline__ void ldmatrix_x4(
    uint32_t& r0, uint32_t& r1, uint32_t& r2, uint32_t& r3, uint32_t addr)
{
    asm volatile("ldmatrix.sync.aligned.m8n8.x4.shared.b16 {%0,%1,%2,%3}, [%4];"
                 : "=r"(r0), "=r"(r1), "=r"(r2), "=r"(r3) : "r"(addr));
}
__device__ __forceinline__ void ldmatrix_x4_trans(
    uint32_t& r0, uint32_t& r1, uint32_t& r2, uint32_t& r3, uint32_t addr)
{
    asm volatile("ldmatrix.sync.aligned.m8n8.x4.trans.shared.b16 {%0,%1,%2,%3}, [%4];"
                 : "=r"(r0), "=r"(r1), "=r"(r2), "=r"(r3) : "r"(addr));
}

__device__ __forceinline__ float gelu_fn(float x) {
    const float c = 0.7978845608028654f;
    float x3 = x * x * x;
    return 0.5f * x * (1.0f + tanhf(c * (x + 0.044715f * x3)));
}

// ---------------------------------------------------------------------------
// Weight transpose to fp16:  Wt[n][k] = half(W[k][n])
// ---------------------------------------------------------------------------
__global__ void __launch_bounds__(256) transpose_h_kernel(
    const float* __restrict__ W, __half* __restrict__ Wt, int K, int N)
{
    __shared__ float t[32][33];
    const int bx = blockIdx.x * 32;
    const int by = blockIdx.y * 32;
    const int tx = threadIdx.x & 31;
    const int ty = threadIdx.x >> 5;
#pragma unroll
    for (int q = 0; q < 4; q++)
        t[ty + q * 8][tx] = W[(size_t)(by + ty + q * 8) * N + bx + tx];
    __syncthreads();
#pragma unroll
    for (int q = 0; q < 4; q++)
        Wt[(size_t)(bx + ty + q * 8) * K + by + tx] = __float2half_rn(t[tx][ty + q * 8]);
}

// x (fp32) -> xh (fp16)
__global__ void __launch_bounds__(256) convert_h_kernel(
    const float* __restrict__ X, __half* __restrict__ Xh)
{
    const int i = (blockIdx.x * 256 + threadIdx.x) * 8;
    float4 a = *(const float4*)&X[i];
    float4 b = *(const float4*)&X[i + 4];
    __half2 h[4];
    h[0] = __floats2half2_rn(a.x, a.y);
    h[1] = __floats2half2_rn(a.z, a.w);
    h[2] = __floats2half2_rn(b.x, b.y);
    h[3] = __floats2half2_rn(b.z, b.w);
    *(uint4*)&Xh[i] = *(uint4*)h;
}

// concat 3 bias vectors
__global__ void __launch_bounds__(256) bias_concat_kernel(
    const float* __restrict__ bq, const float* __restrict__ bk,
    const float* __restrict__ bv, float* __restrict__ o)
{
    const int i = blockIdx.x * 256 + threadIdx.x;      // 0..3071
    const int seg = i >> 10, off = i & 1023;
    o[i] = (seg == 0) ? bq[off] : (seg == 1) ? bk[off] : bv[off];
}

// ---------------------------------------------------------------------------
// fp16 mma.sync GEMM:  C[M,N] = A[M,K] @ W[K,N] + bias   (W given as Wt[n][k])
// CTA tile 128x256, BK=64 halves, 3-stage cp.async pipeline, 8 warps (2m x 4n),
// warp tile 64x64 = 4x8 m16n8k16 mma tiles. Fragments via ldmatrix.x4.
// EPI: 0 = fp32 out, 1 = half out, 2 = half out + GELU
// ---------------------------------------------------------------------------
#define HPAD 72
#define BN 256
#define STAGE_H ((128 + BN) * HPAD)                    // halves per stage
#define GEMM_SMEM (3 * STAGE_H * 2)                    // 165888 bytes

__device__ __forceinline__ void fill_stage(
    __half* As, __half* Bs, const __half* A, const __half* Bt,
    int bm, int bn, int k0, int K, int tid)
{
#pragma unroll
    for (int q = 0; q < 4; q++) {
        int idx = q * 256 + tid;
        int row = idx >> 3, c = idx & 7;
        cp_async16(smem_u32(&As[row * HPAD + c * 8]),
                   &A[(size_t)(bm + row) * K + k0 + c * 8]);
    }
#pragma unroll
    for (int q = 0; q < 8; q++) {
        int idx = q * 256 + tid;
        int row = idx >> 3, c = idx & 7;
        cp_async16(smem_u32(&Bs[row * HPAD + c * 8]),
                   &Bt[(size_t)(bn + row) * K + k0 + c * 8]);
    }
}

template<int EPI>
__global__ void __launch_bounds__(256) mma_gemm_h(
    const __half* __restrict__ A, const __half* __restrict__ Bt,
    const float* __restrict__ bias, void* __restrict__ Cout,
    int M, int N, int K)
{
    extern __shared__ __half shh[];
    const int tid  = threadIdx.x;
    const int wid  = tid >> 5;
    const int lane = tid & 31;
    const int g    = lane >> 2;
    const int t    = lane & 3;
    const int bm   = blockIdx.y * 128;
    const int bn   = blockIdx.x * BN;
    const int moff = (wid >> 2) * 64;
    const int noff = (wid & 3) * 64;

    const int a_r = lane & 15;
    const int a_c = (lane >> 4) * 8;
    const int b_r = (lane & 7) + ((lane >> 4) << 3);
    const int b_c = ((lane >> 3) & 1) * 8;

    const int iters = K >> 6;

    float acc[4][8][4];
#pragma unroll
    for (int a = 0; a < 4; a++)
#pragma unroll
        for (int b = 0; b < 8; b++)
#pragma unroll
            for (int c = 0; c < 4; c++) acc[a][b][c] = 0.0f;

    fill_stage(shh, shh + 128 * HPAD, A, Bt, bm, bn, 0, K, tid);
    CP_COMMIT();
    fill_stage(shh + STAGE_H, shh + STAGE_H + 128 * HPAD, A, Bt, bm, bn, 64, K, tid);
    CP_COMMIT();

    for (int i = 0; i < iters; i++) {
        if (i + 1 < iters) { CP_WAIT(1); } else { CP_WAIT(0); }
        __syncthreads();

        if (i + 2 < iters) {
            __half* st = shh + ((i + 2) % 3) * STAGE_H;
            fill_stage(st, st + 128 * HPAD, A, Bt, bm, bn, (i + 2) * 64, K, tid);
            CP_COMMIT();
        }

        const __half* As = shh + (i % 3) * STAGE_H;
        const __half* Bs = As + 128 * HPAD;
#pragma unroll
        for (int ks = 0; ks < 4; ks++) {
            uint32_t af[4][4], bf[8][2];
#pragma unroll
            for (int mt = 0; mt < 4; mt++) {
                uint32_t addr = smem_u32(
                    &As[(moff + mt * 16 + a_r) * HPAD + ks * 16 + a_c]);
                ldmatrix_x4(af[mt][0], af[mt][1], af[mt][2], af[mt][3], addr);
            }
#pragma unroll
            for (int np = 0; np < 4; np++) {
                uint32_t addr = smem_u32(
                    &Bs[(noff + np * 16 + b_r) * HPAD + ks * 16 + b_c]);
                ldmatrix_x4(bf[np * 2][0], bf[np * 2][1],
                            bf[np * 2 + 1][0], bf[np * 2 + 1][1], addr);
            }
#pragma unroll
            for (int mt = 0; mt < 4; mt++)
#pragma unroll
                for (int nt = 0; nt < 8; nt++)
                    mma_f16(acc[mt][nt][0], acc[mt][nt][1], acc[mt][nt][2], acc[mt][nt][3],
                            af[mt][0], af[mt][1], af[mt][2], af[mt][3],
                            bf[nt][0], bf[nt][1]);
        }
    }

    // epilogue
#pragma unroll
    for (int nt = 0; nt < 8; nt++) {
        const int col = bn + noff + nt * 8 + 2 * t;
        const float2 bv = *(const float2*)&bias[col];
#pragma unroll
        for (int mt = 0; mt < 4; mt++) {
            const int r0 = bm + moff + mt * 16 + g;
            float c0 = acc[mt][nt][0] + bv.x;
            float c1 = acc[mt][nt][1] + bv.y;
            float c2 = acc[mt][nt][2] + bv.x;
            float c3 = acc[mt][nt][3] + bv.y;
            if (EPI == 2) {
                c0 = gelu_fn(c0); c1 = gelu_fn(c1);
                c2 = gelu_fn(c2); c3 = gelu_fn(c3);
            }
            if (EPI == 0) {
                float* C = (float*)Cout;
                *(float2*)&C[(size_t)r0 * N + col]       = make_float2(c0, c1);
                *(float2*)&C[(size_t)(r0 + 8) * N + col] = make_float2(c2, c3);
            } else {
                __half* C = (__half*)Cout;
                *(__half2*)&C[(size_t)r0 * N + col]       = __floats2half2_rn(c0, c1);
                *(__half2*)&C[(size_t)(r0 + 8) * N + col] = __floats2half2_rn(c2, c3);
            }
        }
    }
}

// ---------------------------------------------------------------------------
// Flash attention, fp16 mma (m16n8k16).
// Q/K/V come from the fused QKV buffer (row stride NQKV).
// CTA: 128 queries x (head, batch). 8 warps x 16 query rows. Key blocks of 64.
// __launch_bounds__(256, 2) caps regs at 128 for 2 CTAs/SM.
// ---------------------------------------------------------------------------
#define BQ   128
#define BKV  64
#define NKB  (SEQ / BKV)
#define ATT_SMEM ((4 * BKV * HPAD + BQ * HPAD) * 2)    // 55296 B

__global__ void __launch_bounds__(256, 2) attn_mma_h_kernel(
    const __half* __restrict__ QKV, __half* __restrict__ Og)
{
    extern __shared__ __half sha[];
    __half* Ks = sha;                        // [2][BKV][HPAD]
    __half* Vs = sha + 2 * BKV * HPAD;       // [2][BKV][HPAD]
    __half* Ps = sha + 4 * BKV * HPAD;       // [BQ][HPAD] (Q staging, then P)

    const int tid  = threadIdx.x;
    const int wid  = tid >> 5;
    const int lane = tid & 31;
    const int g    = lane >> 2;
    const int t    = lane & 3;
    const int qt   = blockIdx.x;
    const int head = blockIdx.y;
    const int b    = blockIdx.z;

    const size_t baseq = ((size_t)b * SEQ) * NQKV + (size_t)head * DK;
    const __half* Qg = QKV + baseq;
    const __half* Kg = QKV + baseq + HID;
    const __half* Vg = QKV + baseq + 2 * HID;
    const size_t baso = ((size_t)b * SEQ) * HID + (size_t)head * DK;

    const int q0   = qt * BQ;
    const int moff = wid * 16;

    const int b_r = (lane & 7) + ((lane >> 4) << 3);
    const int b_c = ((lane >> 3) & 1) * 8;

    // prologue: Q (into Ps) + K0/V0
#pragma unroll
    for (int q = 0; q < 4; q++) {
        int idx = q * 256 + tid;
        int r = idx >> 3, c = idx & 7;
        cp_async16(smem_u32(&Ps[r * HPAD + c * 8]),
                   &Qg[(size_t)(q0 + r) * NQKV + c * 8]);
    }
#pragma unroll
    for (int q = 0; q < 2; q++) {
        int idx = q * 256 + tid;
        int r = idx >> 3, c = idx & 7;
        cp_async16(smem_u32(&Ks[r * HPAD + c * 8]),
                   &Kg[(size_t)r * NQKV + c * 8]);
        cp_async16(smem_u32(&Vs[r * HPAD + c * 8]),
                   &Vg[(size_t)r * NQKV + c * 8]);
    }
    CP_COMMIT();

    const uint32_t vlane_off = (uint32_t)((lane & 15) * HPAD + (lane >> 4) * 8);

    uint32_t qf[4][4];
    float oacc[8][4];
#pragma unroll
    for (int nt = 0; nt < 8; nt++)
#pragma unroll
        for (int c = 0; c < 4; c++) oacc[nt][c] = 0.0f;
    float m0 = -1e30f, m1 = -1e30f, l0 = 0.0f, l1 = 0.0f;

    for (int i = 0; i < NKB; i++) {
        if (i + 1 < NKB) {
            const int kn = (i + 1) * BKV;
            __half* Kb = Ks + ((i + 1) & 1) * BKV * HPAD;
            __half* Vb = Vs + ((i + 1) & 1) * BKV * HPAD;
#pragma unroll
            for (int q = 0; q < 2; q++) {
                int idx = q * 256 + tid;
                int r = idx >> 3, c = idx & 7;
                cp_async16(smem_u32(&Kb[r * HPAD + c * 8]),
                           &Kg[(size_t)(kn + r) * NQKV + c * 8]);
                cp_async16(smem_u32(&Vb[r * HPAD + c * 8]),
                           &Vg[(size_t)(kn + r) * NQKV + c * 8]);
            }
            CP_COMMIT();
            CP_WAIT(1);
        } else {
            CP_WAIT(0);
        }
        __syncthreads();

        if (i == 0) {
#pragma unroll
            for (int ks = 0; ks < 4; ks++) {
                const int kc = ks * 16 + 2 * t;
                qf[ks][0] = *(const uint32_t*)&Ps[(moff + g) * HPAD + kc];
                qf[ks][1] = *(const uint32_t*)&Ps[(moff + 8 + g) * HPAD + kc];
                qf[ks][2] = *(const uint32_t*)&Ps[(moff + g) * HPAD + kc + 8];
                qf[ks][3] = *(const uint32_t*)&Ps[(moff + 8 + g) * HPAD + kc + 8];
            }
        }

        const __half* Kb = Ks + (i & 1) * BKV * HPAD;
        const __half* Vb = Vs + (i & 1) * BKV * HPAD;

        // ---- S = Q K^T ----
        float sacc[8][4];
#pragma unroll
        for (int nt = 0; nt < 8; nt++)
#pragma unroll
            for (int c = 0; c < 4; c++) sacc[nt][c] = 0.0f;

#pragma unroll
        for (int ks = 0; ks < 4; ks++) {
            uint32_t bf[8][2];
#pragma unroll
            for (int np = 0; np < 4; np++) {
                uint32_t addr = smem_u32(
                    &Kb[(np * 16 + b_r) * HPAD + ks * 16 + b_c]);
                ldmatrix_x4(bf[np * 2][0], bf[np * 2][1],
                            bf[np * 2 + 1][0], bf[np * 2 + 1][1], addr);
            }
#pragma unroll
            for (int nt = 0; nt < 8; nt++)
                mma_f16(sacc[nt][0], sacc[nt][1], sacc[nt][2], sacc[nt][3],
                        qf[ks][0], qf[ks][1], qf[ks][2], qf[ks][3],
                        bf[nt][0], bf[nt][1]);
        }

        // ---- online softmax ----
        float rx0 = -1e30f, rx1 = -1e30f;
#pragma unroll
        for (int nt = 0; nt < 8; nt++) {
            sacc[nt][0] *= 0.125f; sacc[nt][1] *= 0.125f;
            sacc[nt][2] *= 0.125f; sacc[nt][3] *= 0.125f;
            rx0 = fmaxf(rx0, fmaxf(sacc[nt][0], sacc[nt][1]));
            rx1 = fmaxf(rx1, fmaxf(sacc[nt][2], sacc[nt][3]));
        }
        rx0 = fmaxf(rx0, __shfl_xor_sync(0xffffffffu, rx0, 1));
        rx0 = fmaxf(rx0, __shfl_xor_sync(0xffffffffu, rx0, 2));
        rx1 = fmaxf(rx1, __shfl_xor_sync(0xffffffffu, rx1, 1));
        rx1 = fmaxf(rx1, __shfl_xor_sync(0xffffffffu, rx1, 2));

        const float nm0 = fmaxf(m0, rx0);
        const float nm1 = fmaxf(m1, rx1);
        const float corr0 = __expf(m0 - nm0);
        const float corr1 = __expf(m1 - nm1);

        float rs0 = 0.0f, rs1 = 0.0f;
#pragma unroll
        for (int nt = 0; nt < 8; nt++) {
            sacc[nt][0] = __expf(sacc[nt][0] - nm0);
            sacc[nt][1] = __expf(sacc[nt][1] - nm0);
            sacc[nt][2] = __expf(sacc[nt][2] - nm1);
            sacc[nt][3] = __expf(sacc[nt][3] - nm1);
            rs0 += sacc[nt][0] + sacc[nt][1];
            rs1 += sacc[nt][2] + sacc[nt][3];
        }
        rs0 += __shfl_xor_sync(0xffffffffu, rs0, 1);
        rs0 += __shfl_xor_sync(0xffffffffu, rs0, 2);
        rs1 += __shfl_xor_sync(0xffffffffu, rs1, 1);
        rs1 += __shfl_xor_sync(0xffffffffu, rs1, 2);

        l0 = l0 * corr0 + rs0;  m0 = nm0;
        l1 = l1 * corr1 + rs1;  m1 = nm1;

#pragma unroll
        for (int nt = 0; nt < 8; nt++) {
            oacc[nt][0] *= corr0; oacc[nt][1] *= corr0;
            oacc[nt][2] *= corr1; oacc[nt][3] *= corr1;
        }

        // ---- P -> smem (half2), warp-private rows ----
#pragma unroll
        for (int nt = 0; nt < 8; nt++) {
            *(__half2*)&Ps[(moff + g) * HPAD + nt * 8 + 2 * t] =
                __floats2half2_rn(sacc[nt][0], sacc[nt][1]);
            *(__half2*)&Ps[(moff + 8 + g) * HPAD + nt * 8 + 2 * t] =
                __floats2half2_rn(sacc[nt][2], sacc[nt][3]);
        }
        __syncwarp();

        // ---- O += P @ V ----
        const uint32_t vbase = smem_u32(Vb) + vlane_off * 2;
#pragma unroll
        for (int ks = 0; ks < 4; ks++) {
            const int kc = ks * 16 + 2 * t;
            const uint32_t a0 = *(const uint32_t*)&Ps[(moff + g) * HPAD + kc];
            const uint32_t a1 = *(const uint32_t*)&Ps[(moff + 8 + g) * HPAD + kc];
            const uint32_t a2 = *(const uint32_t*)&Ps[(moff + g) * HPAD + kc + 8];
            const uint32_t a3 = *(const uint32_t*)&Ps[(moff + 8 + g) * HPAD + kc + 8];
            const uint32_t vrow = vbase + (uint32_t)(ks * 16 * HPAD * 2);
#pragma unroll
            for (int n16 = 0; n16 < 4; n16++) {
                uint32_t r0, r1, r2, r3;
                ldmatrix_x4_trans(r0, r1, r2, r3, vrow + (uint32_t)(n16 * 32));
                mma_f16(oacc[n16 * 2][0], oacc[n16 * 2][1], oacc[n16 * 2][2], oacc[n16 * 2][3],
                        a0, a1, a2, a3, r0, r1);
                mma_f16(oacc[n16 * 2 + 1][0], oacc[n16 * 2 + 1][1],
                        oacc[n16 * 2 + 1][2], oacc[n16 * 2 + 1][3],
                        a0, a1, a2, a3, r2, r3);
            }
        }
        __syncthreads();
    }

    // epilogue: normalize, write ctx (half)
    const float inv0 = 1.0f / l0;
    const float inv1 = 1.0f / l1;
    const int r0 = q0 + moff + g;
    const int r1 = r0 + 8;
#pragma unroll
    for (int nt = 0; nt < 8; nt++) {
        const int col = nt * 8 + 2 * t;
        *(__half2*)&Og[baso + (size_t)r0 * HID + col] =
            __floats2half2_rn(oacc[nt][0] * inv0, oacc[nt][1] * inv0);
        *(__half2*)&Og[baso + (size_t)r1 * HID + col] =
            __floats2half2_rn(oacc[nt][2] * inv1, oacc[nt][3] * inv1);
    }
}

// ---------------------------------------------------------------------------
// Residual add + LayerNorm (optionally also emits a half copy)
// ---------------------------------------------------------------------------
template<int HALF_OUT>
__global__ void __launch_bounds__(256) add_ln_kernel(
    const float* __restrict__ X, const float* __restrict__ Y,
    const float* __restrict__ g, const float* __restrict__ be,
    float* __restrict__ out, __half* __restrict__ outh)
{
    const int row = blockIdx.x;
    const int tid = threadIdx.x;
    const size_t base = (size_t)row * HID;

    float v[4];
    float s = 0.0f, s2 = 0.0f;
#pragma unroll
    for (int k = 0; k < 4; k++) {
        int c = tid + k * 256;
        float tt = X[base + c] + Y[base + c];
        v[k] = tt;
        s += tt;
        s2 += tt * tt;
    }
#pragma unroll
    for (int off = 16; off > 0; off >>= 1) {
        s  += __shfl_xor_sync(0xffffffffu, s,  off);
        s2 += __shfl_xor_sync(0xffffffffu, s2, off);
    }
    __shared__ float red[16];
    const int warp = tid >> 5, lane = tid & 31;
    if (lane == 0) { red[warp] = s; red[warp + 8] = s2; }
    __syncthreads();
    if (tid < 32) {
        float a = (lane < 8) ? red[lane]     : 0.0f;
        float c2 = (lane < 8) ? red[lane + 8] : 0.0f;
#pragma unroll
        for (int off = 4; off > 0; off >>= 1) {
            a  += __shfl_xor_sync(0xffffffffu, a,  off);
            c2 += __shfl_xor_sync(0xffffffffu, c2, off);
        }
        if (lane == 0) { red[0] = a; red[1] = c2; }
    }
    __syncthreads();
    const float mu  = red[0] * (1.0f / HID);
    const float var = red[1] * (1.0f / HID) - mu * mu;
    const float inv = rsqrtf(var + 1e-5f);
#pragma unroll
    for (int k = 0; k < 4; k++) {
        int c = tid + k * 256;
        float r = (v[k] - mu) * inv * g[c] + be[c];
        out[base + c] = r;
        if (HALF_OUT) outh[base + c] = __float2half_rn(r);
    }
}

// ---------------------------------------------------------------------------
// kernel_launch
// ---------------------------------------------------------------------------
extern "C" void kernel_launch(void* const* d_in, const int* in_sizes, int n_in,
                              void* d_out, int out_size)
{
    const float* x  = (const float*)d_in[0];
    const float* Wq = (const float*)d_in[1];
    const float* bq = (const float*)d_in[2];
    const float* Wk = (const float*)d_in[3];
    const float* bk = (const float*)d_in[4];
    const float* Wv = (const float*)d_in[5];
    const float* bv = (const float*)d_in[6];
    const float* Wo = (const float*)d_in[7];
    const float* bo = (const float*)d_in[8];
    const float* W1 = (const float*)d_in[9];
    const float* b1 = (const float*)d_in[10];
    const float* W2 = (const float*)d_in[11];
    const float* b2 = (const float*)d_in[12];
    const float* g1 = (const float*)d_in[13];
    const float* be1= (const float*)d_in[14];
    const float* g2 = (const float*)d_in[15];
    const float* be2= (const float*)d_in[16];
    float* out = (float*)d_out;

    __half *xh, *qkvh, *ctxh, *x1h, *hh;
    float *ao, *x1, *ff, *bqkv;
    __half *wqkvt, *wot, *w1t, *w2t;
    cudaGetSymbolAddress((void**)&xh,    g_xh);
    cudaGetSymbolAddress((void**)&qkvh,  g_qkvh);
    cudaGetSymbolAddress((void**)&ctxh,  g_ctxh);
    cudaGetSymbolAddress((void**)&ao,    g_ao);
    cudaGetSymbolAddress((void**)&x1,    g_x1);
    cudaGetSymbolAddress((void**)&x1h,   g_x1h);
    cudaGetSymbolAddress((void**)&hh,    g_hh);
    cudaGetSymbolAddress((void**)&ff,    g_ff);
    cudaGetSymbolAddress((void**)&wqkvt, g_wqkvt);
    cudaGetSymbolAddress((void**)&wot,   g_wot);
    cudaGetSymbolAddress((void**)&w1t,   g_w1t);
    cudaGetSymbolAddress((void**)&w2t,   g_w2t);
    cudaGetSymbolAddress((void**)&bqkv,  g_bqkv);

    cudaFuncSetAttribute(attn_mma_h_kernel,
                         cudaFuncAttributeMaxDynamicSharedMemorySize, ATT_SMEM);
    cudaFuncSetAttribute(mma_gemm_h<0>,
                         cudaFuncAttributeMaxDynamicSharedMemorySize, GEMM_SMEM);
    cudaFuncSetAttribute(mma_gemm_h<1>,
                         cudaFuncAttributeMaxDynamicSharedMemorySize, GEMM_SMEM);
    cudaFuncSetAttribute(mma_gemm_h<2>,
                         cudaFuncAttributeMaxDynamicSharedMemorySize, GEMM_SMEM);

    const dim3 blk256(256);

    // launches 0-4 (QKV weight prep; QKV GEMM lands at launch index 5 for ncu)
    transpose_h_kernel<<<dim3(HID/32, HID/32), blk256>>>(Wq, wqkvt, HID, HID);
    transpose_h_kernel<<<dim3(HID/32, HID/32), blk256>>>(Wk, wqkvt + (size_t)HID * HID, HID, HID);
    transpose_h_kernel<<<dim3(HID/32, HID/32), blk256>>>(Wv, wqkvt + (size_t)2 * HID * HID, HID, HID);
    convert_h_kernel<<<MTOT * HID / (256 * 8), blk256>>>(x, xh);
    bias_concat_kernel<<<NQKV / 256, blk256>>>(bq, bk, bv, bqkv);

    // launch 5: fused QKV GEMM  (8192 x 3072 x 1024)
    mma_gemm_h<1><<<dim3(NQKV / BN, MTOT / 128), blk256, GEMM_SMEM>>>(
        xh, wqkvt, bqkv, qkvh, MTOT, NQKV, HID);

    // attention (fp16 tensor cores, 2 CTAs/SM target)
    attn_mma_h_kernel<<<dim3(SEQ / BQ, NHEAD, BATCH), blk256, ATT_SMEM>>>(qkvh, ctxh);

    // remaining weight transposes
    transpose_h_kernel<<<dim3(HID/32, HID/32), blk256>>>(Wo, wot, HID, HID);
    transpose_h_kernel<<<dim3(DFF/32, HID/32), blk256>>>(W1, w1t, HID, DFF);
    transpose_h_kernel<<<dim3(HID/32, DFF/32), blk256>>>(W2, w2t, DFF, HID);

    const dim3 gProj(HID / BN, MTOT / 128);   // (4, 64)
    const dim3 gFF1 (DFF / BN, MTOT / 128);   // (16, 64)

    // Output projection (fp32 out) + residual/LN1 (emit half copy for FF1)
    mma_gemm_h<0><<<gProj, blk256, GEMM_SMEM>>>(ctxh, wot, bo, ao, MTOT, HID, HID);
    add_ln_kernel<1><<<MTOT, blk256>>>(x, ao, g1, be1, x1, x1h);

    // FFN
    mma_gemm_h<2><<<gFF1, blk256, GEMM_SMEM>>>(x1h, w1t, b1, hh, MTOT, DFF, HID);
    mma_gemm_h<0><<<gProj, blk256, GEMM_SMEM>>>(hh, w2t, b2, ff, MTOT, HID, DFF);

    // Residual/LN2 -> output
    add_ln_kernel<0><<<MTOT, blk256>>>(x1, ff, g2, be2, out, nullptr);
}

// round 9
// speedup vs baseline: 6.6048x; 1.0129x over previous
#include <cuda_runtime.h>
#include <cuda_fp16.h>
#include <math.h>
#include <cstdint>

// Problem constants
#define BATCH 4
#define SEQ   2048
#define HID   1024
#define NHEAD 16
#define DK    64
#define DFF   4096
#define MTOT  (BATCH * SEQ)          // 8192 rows
#define NQKV  (3 * HID)              // 3072

// ---------------------------------------------------------------------------
// Scratch
// ---------------------------------------------------------------------------
__device__ __half g_xh  [MTOT * HID];
__device__ __half g_qkvh[MTOT * NQKV];
__device__ __half g_ctxh[MTOT * HID];
__device__ float  g_ao  [MTOT * HID];
__device__ float  g_x1  [MTOT * HID];
__device__ __half g_x1h [MTOT * HID];
__device__ __half g_hh  [MTOT * DFF];
__device__ float  g_ff  [MTOT * HID];
__device__ __half g_wqkvt[NQKV * HID];
__device__ __half g_wot [HID * HID];
__device__ __half g_w1t [HID * DFF];
__device__ __half g_w2t [DFF * HID];
__device__ float  g_bqkv[NQKV];

// ---------------------------------------------------------------------------
// helpers
// ---------------------------------------------------------------------------
__device__ __forceinline__ uint32_t smem_u32(const void* p) {
    uint32_t a;
    asm("{ .reg .u64 t; cvta.to.shared.u64 t, %1; cvt.u32.u64 %0, t; }" : "=r"(a) : "l"(p));
    return a;
}
__device__ __forceinline__ void cp_async16(uint32_t saddr, const void* gaddr) {
    asm volatile("cp.async.cg.shared.global [%0], [%1], 16;" :: "r"(saddr), "l"(gaddr) : "memory");
}
#define CP_COMMIT() asm volatile("cp.async.commit_group;" ::: "memory")
#define CP_WAIT(n)  asm volatile("cp.async.wait_group %0;" :: "n"(n) : "memory")

__device__ __forceinline__ void mma_f16(
    float& d0, float& d1, float& d2, float& d3,
    uint32_t a0, uint32_t a1, uint32_t a2, uint32_t a3,
    uint32_t b0, uint32_t b1)
{
    asm volatile(
        "mma.sync.aligned.m16n8k16.row.col.f32.f16.f16.f32 "
        "{%0,%1,%2,%3}, {%4,%5,%6,%7}, {%8,%9}, {%0,%1,%2,%3};"
        : "+f"(d0), "+f"(d1), "+f"(d2), "+f"(d3)
        : "r"(a0), "r"(a1), "r"(a2), "r"(a3), "r"(b0), "r"(b1));
}
__device__ __forceinline__ void ldmatrix_x4(
    uint32_t& r0, uint32_t& r1, uint32_t& r2, uint32_t& r3, uint32_t addr)
{
    asm volatile("ldmatrix.sync.aligned.m8n8.x4.shared.b16 {%0,%1,%2,%3}, [%4];"
                 : "=r"(r0), "=r"(r1), "=r"(r2), "=r"(r3) : "r"(addr));
}
__device__ __forceinline__ void ldmatrix_x4_trans(
    uint32_t& r0, uint32_t& r1, uint32_t& r2, uint32_t& r3, uint32_t addr)
{
    asm volatile("ldmatrix.sync.aligned.m8n8.x4.trans.shared.b16 {%0,%1,%2,%3}, [%4];"
                 : "=r"(r0), "=r"(r1), "=r"(r2), "=r"(r3) : "r"(addr));
}

__device__ __forceinline__ float gelu_fn(float x) {
    const float c = 0.7978845608028654f;
    float x3 = x * x * x;
    return 0.5f * x * (1.0f + tanhf(c * (x + 0.044715f * x3)));
}

// ---------------------------------------------------------------------------
// Fused prep kernel: all weight transposes + x conversion + bias concat.
// Block partition: [0,4096)   4 square 1024x1024 transposes (Wq,Wk,Wv,Wo)
//                  [4096,8192)  W1 (K=1024,N=4096)
//                  [8192,12288) W2 (K=4096,N=1024)
//                  [12288,16384) x -> xh conversion
//                  [16384,16396) bias concat
// ---------------------------------------------------------------------------
__device__ __forceinline__ void transpose_tile(
    float (*t)[33], const float* __restrict__ W, __half* __restrict__ Wt,
    int K, int N, int bx, int by, int tid)
{
    const int tx = tid & 31;
    const int ty = tid >> 5;
    const int b0 = bx * 32, k0 = by * 32;
#pragma unroll
    for (int q = 0; q < 4; q++)
        t[ty + q * 8][tx] = W[(size_t)(k0 + ty + q * 8) * N + b0 + tx];
    __syncthreads();
#pragma unroll
    for (int q = 0; q < 4; q++)
        Wt[(size_t)(b0 + ty + q * 8) * K + k0 + tx] = __float2half_rn(t[tx][ty + q * 8]);
}

__global__ void __launch_bounds__(256) prep_kernel(
    const float* __restrict__ Wq, const float* __restrict__ Wk,
    const float* __restrict__ Wv, const float* __restrict__ Wo,
    const float* __restrict__ W1, const float* __restrict__ W2,
    const float* __restrict__ x,
    const float* __restrict__ bq, const float* __restrict__ bk,
    const float* __restrict__ bv)
{
    __shared__ float t[32][33];
    const int id  = blockIdx.x;
    const int tid = threadIdx.x;

    if (id < 4096) {
        const int m = id >> 10;
        const float* W = (m == 0) ? Wq : (m == 1) ? Wk : (m == 2) ? Wv : Wo;
        __half* Wt = (m == 0) ? g_wqkvt
                   : (m == 1) ? g_wqkvt + (size_t)HID * HID
                   : (m == 2) ? g_wqkvt + (size_t)2 * HID * HID
                   : g_wot;
        const int lid = id & 1023;
        transpose_tile(t, W, Wt, HID, HID, lid & 31, lid >> 5, tid);
    } else if (id < 8192) {
        const int lid = id - 4096;
        transpose_tile(t, W1, g_w1t, HID, DFF, lid & 127, lid >> 7, tid);
    } else if (id < 12288) {
        const int lid = id - 8192;
        transpose_tile(t, W2, g_w2t, DFF, HID, lid & 31, lid >> 5, tid);
    } else if (id < 16384) {
        const int i = ((id - 12288) * 256 + tid) * 8;
        float4 a = *(const float4*)&x[i];
        float4 b = *(const float4*)&x[i + 4];
        __half2 h[4];
        h[0] = __floats2half2_rn(a.x, a.y);
        h[1] = __floats2half2_rn(a.z, a.w);
        h[2] = __floats2half2_rn(b.x, b.y);
        h[3] = __floats2half2_rn(b.z, b.w);
        *(uint4*)&g_xh[i] = *(uint4*)h;
    } else {
        const int i = (id - 16384) * 256 + tid;      // 0..3071
        const int seg = i >> 10, off = i & 1023;
        g_bqkv[i] = (seg == 0) ? bq[off] : (seg == 1) ? bk[off] : bv[off];
    }
}

// ---------------------------------------------------------------------------
// fp16 mma.sync GEMM:  C[M,N] = A[M,K] @ W[K,N] + bias   (W given as Wt[n][k])
// CTA tile 128x256, BK=64, 3-stage cp.async pipeline, 8 warps (2m x 4n),
// warp tile 64x64. Fragments via ldmatrix.x4.
// EPI: 0 = fp32 out, 1 = half out, 2 = half out + GELU
// ---------------------------------------------------------------------------
#define HPAD 72
#define BN 256
#define STAGE_H ((128 + BN) * HPAD)
#define GEMM_SMEM (3 * STAGE_H * 2)                    // 165888 bytes

__device__ __forceinline__ void fill_stage(
    __half* As, __half* Bs, const __half* A, const __half* Bt,
    int bm, int bn, int k0, int K, int tid)
{
#pragma unroll
    for (int q = 0; q < 4; q++) {
        int idx = q * 256 + tid;
        int row = idx >> 3, c = idx & 7;
        cp_async16(smem_u32(&As[row * HPAD + c * 8]),
                   &A[(size_t)(bm + row) * K + k0 + c * 8]);
    }
#pragma unroll
    for (int q = 0; q < 8; q++) {
        int idx = q * 256 + tid;
        int row = idx >> 3, c = idx & 7;
        cp_async16(smem_u32(&Bs[row * HPAD + c * 8]),
                   &Bt[(size_t)(bn + row) * K + k0 + c * 8]);
    }
}

template<int EPI>
__global__ void __launch_bounds__(256) mma_gemm_h(
    const __half* __restrict__ A, const __half* __restrict__ Bt,
    const float* __restrict__ bias, void* __restrict__ Cout,
    int M, int N, int K)
{
    extern __shared__ __half shh[];
    const int tid  = threadIdx.x;
    const int wid  = tid >> 5;
    const int lane = tid & 31;
    const int g    = lane >> 2;
    const int t    = lane & 3;
    const int bm   = blockIdx.y * 128;
    const int bn   = blockIdx.x * BN;
    const int moff = (wid >> 2) * 64;
    const int noff = (wid & 3) * 64;

    const int a_r = lane & 15;
    const int a_c = (lane >> 4) * 8;
    const int b_r = (lane & 7) + ((lane >> 4) << 3);
    const int b_c = ((lane >> 3) & 1) * 8;

    const int iters = K >> 6;

    float acc[4][8][4];
#pragma unroll
    for (int a = 0; a < 4; a++)
#pragma unroll
        for (int b = 0; b < 8; b++)
#pragma unroll
            for (int c = 0; c < 4; c++) acc[a][b][c] = 0.0f;

    fill_stage(shh, shh + 128 * HPAD, A, Bt, bm, bn, 0, K, tid);
    CP_COMMIT();
    fill_stage(shh + STAGE_H, shh + STAGE_H + 128 * HPAD, A, Bt, bm, bn, 64, K, tid);
    CP_COMMIT();

    for (int i = 0; i < iters; i++) {
        if (i + 1 < iters) { CP_WAIT(1); } else { CP_WAIT(0); }
        __syncthreads();

        if (i + 2 < iters) {
            __half* st = shh + ((i + 2) % 3) * STAGE_H;
            fill_stage(st, st + 128 * HPAD, A, Bt, bm, bn, (i + 2) * 64, K, tid);
            CP_COMMIT();
        }

        const __half* As = shh + (i % 3) * STAGE_H;
        const __half* Bs = As + 128 * HPAD;
#pragma unroll
        for (int ks = 0; ks < 4; ks++) {
            uint32_t af[4][4], bf[8][2];
#pragma unroll
            for (int mt = 0; mt < 4; mt++) {
                uint32_t addr = smem_u32(
                    &As[(moff + mt * 16 + a_r) * HPAD + ks * 16 + a_c]);
                ldmatrix_x4(af[mt][0], af[mt][1], af[mt][2], af[mt][3], addr);
            }
#pragma unroll
            for (int np = 0; np < 4; np++) {
                uint32_t addr = smem_u32(
                    &Bs[(noff + np * 16 + b_r) * HPAD + ks * 16 + b_c]);
                ldmatrix_x4(bf[np * 2][0], bf[np * 2][1],
                            bf[np * 2 + 1][0], bf[np * 2 + 1][1], addr);
            }
#pragma unroll
            for (int mt = 0; mt < 4; mt++)
#pragma unroll
                for (int nt = 0; nt < 8; nt++)
                    mma_f16(acc[mt][nt][0], acc[mt][nt][1], acc[mt][nt][2], acc[mt][nt][3],
                            af[mt][0], af[mt][1], af[mt][2], af[mt][3],
                            bf[nt][0], bf[nt][1]);
        }
    }

    // epilogue
#pragma unroll
    for (int nt = 0; nt < 8; nt++) {
        const int col = bn + noff + nt * 8 + 2 * t;
        const float2 bv = *(const float2*)&bias[col];
#pragma unroll
        for (int mt = 0; mt < 4; mt++) {
            const int r0 = bm + moff + mt * 16 + g;
            float c0 = acc[mt][nt][0] + bv.x;
            float c1 = acc[mt][nt][1] + bv.y;
            float c2 = acc[mt][nt][2] + bv.x;
            float c3 = acc[mt][nt][3] + bv.y;
            if (EPI == 2) {
                c0 = gelu_fn(c0); c1 = gelu_fn(c1);
                c2 = gelu_fn(c2); c3 = gelu_fn(c3);
            }
            if (EPI == 0) {
                float* C = (float*)Cout;
                *(float2*)&C[(size_t)r0 * N + col]       = make_float2(c0, c1);
                *(float2*)&C[(size_t)(r0 + 8) * N + col] = make_float2(c2, c3);
            } else {
                __half* C = (__half*)Cout;
                *(__half2*)&C[(size_t)r0 * N + col]       = __floats2half2_rn(c0, c1);
                *(__half2*)&C[(size_t)(r0 + 8) * N + col] = __floats2half2_rn(c2, c3);
            }
        }
    }
}

// ---------------------------------------------------------------------------
// Flash attention, fp16 mma. 2 CTAs/SM (reduced register pressure: Q lives in
// its own smem region; Q fragments re-loaded per key block via ldmatrix).
// CTA: 128 queries x (head, batch). 8 warps x 16 query rows. Key blocks of 64.
// ---------------------------------------------------------------------------
#define BQ   128
#define BKV  64
#define NKB  (SEQ / BKV)
// Qs(BQ) + K,V double(4*BKV) + Ps(BQ), rows of HPAD halves
#define ATT_SMEM ((2 * BQ * HPAD + 4 * BKV * HPAD) * 2)   // 73728 B

__global__ void __launch_bounds__(256, 2) attn_mma_h_kernel(
    const __half* __restrict__ QKV, __half* __restrict__ Og)
{
    extern __shared__ __half sha[];
    __half* Qs = sha;                              // [BQ][HPAD]
    __half* Ks = sha + BQ * HPAD;                  // [2][BKV][HPAD]
    __half* Vs = sha + BQ * HPAD + 2 * BKV * HPAD; // [2][BKV][HPAD]
    __half* Ps = sha + BQ * HPAD + 4 * BKV * HPAD; // [BQ][HPAD]

    const int tid  = threadIdx.x;
    const int wid  = tid >> 5;
    const int lane = tid & 31;
    const int g    = lane >> 2;
    const int t    = lane & 3;
    const int qt   = blockIdx.x;
    const int head = blockIdx.y;
    const int b    = blockIdx.z;

    const size_t baseq = ((size_t)b * SEQ) * NQKV + (size_t)head * DK;
    const __half* Qg = QKV + baseq;
    const __half* Kg = QKV + baseq + HID;
    const __half* Vg = QKV + baseq + 2 * HID;
    const size_t baso = ((size_t)b * SEQ) * HID + (size_t)head * DK;

    const int q0   = qt * BQ;
    const int moff = wid * 16;

    const int a_r = lane & 15;
    const int a_c = (lane >> 4) * 8;
    const int b_r = (lane & 7) + ((lane >> 4) << 3);
    const int b_c = ((lane >> 3) & 1) * 8;

    // prologue: Q (into Qs) + K0/V0
#pragma unroll
    for (int q = 0; q < 4; q++) {
        int idx = q * 256 + tid;
        int r = idx >> 3, c = idx & 7;
        cp_async16(smem_u32(&Qs[r * HPAD + c * 8]),
                   &Qg[(size_t)(q0 + r) * NQKV + c * 8]);
    }
#pragma unroll
    for (int q = 0; q < 2; q++) {
        int idx = q * 256 + tid;
        int r = idx >> 3, c = idx & 7;
        cp_async16(smem_u32(&Ks[r * HPAD + c * 8]),
                   &Kg[(size_t)r * NQKV + c * 8]);
        cp_async16(smem_u32(&Vs[r * HPAD + c * 8]),
                   &Vg[(size_t)r * NQKV + c * 8]);
    }
    CP_COMMIT();

    const uint32_t vlane_off = (uint32_t)((lane & 15) * HPAD + (lane >> 4) * 8);

    float oacc[8][4];
#pragma unroll
    for (int nt = 0; nt < 8; nt++)
#pragma unroll
        for (int c = 0; c < 4; c++) oacc[nt][c] = 0.0f;
    float m0 = -1e30f, m1 = -1e30f, l0 = 0.0f, l1 = 0.0f;

    for (int i = 0; i < NKB; i++) {
        if (i + 1 < NKB) {
            const int kn = (i + 1) * BKV;
            __half* Kb = Ks + ((i + 1) & 1) * BKV * HPAD;
            __half* Vb = Vs + ((i + 1) & 1) * BKV * HPAD;
#pragma unroll
            for (int q = 0; q < 2; q++) {
                int idx = q * 256 + tid;
                int r = idx >> 3, c = idx & 7;
                cp_async16(smem_u32(&Kb[r * HPAD + c * 8]),
                           &Kg[(size_t)(kn + r) * NQKV + c * 8]);
                cp_async16(smem_u32(&Vb[r * HPAD + c * 8]),
                           &Vg[(size_t)(kn + r) * NQKV + c * 8]);
            }
            CP_COMMIT();
            CP_WAIT(1);
        } else {
            CP_WAIT(0);
        }
        __syncthreads();

        const __half* Kb = Ks + (i & 1) * BKV * HPAD;
        const __half* Vb = Vs + (i & 1) * BKV * HPAD;

        // ---- S = Q K^T ----  (Q and K fragments via ldmatrix each block)
        float sacc[8][4];
#pragma unroll
        for (int nt = 0; nt < 8; nt++)
#pragma unroll
            for (int c = 0; c < 4; c++) sacc[nt][c] = 0.0f;

#pragma unroll
        for (int ks = 0; ks < 4; ks++) {
            uint32_t qf[4];
            {
                uint32_t addr = smem_u32(
                    &Qs[(moff + a_r) * HPAD + ks * 16 + a_c]);
                ldmatrix_x4(qf[0], qf[1], qf[2], qf[3], addr);
            }
            uint32_t bf[8][2];
#pragma unroll
            for (int np = 0; np < 4; np++) {
                uint32_t addr = smem_u32(
                    &Kb[(np * 16 + b_r) * HPAD + ks * 16 + b_c]);
                ldmatrix_x4(bf[np * 2][0], bf[np * 2][1],
                            bf[np * 2 + 1][0], bf[np * 2 + 1][1], addr);
            }
#pragma unroll
            for (int nt = 0; nt < 8; nt++)
                mma_f16(sacc[nt][0], sacc[nt][1], sacc[nt][2], sacc[nt][3],
                        qf[0], qf[1], qf[2], qf[3],
                        bf[nt][0], bf[nt][1]);
        }

        // ---- online softmax ----
        float rx0 = -1e30f, rx1 = -1e30f;
#pragma unroll
        for (int nt = 0; nt < 8; nt++) {
            sacc[nt][0] *= 0.125f; sacc[nt][1] *= 0.125f;
            sacc[nt][2] *= 0.125f; sacc[nt][3] *= 0.125f;
            rx0 = fmaxf(rx0, fmaxf(sacc[nt][0], sacc[nt][1]));
            rx1 = fmaxf(rx1, fmaxf(sacc[nt][2], sacc[nt][3]));
        }
        rx0 = fmaxf(rx0, __shfl_xor_sync(0xffffffffu, rx0, 1));
        rx0 = fmaxf(rx0, __shfl_xor_sync(0xffffffffu, rx0, 2));
        rx1 = fmaxf(rx1, __shfl_xor_sync(0xffffffffu, rx1, 1));
        rx1 = fmaxf(rx1, __shfl_xor_sync(0xffffffffu, rx1, 2));

        const float nm0 = fmaxf(m0, rx0);
        const float nm1 = fmaxf(m1, rx1);
        const float corr0 = __expf(m0 - nm0);
        const float corr1 = __expf(m1 - nm1);

        float rs0 = 0.0f, rs1 = 0.0f;
#pragma unroll
        for (int nt = 0; nt < 8; nt++) {
            sacc[nt][0] = __expf(sacc[nt][0] - nm0);
            sacc[nt][1] = __expf(sacc[nt][1] - nm0);
            sacc[nt][2] = __expf(sacc[nt][2] - nm1);
            sacc[nt][3] = __expf(sacc[nt][3] - nm1);
            rs0 += sacc[nt][0] + sacc[nt][1];
            rs1 += sacc[nt][2] + sacc[nt][3];
        }
        rs0 += __shfl_xor_sync(0xffffffffu, rs0, 1);
        rs0 += __shfl_xor_sync(0xffffffffu, rs0, 2);
        rs1 += __shfl_xor_sync(0xffffffffu, rs1, 1);
        rs1 += __shfl_xor_sync(0xffffffffu, rs1, 2);

        l0 = l0 * corr0 + rs0;  m0 = nm0;
        l1 = l1 * corr1 + rs1;  m1 = nm1;

#pragma unroll
        for (int nt = 0; nt < 8; nt++) {
            oacc[nt][0] *= corr0; oacc[nt][1] *= corr0;
            oacc[nt][2] *= corr1; oacc[nt][3] *= corr1;
        }

        // ---- P -> smem (half2), warp-private rows ----
#pragma unroll
        for (int nt = 0; nt < 8; nt++) {
            *(__half2*)&Ps[(moff + g) * HPAD + nt * 8 + 2 * t] =
                __floats2half2_rn(sacc[nt][0], sacc[nt][1]);
            *(__half2*)&Ps[(moff + 8 + g) * HPAD + nt * 8 + 2 * t] =
                __floats2half2_rn(sacc[nt][2], sacc[nt][3]);
        }
        __syncwarp();

        // ---- O += P @ V ----
        const uint32_t vbase = smem_u32(Vb) + vlane_off * 2;
#pragma unroll
        for (int ks = 0; ks < 4; ks++) {
            const int kc = ks * 16 + 2 * t;
            const uint32_t a0 = *(const uint32_t*)&Ps[(moff + g) * HPAD + kc];
            const uint32_t a1 = *(const uint32_t*)&Ps[(moff + 8 + g) * HPAD + kc];
            const uint32_t a2 = *(const uint32_t*)&Ps[(moff + g) * HPAD + kc + 8];
            const uint32_t a3 = *(const uint32_t*)&Ps[(moff + 8 + g) * HPAD + kc + 8];
            const uint32_t vrow = vbase + (uint32_t)(ks * 16 * HPAD * 2);
#pragma unroll
            for (int n16 = 0; n16 < 4; n16++) {
                uint32_t r0, r1, r2, r3;
                ldmatrix_x4_trans(r0, r1, r2, r3, vrow + (uint32_t)(n16 * 32));
                mma_f16(oacc[n16 * 2][0], oacc[n16 * 2][1], oacc[n16 * 2][2], oacc[n16 * 2][3],
                        a0, a1, a2, a3, r0, r1);
                mma_f16(oacc[n16 * 2 + 1][0], oacc[n16 * 2 + 1][1],
                        oacc[n16 * 2 + 1][2], oacc[n16 * 2 + 1][3],
                        a0, a1, a2, a3, r2, r3);
            }
        }
        __syncthreads();
    }

    // epilogue: normalize, write ctx (half)
    const float inv0 = 1.0f / l0;
    const float inv1 = 1.0f / l1;
    const int r0 = q0 + moff + g;
    const int r1 = r0 + 8;
#pragma unroll
    for (int nt = 0; nt < 8; nt++) {
        const int col = nt * 8 + 2 * t;
        *(__half2*)&Og[baso + (size_t)r0 * HID + col] =
            __floats2half2_rn(oacc[nt][0] * inv0, oacc[nt][1] * inv0);
        *(__half2*)&Og[baso + (size_t)r1 * HID + col] =
            __floats2half2_rn(oacc[nt][2] * inv1, oacc[nt][3] * inv1);
    }
}

// ---------------------------------------------------------------------------
// Residual add + LayerNorm (optionally also emits a half copy)
// ---------------------------------------------------------------------------
template<int HALF_OUT>
__global__ void __launch_bounds__(256) add_ln_kernel(
    const float* __restrict__ X, const float* __restrict__ Y,
    const float* __restrict__ g, const float* __restrict__ be,
    float* __restrict__ out, __half* __restrict__ outh)
{
    const int row = blockIdx.x;
    const int tid = threadIdx.x;
    const size_t base = (size_t)row * HID;

    float v[4];
    float s = 0.0f, s2 = 0.0f;
#pragma unroll
    for (int k = 0; k < 4; k++) {
        int c = tid + k * 256;
        float tt = X[base + c] + Y[base + c];
        v[k] = tt;
        s += tt;
        s2 += tt * tt;
    }
#pragma unroll
    for (int off = 16; off > 0; off >>= 1) {
        s  += __shfl_xor_sync(0xffffffffu, s,  off);
        s2 += __shfl_xor_sync(0xffffffffu, s2, off);
    }
    __shared__ float red[16];
    const int warp = tid >> 5, lane = tid & 31;
    if (lane == 0) { red[warp] = s; red[warp + 8] = s2; }
    __syncthreads();
    if (tid < 32) {
        float a = (lane < 8) ? red[lane]     : 0.0f;
        float c2 = (lane < 8) ? red[lane + 8] : 0.0f;
#pragma unroll
        for (int off = 4; off > 0; off >>= 1) {
            a  += __shfl_xor_sync(0xffffffffu, a,  off);
            c2 += __shfl_xor_sync(0xffffffffu, c2, off);
        }
        if (lane == 0) { red[0] = a; red[1] = c2; }
    }
    __syncthreads();
    const float mu  = red[0] * (1.0f / HID);
    const float var = red[1] * (1.0f / HID) - mu * mu;
    const float inv = rsqrtf(var + 1e-5f);
#pragma unroll
    for (int k = 0; k < 4; k++) {
        int c = tid + k * 256;
        float r = (v[k] - mu) * inv * g[c] + be[c];
        out[base + c] = r;
        if (HALF_OUT) outh[base + c] = __float2half_rn(r);
    }
}

// ---------------------------------------------------------------------------
// kernel_launch
// ---------------------------------------------------------------------------
extern "C" void kernel_launch(void* const* d_in, const int* in_sizes, int n_in,
                              void* d_out, int out_size)
{
    const float* x  = (const float*)d_in[0];
    const float* Wq = (const float*)d_in[1];
    const float* bq = (const float*)d_in[2];
    const float* Wk = (const float*)d_in[3];
    const float* bk = (const float*)d_in[4];
    const float* Wv = (const float*)d_in[5];
    const float* bv = (const float*)d_in[6];
    const float* Wo = (const float*)d_in[7];
    const float* bo = (const float*)d_in[8];
    const float* W1 = (const float*)d_in[9];
    const float* b1 = (const float*)d_in[10];
    const float* W2 = (const float*)d_in[11];
    const float* b2 = (const float*)d_in[12];
    const float* g1 = (const float*)d_in[13];
    const float* be1= (const float*)d_in[14];
    const float* g2 = (const float*)d_in[15];
    const float* be2= (const float*)d_in[16];
    float* out = (float*)d_out;

    __half *xh, *qkvh, *ctxh, *x1h, *hh;
    float *ao, *x1, *ff, *bqkv;
    __half *wqkvt, *wot, *w1t, *w2t;
    cudaGetSymbolAddress((void**)&xh,    g_xh);
    cudaGetSymbolAddress((void**)&qkvh,  g_qkvh);
    cudaGetSymbolAddress((void**)&ctxh,  g_ctxh);
    cudaGetSymbolAddress((void**)&ao,    g_ao);
    cudaGetSymbolAddress((void**)&x1,    g_x1);
    cudaGetSymbolAddress((void**)&x1h,   g_x1h);
    cudaGetSymbolAddress((void**)&hh,    g_hh);
    cudaGetSymbolAddress((void**)&ff,    g_ff);
    cudaGetSymbolAddress((void**)&wqkvt, g_wqkvt);
    cudaGetSymbolAddress((void**)&wot,   g_wot);
    cudaGetSymbolAddress((void**)&w1t,   g_w1t);
    cudaGetSymbolAddress((void**)&w2t,   g_w2t);
    cudaGetSymbolAddress((void**)&bqkv,  g_bqkv);

    cudaFuncSetAttribute(attn_mma_h_kernel,
                         cudaFuncAttributeMaxDynamicSharedMemorySize, ATT_SMEM);
    cudaFuncSetAttribute(mma_gemm_h<0>,
                         cudaFuncAttributeMaxDynamicSharedMemorySize, GEMM_SMEM);
    cudaFuncSetAttribute(mma_gemm_h<1>,
                         cudaFuncAttributeMaxDynamicSharedMemorySize, GEMM_SMEM);
    cudaFuncSetAttribute(mma_gemm_h<2>,
                         cudaFuncAttributeMaxDynamicSharedMemorySize, GEMM_SMEM);

    const dim3 blk256(256);

    // single fused prep launch
    prep_kernel<<<16396, blk256>>>(Wq, Wk, Wv, Wo, W1, W2, x, bq, bk, bv);

    // fused QKV GEMM  (8192 x 3072 x 1024)
    mma_gemm_h<1><<<dim3(NQKV / BN, MTOT / 128), blk256, GEMM_SMEM>>>(
        xh, wqkvt, bqkv, qkvh, MTOT, NQKV, HID);

    // attention
    attn_mma_h_kernel<<<dim3(SEQ / BQ, NHEAD, BATCH), blk256, ATT_SMEM>>>(qkvh, ctxh);

    const dim3 gProj(HID / BN, MTOT / 128);   // (4, 64)
    const dim3 gFF1 (DFF / BN, MTOT / 128);   // (16, 64)

    // Output projection (fp32 out) + residual/LN1 (emit half copy for FF1)
    mma_gemm_h<0><<<gProj, blk256, GEMM_SMEM>>>(ctxh, wot, bo, ao, MTOT, HID, HID);
    add_ln_kernel<1><<<MTOT, blk256>>>(x, ao, g1, be1, x1, x1h);

    // FFN
    mma_gemm_h<2><<<gFF1, blk256, GEMM_SMEM>>>(x1h, w1t, b1, hh, MTOT, DFF, HID);
    mma_gemm_h<0><<<gProj, blk256, GEMM_SMEM>>>(hh, w2t, b2, ff, MTOT, HID, DFF);

    // Residual/LN2 -> output
    add_ln_kernel<0><<<MTOT, blk256>>>(x1, ff, g2, be2, out, nullptr);
}

// round 10
// speedup vs baseline: 6.7034x; 1.0149x over previous
#include <cuda_runtime.h>
#include <cuda_fp16.h>
#include <math.h>
#include <cstdint>

// Problem constants
#define BATCH 4
#define SEQ   2048
#define HID   1024
#define NHEAD 16
#define DK    64
#define DFF   4096
#define MTOT  (BATCH * SEQ)          // 8192 rows
#define NQKV  (3 * HID)              // 3072

// ---------------------------------------------------------------------------
// Scratch
// ---------------------------------------------------------------------------
__device__ __half g_xh  [MTOT * HID];
__device__ __half g_qkvh[MTOT * NQKV];
__device__ __half g_ctxh[MTOT * HID];
__device__ float  g_ao  [MTOT * HID];
__device__ float  g_x1  [MTOT * HID];
__device__ __half g_x1h [MTOT * HID];
__device__ __half g_hh  [MTOT * DFF];
__device__ float  g_ff  [MTOT * HID];
__device__ __half g_wqkvt[NQKV * HID];
__device__ __half g_wot [HID * HID];
__device__ __half g_w1t [HID * DFF];
__device__ __half g_w2t [DFF * HID];
__device__ float  g_bqkv[NQKV];

// ---------------------------------------------------------------------------
// helpers
// ---------------------------------------------------------------------------
__device__ __forceinline__ uint32_t smem_u32(const void* p) {
    uint32_t a;
    asm("{ .reg .u64 t; cvta.to.shared.u64 t, %1; cvt.u32.u64 %0, t; }" : "=r"(a) : "l"(p));
    return a;
}
__device__ __forceinline__ void cp_async16(uint32_t saddr, const void* gaddr) {
    asm volatile("cp.async.cg.shared.global [%0], [%1], 16;" :: "r"(saddr), "l"(gaddr) : "memory");
}
#define CP_COMMIT() asm volatile("cp.async.commit_group;" ::: "memory")
#define CP_WAIT(n)  asm volatile("cp.async.wait_group %0;" :: "n"(n) : "memory")

__device__ __forceinline__ void mma_f16(
    float& d0, float& d1, float& d2, float& d3,
    uint32_t a0, uint32_t a1, uint32_t a2, uint32_t a3,
    uint32_t b0, uint32_t b1)
{
    asm volatile(
        "mma.sync.aligned.m16n8k16.row.col.f32.f16.f16.f32 "
        "{%0,%1,%2,%3}, {%4,%5,%6,%7}, {%8,%9}, {%0,%1,%2,%3};"
        : "+f"(d0), "+f"(d1), "+f"(d2), "+f"(d3)
        : "r"(a0), "r"(a1), "r"(a2), "r"(a3), "r"(b0), "r"(b1));
}
__device__ __forceinline__ void ldmatrix_x4(
    uint32_t& r0, uint32_t& r1, uint32_t& r2, uint32_t& r3, uint32_t addr)
{
    asm volatile("ldmatrix.sync.aligned.m8n8.x4.shared.b16 {%0,%1,%2,%3}, [%4];"
                 : "=r"(r0), "=r"(r1), "=r"(r2), "=r"(r3) : "r"(addr));
}
__device__ __forceinline__ void ldmatrix_x4_trans(
    uint32_t& r0, uint32_t& r1, uint32_t& r2, uint32_t& r3, uint32_t addr)
{
    asm volatile("ldmatrix.sync.aligned.m8n8.x4.trans.shared.b16 {%0,%1,%2,%3}, [%4];"
                 : "=r"(r0), "=r"(r1), "=r"(r2), "=r"(r3) : "r"(addr));
}

__device__ __forceinline__ float gelu_fn(float x) {
    const float c = 0.7978845608028654f;
    float x3 = x * x * x;
    return 0.5f * x * (1.0f + tanhf(c * (x + 0.044715f * x3)));
}

// ---------------------------------------------------------------------------
// Fused prep kernel (transposes + x conversion + bias concat)
// ---------------------------------------------------------------------------
__device__ __forceinline__ void transpose_tile(
    float (*t)[33], const float* __restrict__ W, __half* __restrict__ Wt,
    int K, int N, int bx, int by, int tid)
{
    const int tx = tid & 31;
    const int ty = tid >> 5;
    const int b0 = bx * 32, k0 = by * 32;
#pragma unroll
    for (int q = 0; q < 4; q++)
        t[ty + q * 8][tx] = W[(size_t)(k0 + ty + q * 8) * N + b0 + tx];
    __syncthreads();
#pragma unroll
    for (int q = 0; q < 4; q++)
        Wt[(size_t)(b0 + ty + q * 8) * K + k0 + tx] = __float2half_rn(t[tx][ty + q * 8]);
}

__global__ void __launch_bounds__(256) prep_kernel(
    const float* __restrict__ Wq, const float* __restrict__ Wk,
    const float* __restrict__ Wv, const float* __restrict__ Wo,
    const float* __restrict__ W1, const float* __restrict__ W2,
    const float* __restrict__ x,
    const float* __restrict__ bq, const float* __restrict__ bk,
    const float* __restrict__ bv)
{
    __shared__ float t[32][33];
    const int id  = blockIdx.x;
    const int tid = threadIdx.x;

    if (id < 4096) {
        const int m = id >> 10;
        const float* W = (m == 0) ? Wq : (m == 1) ? Wk : (m == 2) ? Wv : Wo;
        __half* Wt = (m == 0) ? g_wqkvt
                   : (m == 1) ? g_wqkvt + (size_t)HID * HID
                   : (m == 2) ? g_wqkvt + (size_t)2 * HID * HID
                   : g_wot;
        const int lid = id & 1023;
        transpose_tile(t, W, Wt, HID, HID, lid & 31, lid >> 5, tid);
    } else if (id < 8192) {
        const int lid = id - 4096;
        transpose_tile(t, W1, g_w1t, HID, DFF, lid & 127, lid >> 7, tid);
    } else if (id < 12288) {
        const int lid = id - 8192;
        transpose_tile(t, W2, g_w2t, DFF, HID, lid & 31, lid >> 5, tid);
    } else if (id < 16384) {
        const int i = ((id - 12288) * 256 + tid) * 8;
        float4 a = *(const float4*)&x[i];
        float4 b = *(const float4*)&x[i + 4];
        __half2 h[4];
        h[0] = __floats2half2_rn(a.x, a.y);
        h[1] = __floats2half2_rn(a.z, a.w);
        h[2] = __floats2half2_rn(b.x, b.y);
        h[3] = __floats2half2_rn(b.z, b.w);
        *(uint4*)&g_xh[i] = *(uint4*)h;
    } else {
        const int i = (id - 16384) * 256 + tid;      // 0..3071
        const int seg = i >> 10, off = i & 1023;
        g_bqkv[i] = (seg == 0) ? bq[off] : (seg == 1) ? bk[off] : bv[off];
    }
}

// ---------------------------------------------------------------------------
// fp16 mma.sync GEMM:  C[M,N] = A[M,K] @ W[K,N] + bias   (W given as Wt[n][k])
// CTA tile 128x128, BK=64, 2-stage cp.async pipeline, 8 warps (4m x 2n),
// warp tile 32x64. 2 CTAs/SM (regs capped at 128, smem 73.7KB).
// EPI: 0 = fp32 out, 1 = half out, 2 = half out + GELU
// ---------------------------------------------------------------------------
#define HPAD 72
#define BM 128
#define BN 128
#define STAGE_H ((BM + BN) * HPAD)                     // halves per stage
#define GEMM_SMEM (2 * STAGE_H * 2)                    // 73728 bytes

__device__ __forceinline__ void fill_stage(
    __half* As, __half* Bs, const __half* A, const __half* Bt,
    int bm, int bn, int k0, int K, int tid)
{
#pragma unroll
    for (int q = 0; q < 4; q++) {
        int idx = q * 256 + tid;
        int row = idx >> 3, c = idx & 7;
        cp_async16(smem_u32(&As[row * HPAD + c * 8]),
                   &A[(size_t)(bm + row) * K + k0 + c * 8]);
    }
#pragma unroll
    for (int q = 0; q < 4; q++) {
        int idx = q * 256 + tid;
        int row = idx >> 3, c = idx & 7;
        cp_async16(smem_u32(&Bs[row * HPAD + c * 8]),
                   &Bt[(size_t)(bn + row) * K + k0 + c * 8]);
    }
}

template<int EPI>
__global__ void __launch_bounds__(256, 2) mma_gemm_h(
    const __half* __restrict__ A, const __half* __restrict__ Bt,
    const float* __restrict__ bias, void* __restrict__ Cout,
    int M, int N, int K)
{
    extern __shared__ __half shh[];
    const int tid  = threadIdx.x;
    const int wid  = tid >> 5;
    const int lane = tid & 31;
    const int g    = lane >> 2;
    const int t    = lane & 3;
    const int bm   = blockIdx.y * BM;
    const int bn   = blockIdx.x * BN;
    const int moff = (wid & 3) * 32;       // 4 warps in m
    const int noff = (wid >> 2) * 64;      // 2 warps in n

    const int a_r = lane & 15;
    const int a_c = (lane >> 4) * 8;
    const int b_r = (lane & 7) + ((lane >> 4) << 3);
    const int b_c = ((lane >> 3) & 1) * 8;

    const int iters = K >> 6;

    float acc[2][8][4];
#pragma unroll
    for (int a = 0; a < 2; a++)
#pragma unroll
        for (int b = 0; b < 8; b++)
#pragma unroll
            for (int c = 0; c < 4; c++) acc[a][b][c] = 0.0f;

    // prologue: stage 0
    fill_stage(shh, shh + BM * HPAD, A, Bt, bm, bn, 0, K, tid);
    CP_COMMIT();

    for (int i = 0; i < iters; i++) {
        CP_WAIT(0);
        __syncthreads();

        // prefetch stage i+1 into the other buffer (safe: all warps are past
        // the compute of iteration i-1 that used it)
        if (i + 1 < iters) {
            __half* st = shh + ((i + 1) & 1) * STAGE_H;
            fill_stage(st, st + BM * HPAD, A, Bt, bm, bn, (i + 1) * 64, K, tid);
            CP_COMMIT();
        }

        const __half* As = shh + (i & 1) * STAGE_H;
        const __half* Bs = As + BM * HPAD;
#pragma unroll
        for (int ks = 0; ks < 4; ks++) {
            uint32_t af[2][4], bf[8][2];
#pragma unroll
            for (int mt = 0; mt < 2; mt++) {
                uint32_t addr = smem_u32(
                    &As[(moff + mt * 16 + a_r) * HPAD + ks * 16 + a_c]);
                ldmatrix_x4(af[mt][0], af[mt][1], af[mt][2], af[mt][3], addr);
            }
#pragma unroll
            for (int np = 0; np < 4; np++) {
                uint32_t addr = smem_u32(
                    &Bs[(noff + np * 16 + b_r) * HPAD + ks * 16 + b_c]);
                ldmatrix_x4(bf[np * 2][0], bf[np * 2][1],
                            bf[np * 2 + 1][0], bf[np * 2 + 1][1], addr);
            }
#pragma unroll
            for (int mt = 0; mt < 2; mt++)
#pragma unroll
                for (int nt = 0; nt < 8; nt++)
                    mma_f16(acc[mt][nt][0], acc[mt][nt][1], acc[mt][nt][2], acc[mt][nt][3],
                            af[mt][0], af[mt][1], af[mt][2], af[mt][3],
                            bf[nt][0], bf[nt][1]);
        }
        __syncthreads();
    }

    // epilogue
#pragma unroll
    for (int nt = 0; nt < 8; nt++) {
        const int col = bn + noff + nt * 8 + 2 * t;
        const float2 bv = *(const float2*)&bias[col];
#pragma unroll
        for (int mt = 0; mt < 2; mt++) {
            const int r0 = bm + moff + mt * 16 + g;
            float c0 = acc[mt][nt][0] + bv.x;
            float c1 = acc[mt][nt][1] + bv.y;
            float c2 = acc[mt][nt][2] + bv.x;
            float c3 = acc[mt][nt][3] + bv.y;
            if (EPI == 2) {
                c0 = gelu_fn(c0); c1 = gelu_fn(c1);
                c2 = gelu_fn(c2); c3 = gelu_fn(c3);
            }
            if (EPI == 0) {
                float* C = (float*)Cout;
                *(float2*)&C[(size_t)r0 * N + col]       = make_float2(c0, c1);
                *(float2*)&C[(size_t)(r0 + 8) * N + col] = make_float2(c2, c3);
            } else {
                __half* C = (__half*)Cout;
                *(__half2*)&C[(size_t)r0 * N + col]       = __floats2half2_rn(c0, c1);
                *(__half2*)&C[(size_t)(r0 + 8) * N + col] = __floats2half2_rn(c2, c3);
            }
        }
    }
}

// ---------------------------------------------------------------------------
// Flash attention, fp16 mma. (unchanged from round 9)
// ---------------------------------------------------------------------------
#define BQ   128
#define BKV  64
#define NKB  (SEQ / BKV)
#define ATT_SMEM ((2 * BQ * HPAD + 4 * BKV * HPAD) * 2)   // 73728 B

__global__ void __launch_bounds__(256, 2) attn_mma_h_kernel(
    const __half* __restrict__ QKV, __half* __restrict__ Og)
{
    extern __shared__ __half sha[];
    __half* Qs = sha;                              // [BQ][HPAD]
    __half* Ks = sha + BQ * HPAD;                  // [2][BKV][HPAD]
    __half* Vs = sha + BQ * HPAD + 2 * BKV * HPAD; // [2][BKV][HPAD]
    __half* Ps = sha + BQ * HPAD + 4 * BKV * HPAD; // [BQ][HPAD]

    const int tid  = threadIdx.x;
    const int wid  = tid >> 5;
    const int lane = tid & 31;
    const int g    = lane >> 2;
    const int t    = lane & 3;
    const int qt   = blockIdx.x;
    const int head = blockIdx.y;
    const int b    = blockIdx.z;

    const size_t baseq = ((size_t)b * SEQ) * NQKV + (size_t)head * DK;
    const __half* Qg = QKV + baseq;
    const __half* Kg = QKV + baseq + HID;
    const __half* Vg = QKV + baseq + 2 * HID;
    const size_t baso = ((size_t)b * SEQ) * HID + (size_t)head * DK;

    const int q0   = qt * BQ;
    const int moff = wid * 16;

    const int a_r = lane & 15;
    const int a_c = (lane >> 4) * 8;
    const int b_r = (lane & 7) + ((lane >> 4) << 3);
    const int b_c = ((lane >> 3) & 1) * 8;

#pragma unroll
    for (int q = 0; q < 4; q++) {
        int idx = q * 256 + tid;
        int r = idx >> 3, c = idx & 7;
        cp_async16(smem_u32(&Qs[r * HPAD + c * 8]),
                   &Qg[(size_t)(q0 + r) * NQKV + c * 8]);
    }
#pragma unroll
    for (int q = 0; q < 2; q++) {
        int idx = q * 256 + tid;
        int r = idx >> 3, c = idx & 7;
        cp_async16(smem_u32(&Ks[r * HPAD + c * 8]),
                   &Kg[(size_t)r * NQKV + c * 8]);
        cp_async16(smem_u32(&Vs[r * HPAD + c * 8]),
                   &Vg[(size_t)r * NQKV + c * 8]);
    }
    CP_COMMIT();

    const uint32_t vlane_off = (uint32_t)((lane & 15) * HPAD + (lane >> 4) * 8);

    float oacc[8][4];
#pragma unroll
    for (int nt = 0; nt < 8; nt++)
#pragma unroll
        for (int c = 0; c < 4; c++) oacc[nt][c] = 0.0f;
    float m0 = -1e30f, m1 = -1e30f, l0 = 0.0f, l1 = 0.0f;

    for (int i = 0; i < NKB; i++) {
        if (i + 1 < NKB) {
            const int kn = (i + 1) * BKV;
            __half* Kb = Ks + ((i + 1) & 1) * BKV * HPAD;
            __half* Vb = Vs + ((i + 1) & 1) * BKV * HPAD;
#pragma unroll
            for (int q = 0; q < 2; q++) {
                int idx = q * 256 + tid;
                int r = idx >> 3, c = idx & 7;
                cp_async16(smem_u32(&Kb[r * HPAD + c * 8]),
                           &Kg[(size_t)(kn + r) * NQKV + c * 8]);
                cp_async16(smem_u32(&Vb[r * HPAD + c * 8]),
                           &Vg[(size_t)(kn + r) * NQKV + c * 8]);
            }
            CP_COMMIT();
            CP_WAIT(1);
        } else {
            CP_WAIT(0);
        }
        __syncthreads();

        const __half* Kb = Ks + (i & 1) * BKV * HPAD;
        const __half* Vb = Vs + (i & 1) * BKV * HPAD;

        // ---- S = Q K^T ----
        float sacc[8][4];
#pragma unroll
        for (int nt = 0; nt < 8; nt++)
#pragma unroll
            for (int c = 0; c < 4; c++) sacc[nt][c] = 0.0f;

#pragma unroll
        for (int ks = 0; ks < 4; ks++) {
            uint32_t qf[4];
            {
                uint32_t addr = smem_u32(
                    &Qs[(moff + a_r) * HPAD + ks * 16 + a_c]);
                ldmatrix_x4(qf[0], qf[1], qf[2], qf[3], addr);
            }
            uint32_t bf[8][2];
#pragma unroll
            for (int np = 0; np < 4; np++) {
                uint32_t addr = smem_u32(
                    &Kb[(np * 16 + b_r) * HPAD + ks * 16 + b_c]);
                ldmatrix_x4(bf[np * 2][0], bf[np * 2][1],
                            bf[np * 2 + 1][0], bf[np * 2 + 1][1], addr);
            }
#pragma unroll
            for (int nt = 0; nt < 8; nt++)
                mma_f16(sacc[nt][0], sacc[nt][1], sacc[nt][2], sacc[nt][3],
                        qf[0], qf[1], qf[2], qf[3],
                        bf[nt][0], bf[nt][1]);
        }

        // ---- online softmax ----
        float rx0 = -1e30f, rx1 = -1e30f;
#pragma unroll
        for (int nt = 0; nt < 8; nt++) {
            sacc[nt][0] *= 0.125f; sacc[nt][1] *= 0.125f;
            sacc[nt][2] *= 0.125f; sacc[nt][3] *= 0.125f;
            rx0 = fmaxf(rx0, fmaxf(sacc[nt][0], sacc[nt][1]));
            rx1 = fmaxf(rx1, fmaxf(sacc[nt][2], sacc[nt][3]));
        }
        rx0 = fmaxf(rx0, __shfl_xor_sync(0xffffffffu, rx0, 1));
        rx0 = fmaxf(rx0, __shfl_xor_sync(0xffffffffu, rx0, 2));
        rx1 = fmaxf(rx1, __shfl_xor_sync(0xffffffffu, rx1, 1));
        rx1 = fmaxf(rx1, __shfl_xor_sync(0xffffffffu, rx1, 2));

        const float nm0 = fmaxf(m0, rx0);
        const float nm1 = fmaxf(m1, rx1);
        const float corr0 = __expf(m0 - nm0);
        const float corr1 = __expf(m1 - nm1);

        float rs0 = 0.0f, rs1 = 0.0f;
#pragma unroll
        for (int nt = 0; nt < 8; nt++) {
            sacc[nt][0] = __expf(sacc[nt][0] - nm0);
            sacc[nt][1] = __expf(sacc[nt][1] - nm0);
            sacc[nt][2] = __expf(sacc[nt][2] - nm1);
            sacc[nt][3] = __expf(sacc[nt][3] - nm1);
            rs0 += sacc[nt][0] + sacc[nt][1];
            rs1 += sacc[nt][2] + sacc[nt][3];
        }
        rs0 += __shfl_xor_sync(0xffffffffu, rs0, 1);
        rs0 += __shfl_xor_sync(0xffffffffu, rs0, 2);
        rs1 += __shfl_xor_sync(0xffffffffu, rs1, 1);
        rs1 += __shfl_xor_sync(0xffffffffu, rs1, 2);

        l0 = l0 * corr0 + rs0;  m0 = nm0;
        l1 = l1 * corr1 + rs1;  m1 = nm1;

#pragma unroll
        for (int nt = 0; nt < 8; nt++) {
            oacc[nt][0] *= corr0; oacc[nt][1] *= corr0;
            oacc[nt][2] *= corr1; oacc[nt][3] *= corr1;
        }

        // ---- P -> smem (half2), warp-private rows ----
#pragma unroll
        for (int nt = 0; nt < 8; nt++) {
            *(__half2*)&Ps[(moff + g) * HPAD + nt * 8 + 2 * t] =
                __floats2half2_rn(sacc[nt][0], sacc[nt][1]);
            *(__half2*)&Ps[(moff + 8 + g) * HPAD + nt * 8 + 2 * t] =
                __floats2half2_rn(sacc[nt][2], sacc[nt][3]);
        }
        __syncwarp();

        // ---- O += P @ V ----
        const uint32_t vbase = smem_u32(Vb) + vlane_off * 2;
#pragma unroll
        for (int ks = 0; ks < 4; ks++) {
            const int kc = ks * 16 + 2 * t;
            const uint32_t a0 = *(const uint32_t*)&Ps[(moff + g) * HPAD + kc];
            const uint32_t a1 = *(const uint32_t*)&Ps[(moff + 8 + g) * HPAD + kc];
            const uint32_t a2 = *(const uint32_t*)&Ps[(moff + g) * HPAD + kc + 8];
            const uint32_t a3 = *(const uint32_t*)&Ps[(moff + 8 + g) * HPAD + kc + 8];
            const uint32_t vrow = vbase + (uint32_t)(ks * 16 * HPAD * 2);
#pragma unroll
            for (int n16 = 0; n16 < 4; n16++) {
                uint32_t r0, r1, r2, r3;
                ldmatrix_x4_trans(r0, r1, r2, r3, vrow + (uint32_t)(n16 * 32));
                mma_f16(oacc[n16 * 2][0], oacc[n16 * 2][1], oacc[n16 * 2][2], oacc[n16 * 2][3],
                        a0, a1, a2, a3, r0, r1);
                mma_f16(oacc[n16 * 2 + 1][0], oacc[n16 * 2 + 1][1],
                        oacc[n16 * 2 + 1][2], oacc[n16 * 2 + 1][3],
                        a0, a1, a2, a3, r2, r3);
            }
        }
        __syncthreads();
    }

    // epilogue: normalize, write ctx (half)
    const float inv0 = 1.0f / l0;
    const float inv1 = 1.0f / l1;
    const int r0 = q0 + moff + g;
    const int r1 = r0 + 8;
#pragma unroll
    for (int nt = 0; nt < 8; nt++) {
        const int col = nt * 8 + 2 * t;
        *(__half2*)&Og[baso + (size_t)r0 * HID + col] =
            __floats2half2_rn(oacc[nt][0] * inv0, oacc[nt][1] * inv0);
        *(__half2*)&Og[baso + (size_t)r1 * HID + col] =
            __floats2half2_rn(oacc[nt][2] * inv1, oacc[nt][3] * inv1);
    }
}

// ---------------------------------------------------------------------------
// Residual add + LayerNorm (optionally also emits a half copy)
// ---------------------------------------------------------------------------
template<int HALF_OUT>
__global__ void __launch_bounds__(256) add_ln_kernel(
    const float* __restrict__ X, const float* __restrict__ Y,
    const float* __restrict__ g, const float* __restrict__ be,
    float* __restrict__ out, __half* __restrict__ outh)
{
    const int row = blockIdx.x;
    const int tid = threadIdx.x;
    const size_t base = (size_t)row * HID;

    float v[4];
    float s = 0.0f, s2 = 0.0f;
#pragma unroll
    for (int k = 0; k < 4; k++) {
        int c = tid + k * 256;
        float tt = X[base + c] + Y[base + c];
        v[k] = tt;
        s += tt;
        s2 += tt * tt;
    }
#pragma unroll
    for (int off = 16; off > 0; off >>= 1) {
        s  += __shfl_xor_sync(0xffffffffu, s,  off);
        s2 += __shfl_xor_sync(0xffffffffu, s2, off);
    }
    __shared__ float red[16];
    const int warp = tid >> 5, lane = tid & 31;
    if (lane == 0) { red[warp] = s; red[warp + 8] = s2; }
    __syncthreads();
    if (tid < 32) {
        float a = (lane < 8) ? red[lane]     : 0.0f;
        float c2 = (lane < 8) ? red[lane + 8] : 0.0f;
#pragma unroll
        for (int off = 4; off > 0; off >>= 1) {
            a  += __shfl_xor_sync(0xffffffffu, a,  off);
            c2 += __shfl_xor_sync(0xffffffffu, c2, off);
        }
        if (lane == 0) { red[0] = a; red[1] = c2; }
    }
    __syncthreads();
    const float mu  = red[0] * (1.0f / HID);
    const float var = red[1] * (1.0f / HID) - mu * mu;
    const float inv = rsqrtf(var + 1e-5f);
#pragma unroll
    for (int k = 0; k < 4; k++) {
        int c = tid + k * 256;
        float r = (v[k] - mu) * inv * g[c] + be[c];
        out[base + c] = r;
        if (HALF_OUT) outh[base + c] = __float2half_rn(r);
    }
}

// ---------------------------------------------------------------------------
// kernel_launch
// ---------------------------------------------------------------------------
extern "C" void kernel_launch(void* const* d_in, const int* in_sizes, int n_in,
                              void* d_out, int out_size)
{
    const float* x  = (const float*)d_in[0];
    const float* Wq = (const float*)d_in[1];
    const float* bq = (const float*)d_in[2];
    const float* Wk = (const float*)d_in[3];
    const float* bk = (const float*)d_in[4];
    const float* Wv = (const float*)d_in[5];
    const float* bv = (const float*)d_in[6];
    const float* Wo = (const float*)d_in[7];
    const float* bo = (const float*)d_in[8];
    const float* W1 = (const float*)d_in[9];
    const float* b1 = (const float*)d_in[10];
    const float* W2 = (const float*)d_in[11];
    const float* b2 = (const float*)d_in[12];
    const float* g1 = (const float*)d_in[13];
    const float* be1= (const float*)d_in[14];
    const float* g2 = (const float*)d_in[15];
    const float* be2= (const float*)d_in[16];
    float* out = (float*)d_out;

    __half *xh, *qkvh, *ctxh, *x1h, *hh;
    float *ao, *x1, *ff, *bqkv;
    __half *wqkvt, *wot, *w1t, *w2t;
    cudaGetSymbolAddress((void**)&xh,    g_xh);
    cudaGetSymbolAddress((void**)&qkvh,  g_qkvh);
    cudaGetSymbolAddress((void**)&ctxh,  g_ctxh);
    cudaGetSymbolAddress((void**)&ao,    g_ao);
    cudaGetSymbolAddress((void**)&x1,    g_x1);
    cudaGetSymbolAddress((void**)&x1h,   g_x1h);
    cudaGetSymbolAddress((void**)&hh,    g_hh);
    cudaGetSymbolAddress((void**)&ff,    g_ff);
    cudaGetSymbolAddress((void**)&wqkvt, g_wqkvt);
    cudaGetSymbolAddress((void**)&wot,   g_wot);
    cudaGetSymbolAddress((void**)&w1t,   g_w1t);
    cudaGetSymbolAddress((void**)&w2t,   g_w2t);
    cudaGetSymbolAddress((void**)&bqkv,  g_bqkv);

    cudaFuncSetAttribute(attn_mma_h_kernel,
                         cudaFuncAttributeMaxDynamicSharedMemorySize, ATT_SMEM);
    cudaFuncSetAttribute(mma_gemm_h<0>,
                         cudaFuncAttributeMaxDynamicSharedMemorySize, GEMM_SMEM);
    cudaFuncSetAttribute(mma_gemm_h<1>,
                         cudaFuncAttributeMaxDynamicSharedMemorySize, GEMM_SMEM);
    cudaFuncSetAttribute(mma_gemm_h<2>,
                         cudaFuncAttributeMaxDynamicSharedMemorySize, GEMM_SMEM);

    const dim3 blk256(256);

    // single fused prep launch
    prep_kernel<<<16396, blk256>>>(Wq, Wk, Wv, Wo, W1, W2, x, bq, bk, bv);

    // fused QKV GEMM  (8192 x 3072 x 1024)
    mma_gemm_h<1><<<dim3(NQKV / BN, MTOT / BM), blk256, GEMM_SMEM>>>(
        xh, wqkvt, bqkv, qkvh, MTOT, NQKV, HID);

    // attention
    attn_mma_h_kernel<<<dim3(SEQ / BQ, NHEAD, BATCH), blk256, ATT_SMEM>>>(qkvh, ctxh);

    const dim3 gProj(HID / BN, MTOT / BM);   // (8, 64)
    const dim3 gFF1 (DFF / BN, MTOT / BM);   // (32, 64)

    // Output projection (fp32 out) + residual/LN1 (emit half copy for FF1)
    mma_gemm_h<0><<<gProj, blk256, GEMM_SMEM>>>(ctxh, wot, bo, ao, MTOT, HID, HID);
    add_ln_kernel<1><<<MTOT, blk256>>>(x, ao, g1, be1, x1, x1h);

    // FFN
    mma_gemm_h<2><<<gFF1, blk256, GEMM_SMEM>>>(x1h, w1t, b1, hh, MTOT, DFF, HID);
    mma_gemm_h<0><<<gProj, blk256, GEMM_SMEM>>>(hh, w2t, b2, ff, MTOT, HID, DFF);

    // Residual/LN2 -> output
    add_ln_kernel<0><<<MTOT, blk256>>>(x1, ff, g2, be2, out, nullptr);
}